// round 1
// baseline (speedup 1.0000x reference)
#include <cuda_runtime.h>
#include <math.h>

// Problem constants
#define NB   4
#define TT   2048
#define DD   1024
#define HH   16
#define DHD  64
#define BT   (NB * TT)          // 8192 rows
#define D3   (3 * DD)           // 3072

// Scratch (no cudaMalloc allowed — device globals)
__device__ float g_xn[BT * DD];        // layernormed input
__device__ float g_qkv[BT * D3];       // fused QKV
__device__ float g_ctx[BT * DD];       // attention output (pre out-proj)

// ---------------------------------------------------------------------------
// LayerNorm: one block (256 threads) per row of 1024
// ---------------------------------------------------------------------------
__global__ void __launch_bounds__(256) ln_kernel(const float* __restrict__ x,
                                                 const float* __restrict__ gamma,
                                                 const float* __restrict__ beta) {
    int row = blockIdx.x;
    int tid = threadIdx.x;
    __shared__ float red[2][8];

    const float4* xr = (const float4*)(x + (size_t)row * DD);
    float4 xv = xr[tid];
    float s  = xv.x + xv.y + xv.z + xv.w;
    float s2 = xv.x * xv.x + xv.y * xv.y + xv.z * xv.z + xv.w * xv.w;

    #pragma unroll
    for (int o = 16; o > 0; o >>= 1) {
        s  += __shfl_xor_sync(0xffffffffu, s, o);
        s2 += __shfl_xor_sync(0xffffffffu, s2, o);
    }
    if ((tid & 31) == 0) { red[0][tid >> 5] = s; red[1][tid >> 5] = s2; }
    __syncthreads();
    if (tid < 32) {
        float a = (tid < 8) ? red[0][tid] : 0.f;
        float b = (tid < 8) ? red[1][tid] : 0.f;
        #pragma unroll
        for (int o = 4; o > 0; o >>= 1) {
            a += __shfl_xor_sync(0xffffffffu, a, o);
            b += __shfl_xor_sync(0xffffffffu, b, o);
        }
        if (tid == 0) { red[0][0] = a * (1.f / DD); red[1][0] = b * (1.f / DD); }
    }
    __syncthreads();

    float mu   = red[0][0];
    float var  = red[1][0] - mu * mu;
    float rstd = rsqrtf(var + 1e-5f);

    float4 g = ((const float4*)gamma)[tid];
    float4 bb = ((const float4*)beta)[tid];
    float4 y;
    y.x = (xv.x - mu) * rstd * g.x + bb.x;
    y.y = (xv.y - mu) * rstd * g.y + bb.y;
    y.z = (xv.z - mu) * rstd * g.z + bb.z;
    y.w = (xv.w - mu) * rstd * g.w + bb.w;
    ((float4*)(g_xn + (size_t)row * DD))[tid] = y;
}

// ---------------------------------------------------------------------------
// SGEMM: C[M,N] = A[M,K] * B[N,K]^T   (torch Linear layout: both K-contiguous)
// 128x128 block tile, BK=16, 256 threads, 8x8 microtile
// Requires M%128==0, N%128==0, K%16==0 (true for all calls here)
// ---------------------------------------------------------------------------
__global__ void __launch_bounds__(256) sgemm_tn(const float* __restrict__ A,
                                                const float* __restrict__ B,
                                                float* __restrict__ C,
                                                int M, int N, int K) {
    __shared__ float As[16][128];
    __shared__ float Bs[16][128];

    int tid = threadIdx.x;
    int bm = blockIdx.y * 128;
    int bn = blockIdx.x * 128;
    int ty = tid >> 4;           // 0..15
    int tx = tid & 15;           // 0..15
    int lr = tid >> 2;           // 0..63 (load row)
    int lc = (tid & 3) << 2;     // 0,4,8,12 (load col group)

    const float* Ab = A + (size_t)(bm + lr) * K + lc;
    const float* Bb = B + (size_t)(bn + lr) * K + lc;

    float acc[8][8];
    #pragma unroll
    for (int i = 0; i < 8; i++)
        #pragma unroll
        for (int j = 0; j < 8; j++) acc[i][j] = 0.f;

    for (int kt = 0; kt < K; kt += 16) {
        float4 a0 = *(const float4*)(Ab + kt);
        float4 a1 = *(const float4*)(Ab + (size_t)64 * K + kt);
        float4 b0 = *(const float4*)(Bb + kt);
        float4 b1 = *(const float4*)(Bb + (size_t)64 * K + kt);

        As[lc + 0][lr] = a0.x; As[lc + 1][lr] = a0.y; As[lc + 2][lr] = a0.z; As[lc + 3][lr] = a0.w;
        As[lc + 0][lr + 64] = a1.x; As[lc + 1][lr + 64] = a1.y; As[lc + 2][lr + 64] = a1.z; As[lc + 3][lr + 64] = a1.w;
        Bs[lc + 0][lr] = b0.x; Bs[lc + 1][lr] = b0.y; Bs[lc + 2][lr] = b0.z; Bs[lc + 3][lr] = b0.w;
        Bs[lc + 0][lr + 64] = b1.x; Bs[lc + 1][lr + 64] = b1.y; Bs[lc + 2][lr + 64] = b1.z; Bs[lc + 3][lr + 64] = b1.w;
        __syncthreads();

        #pragma unroll
        for (int k = 0; k < 16; k++) {
            float4 aa0 = *(const float4*)&As[k][ty * 8];
            float4 aa1 = *(const float4*)&As[k][ty * 8 + 4];
            float4 bb0 = *(const float4*)&Bs[k][tx * 8];
            float4 bb1 = *(const float4*)&Bs[k][tx * 8 + 4];
            float af[8] = {aa0.x, aa0.y, aa0.z, aa0.w, aa1.x, aa1.y, aa1.z, aa1.w};
            float bf[8] = {bb0.x, bb0.y, bb0.z, bb0.w, bb1.x, bb1.y, bb1.z, bb1.w};
            #pragma unroll
            for (int i = 0; i < 8; i++)
                #pragma unroll
                for (int j = 0; j < 8; j++)
                    acc[i][j] += af[i] * bf[j];
        }
        __syncthreads();
    }

    #pragma unroll
    for (int i = 0; i < 8; i++) {
        float* crow = C + (size_t)(bm + ty * 8 + i) * N + bn + tx * 8;
        *(float4*)(crow)     = make_float4(acc[i][0], acc[i][1], acc[i][2], acc[i][3]);
        *(float4*)(crow + 4) = make_float4(acc[i][4], acc[i][5], acc[i][6], acc[i][7]);
    }
}

// ---------------------------------------------------------------------------
// Causal flash attention, fp32.
// grid = (T/128, B*H), block = 128 threads, 1 query per thread.
// qkv layout: row (b*T + t), col = h*192 + {0..63:Q, 64..127:K, 128..191:V}
// ---------------------------------------------------------------------------
__global__ void __launch_bounds__(128) attn_kernel() {
    int qt  = blockIdx.x;
    int bh  = blockIdx.y;
    int b   = bh / HH;
    int h   = bh % HH;
    int tid = threadIdx.x;
    int qi  = qt * 128 + tid;

    __shared__ float4 Ksh[64][16];
    __shared__ float4 Vsh[64][16];

    const float4* qrow = (const float4*)(g_qkv + ((size_t)(b * TT + qi)) * D3 + h * 192);
    float4 q4[16];
    #pragma unroll
    for (int i = 0; i < 16; i++) q4[i] = qrow[i];

    float m = -INFINITY, l = 0.f;
    float4 o4[16];
    #pragma unroll
    for (int i = 0; i < 16; i++) o4[i] = make_float4(0.f, 0.f, 0.f, 0.f);

    int ntiles = qt * 2 + 2;   // key tiles of 64 covering keys <= max qi in this block
    for (int kt = 0; kt < ntiles; kt++) {
        // cooperative load of 64 keys + values (1024 float4 each / 128 threads)
        #pragma unroll
        for (int j = 0; j < 8; j++) {
            int idx = tid + j * 128;
            int rr = idx >> 4, cc = idx & 15;
            const float4* src = (const float4*)(g_qkv + ((size_t)(b * TT + kt * 64 + rr)) * D3 + h * 192);
            Ksh[rr][cc] = src[16 + cc];
            Vsh[rr][cc] = src[32 + cc];
        }
        __syncthreads();

        int kmax = qi - kt * 64 + 1;
        if (kmax > 64) kmax = 64;
        for (int kk = 0; kk < kmax; kk++) {
            float s = 0.f;
            #pragma unroll
            for (int i = 0; i < 16; i++) {
                float4 k4 = Ksh[kk][i];   // warp-broadcast read
                s += q4[i].x * k4.x + q4[i].y * k4.y + q4[i].z * k4.z + q4[i].w * k4.w;
            }
            s *= 0.125f;  // 1/sqrt(64)
            if (s > m) {
                float corr = __expf(m - s);
                m = s;
                l *= corr;
                #pragma unroll
                for (int i = 0; i < 16; i++) {
                    o4[i].x *= corr; o4[i].y *= corr; o4[i].z *= corr; o4[i].w *= corr;
                }
            }
            float p = __expf(s - m);
            l += p;
            #pragma unroll
            for (int i = 0; i < 16; i++) {
                float4 v4 = Vsh[kk][i];   // warp-broadcast read
                o4[i].x += p * v4.x; o4[i].y += p * v4.y;
                o4[i].z += p * v4.z; o4[i].w += p * v4.w;
            }
        }
        __syncthreads();
    }

    float inv = 1.f / l;
    float4* dst = (float4*)(g_ctx + ((size_t)(b * TT + qi)) * DD + h * DHD);
    #pragma unroll
    for (int i = 0; i < 16; i++) {
        float4 o = o4[i];
        dst[i] = make_float4(o.x * inv, o.y * inv, o.z * inv, o.w * inv);
    }
}

// ---------------------------------------------------------------------------
// Launch
// ---------------------------------------------------------------------------
extern "C" void kernel_launch(void* const* d_in, const int* in_sizes, int n_in,
                              void* d_out, int out_size) {
    const float* x     = (const float*)d_in[0];
    const float* gamma = (const float*)d_in[1];
    const float* beta  = (const float*)d_in[2];
    const float* w_qkv = (const float*)d_in[3];   // [3072, 1024]
    const float* w_o   = (const float*)d_in[4];   // [1024, 1024]
    float* out = (float*)d_out;                   // [8192, 1024]

    float* xn;  cudaGetSymbolAddress((void**)&xn,  g_xn);
    float* qkv; cudaGetSymbolAddress((void**)&qkv, g_qkv);
    float* ctx; cudaGetSymbolAddress((void**)&ctx, g_ctx);

    // 1. LayerNorm
    ln_kernel<<<BT, 256>>>(x, gamma, beta);

    // 2. QKV projection: [8192,3072] = xn[8192,1024] @ W_qkv^T
    {
        dim3 grid(D3 / 128, BT / 128);
        sgemm_tn<<<grid, 256>>>(xn, w_qkv, qkv, BT, D3, DD);
    }

    // 3. Causal attention
    {
        dim3 grid(TT / 128, NB * HH);
        attn_kernel<<<grid, 128>>>();
    }

    // 4. Output projection: [8192,1024] = ctx @ W_o^T
    {
        dim3 grid(DD / 128, BT / 128);
        sgemm_tn<<<grid, 256>>>(ctx, w_o, out, BT, DD, DD);
    }
}

// round 3
// speedup vs baseline: 1.3074x; 1.3074x over previous
#include <cuda_runtime.h>
#include <cuda_bf16.h>
#include <math.h>
#include <stdint.h>

// Problem constants
#define NB   4
#define TT   2048
#define DD   1024
#define HH   16
#define DHD  64
#define BT   (NB * TT)          // 8192 rows
#define D3   (3 * DD)           // 3072

// ---------------------------------------------------------------------------
// Scratch (no cudaMalloc allowed — device globals)
// ---------------------------------------------------------------------------
__device__ float g_qkv[BT * D3];                       // fused QKV (fp32)
__device__ float g_ctx[BT * DD];                       // attention output (fp32)
__device__ __nv_bfloat16 g_xnh[BT * DD], g_xnl[BT * DD];   // LN output hi/lo
__device__ __nv_bfloat16 g_wqh[D3 * DD], g_wql[D3 * DD];   // W_qkv hi/lo
__device__ __nv_bfloat16 g_woh[DD * DD], g_wol[DD * DD];   // W_o hi/lo
__device__ __nv_bfloat16 g_cxh[BT * DD], g_cxl[BT * DD];   // ctx hi/lo

// ---------------------------------------------------------------------------
// HMMA m16n8k16 bf16 (row.col) — supported on plain sm_103 target
// ---------------------------------------------------------------------------
#define MMA16816(Cacc, Afrag, Bfrag) \
    asm volatile( \
        "mma.sync.aligned.m16n8k16.row.col.f32.bf16.bf16.f32 " \
        "{%0,%1,%2,%3}, {%4,%5,%6,%7}, {%8,%9}, {%0,%1,%2,%3};" \
        : "+f"((Cacc)[0]), "+f"((Cacc)[1]), "+f"((Cacc)[2]), "+f"((Cacc)[3]) \
        : "r"((Afrag)[0]), "r"((Afrag)[1]), "r"((Afrag)[2]), "r"((Afrag)[3]), \
          "r"((Bfrag)[0]), "r"((Bfrag)[1]))

// ---------------------------------------------------------------------------
// LayerNorm: one block (256 threads) per row; writes bf16 hi/lo split
// ---------------------------------------------------------------------------
__global__ void __launch_bounds__(256) ln_kernel(const float* __restrict__ x,
                                                 const float* __restrict__ gamma,
                                                 const float* __restrict__ beta) {
    int row = blockIdx.x;
    int tid = threadIdx.x;
    __shared__ float red[2][8];

    const float4* xr = (const float4*)(x + (size_t)row * DD);
    float4 xv = xr[tid];
    float s  = xv.x + xv.y + xv.z + xv.w;
    float s2 = xv.x * xv.x + xv.y * xv.y + xv.z * xv.z + xv.w * xv.w;

    #pragma unroll
    for (int o = 16; o > 0; o >>= 1) {
        s  += __shfl_xor_sync(0xffffffffu, s, o);
        s2 += __shfl_xor_sync(0xffffffffu, s2, o);
    }
    if ((tid & 31) == 0) { red[0][tid >> 5] = s; red[1][tid >> 5] = s2; }
    __syncthreads();
    if (tid < 32) {
        float a = (tid < 8) ? red[0][tid] : 0.f;
        float b = (tid < 8) ? red[1][tid] : 0.f;
        #pragma unroll
        for (int o = 4; o > 0; o >>= 1) {
            a += __shfl_xor_sync(0xffffffffu, a, o);
            b += __shfl_xor_sync(0xffffffffu, b, o);
        }
        if (tid == 0) { red[0][0] = a * (1.f / DD); red[1][0] = b * (1.f / DD); }
    }
    __syncthreads();

    float mu   = red[0][0];
    float var  = red[1][0] - mu * mu;
    float rstd = rsqrtf(var + 1e-5f);

    float4 g  = ((const float4*)gamma)[tid];
    float4 bb = ((const float4*)beta)[tid];
    float y[4];
    y[0] = (xv.x - mu) * rstd * g.x + bb.x;
    y[1] = (xv.y - mu) * rstd * g.y + bb.y;
    y[2] = (xv.z - mu) * rstd * g.z + bb.z;
    y[3] = (xv.w - mu) * rstd * g.w + bb.w;

    __nv_bfloat16 h[4], l[4];
    #pragma unroll
    for (int i = 0; i < 4; i++) {
        h[i] = __float2bfloat16(y[i]);
        l[i] = __float2bfloat16(y[i] - __bfloat162float(h[i]));
    }
    size_t base = (size_t)row * DD + tid * 4;
    ((__nv_bfloat162*)(g_xnh + base))[0] = __nv_bfloat162(h[0], h[1]);
    ((__nv_bfloat162*)(g_xnh + base))[1] = __nv_bfloat162(h[2], h[3]);
    ((__nv_bfloat162*)(g_xnl + base))[0] = __nv_bfloat162(l[0], l[1]);
    ((__nv_bfloat162*)(g_xnl + base))[1] = __nv_bfloat162(l[2], l[3]);
}

// ---------------------------------------------------------------------------
// fp32 -> bf16 hi/lo split convert (for weights / ctx)
// ---------------------------------------------------------------------------
__global__ void __launch_bounds__(256) cvt_kernel(const float* __restrict__ src,
                                                  __nv_bfloat16* __restrict__ oh,
                                                  __nv_bfloat16* __restrict__ ol,
                                                  int n4) {
    int i = blockIdx.x * blockDim.x + threadIdx.x;
    if (i >= n4) return;
    float4 v = ((const float4*)src)[i];
    float y[4] = {v.x, v.y, v.z, v.w};
    __nv_bfloat16 h[4], l[4];
    #pragma unroll
    for (int j = 0; j < 4; j++) {
        h[j] = __float2bfloat16(y[j]);
        l[j] = __float2bfloat16(y[j] - __bfloat162float(h[j]));
    }
    size_t base = (size_t)i * 4;
    ((__nv_bfloat162*)(oh + base))[0] = __nv_bfloat162(h[0], h[1]);
    ((__nv_bfloat162*)(oh + base))[1] = __nv_bfloat162(h[2], h[3]);
    ((__nv_bfloat162*)(ol + base))[0] = __nv_bfloat162(l[0], l[1]);
    ((__nv_bfloat162*)(ol + base))[1] = __nv_bfloat162(l[2], l[3]);
}

// ---------------------------------------------------------------------------
// HMMA bf16x3 GEMM: C[M,Ntot] = (Ah+Al)[M,K] @ (Bh+Bl)[Ntot,K]^T
// CTA tile 128x128, 256 threads (8 warps, 2Mx4N), warp tile 64x32.
// BK=32 staged in smem, padded rows (stride 40) for conflict-light LDS.
// ---------------------------------------------------------------------------
#define SPAD 40

__global__ void __launch_bounds__(256, 1) gemm3(const __nv_bfloat16* __restrict__ Ah,
                                                const __nv_bfloat16* __restrict__ Al,
                                                const __nv_bfloat16* __restrict__ Bh,
                                                const __nv_bfloat16* __restrict__ Bl,
                                                float* __restrict__ C, int Ntot) {
    __shared__ __align__(16) uint16_t sAh[128][SPAD], sAl[128][SPAD];
    __shared__ __align__(16) uint16_t sBh[128][SPAD], sBl[128][SPAD];

    int tid = threadIdx.x;
    int wid = tid >> 5, lid = tid & 31;
    int wm = wid >> 2, wn = wid & 3;         // 2 x 4 warp grid
    int g = lid >> 2, t = lid & 3;
    int bm = blockIdx.y * 128;
    int bn = blockIdx.x * 128;

    float acc[4][4][4];
    #pragma unroll
    for (int i = 0; i < 4; i++)
        #pragma unroll
        for (int j = 0; j < 4; j++)
            #pragma unroll
            for (int r = 0; r < 4; r++) acc[i][j][r] = 0.f;

    for (int kc = 0; kc < DD; kc += 32) {
        // ---- stage tiles: each array 128 rows x 32 bf16 = 512 8-elem chunks
        #pragma unroll
        for (int c = 0; c < 2; c++) {
            int idx = tid + c * 256;
            int row = idx >> 2, c8 = idx & 3;
            size_t ga = (size_t)(bm + row) * DD + kc + c8 * 8;
            size_t gb = (size_t)(bn + row) * DD + kc + c8 * 8;
            *(uint4*)&sAh[row][c8 * 8] = *(const uint4*)(Ah + ga);
            *(uint4*)&sAl[row][c8 * 8] = *(const uint4*)(Al + ga);
            *(uint4*)&sBh[row][c8 * 8] = *(const uint4*)(Bh + gb);
            *(uint4*)&sBl[row][c8 * 8] = *(const uint4*)(Bl + gb);
        }
        __syncthreads();

        #pragma unroll
        for (int ks = 0; ks < 2; ks++) {
            int kb = ks * 16;
            uint32_t ah[4][4], al[4][4], bh[4][2], bl[4][2];
            #pragma unroll
            for (int i = 0; i < 4; i++) {
                int m0 = wm * 64 + i * 16;
                ah[i][0] = *(const uint32_t*)&sAh[m0 + g][kb + 2 * t];
                ah[i][1] = *(const uint32_t*)&sAh[m0 + 8 + g][kb + 2 * t];
                ah[i][2] = *(const uint32_t*)&sAh[m0 + g][kb + 8 + 2 * t];
                ah[i][3] = *(const uint32_t*)&sAh[m0 + 8 + g][kb + 8 + 2 * t];
                al[i][0] = *(const uint32_t*)&sAl[m0 + g][kb + 2 * t];
                al[i][1] = *(const uint32_t*)&sAl[m0 + 8 + g][kb + 2 * t];
                al[i][2] = *(const uint32_t*)&sAl[m0 + g][kb + 8 + 2 * t];
                al[i][3] = *(const uint32_t*)&sAl[m0 + 8 + g][kb + 8 + 2 * t];
            }
            #pragma unroll
            for (int j = 0; j < 4; j++) {
                int n0 = wn * 32 + j * 8;
                bh[j][0] = *(const uint32_t*)&sBh[n0 + g][kb + 2 * t];
                bh[j][1] = *(const uint32_t*)&sBh[n0 + g][kb + 8 + 2 * t];
                bl[j][0] = *(const uint32_t*)&sBl[n0 + g][kb + 2 * t];
                bl[j][1] = *(const uint32_t*)&sBl[n0 + g][kb + 8 + 2 * t];
            }
            #pragma unroll
            for (int i = 0; i < 4; i++)
                #pragma unroll
                for (int j = 0; j < 4; j++) {
                    MMA16816(acc[i][j], ah[i], bh[j]);
                    MMA16816(acc[i][j], ah[i], bl[j]);
                    MMA16816(acc[i][j], al[i], bh[j]);
                }
        }
        __syncthreads();
    }

    // ---- epilogue
    #pragma unroll
    for (int i = 0; i < 4; i++) {
        int r0 = bm + wm * 64 + i * 16 + g;
        #pragma unroll
        for (int j = 0; j < 4; j++) {
            int c0 = bn + wn * 32 + j * 8 + 2 * t;
            *(float2*)&C[(size_t)r0 * Ntot + c0]       = make_float2(acc[i][j][0], acc[i][j][1]);
            *(float2*)&C[(size_t)(r0 + 8) * Ntot + c0] = make_float2(acc[i][j][2], acc[i][j][3]);
        }
    }
}

// ---------------------------------------------------------------------------
// Causal flash attention, fp32 (unchanged; target for next round).
// ---------------------------------------------------------------------------
__global__ void __launch_bounds__(128) attn_kernel() {
    int qt  = blockIdx.x;
    int bh  = blockIdx.y;
    int b   = bh / HH;
    int h   = bh % HH;
    int tid = threadIdx.x;
    int qi  = qt * 128 + tid;

    __shared__ float4 Ksh[64][16];
    __shared__ float4 Vsh[64][16];

    const float4* qrow = (const float4*)(g_qkv + ((size_t)(b * TT + qi)) * D3 + h * 192);
    float4 q4[16];
    #pragma unroll
    for (int i = 0; i < 16; i++) q4[i] = qrow[i];

    float m = -INFINITY, l = 0.f;
    float4 o4[16];
    #pragma unroll
    for (int i = 0; i < 16; i++) o4[i] = make_float4(0.f, 0.f, 0.f, 0.f);

    int ntiles = qt * 2 + 2;
    for (int kt = 0; kt < ntiles; kt++) {
        #pragma unroll
        for (int j = 0; j < 8; j++) {
            int idx = tid + j * 128;
            int rr = idx >> 4, cc = idx & 15;
            const float4* src = (const float4*)(g_qkv + ((size_t)(b * TT + kt * 64 + rr)) * D3 + h * 192);
            Ksh[rr][cc] = src[16 + cc];
            Vsh[rr][cc] = src[32 + cc];
        }
        __syncthreads();

        int kmax = qi - kt * 64 + 1;
        if (kmax > 64) kmax = 64;
        for (int kk = 0; kk < kmax; kk++) {
            float s = 0.f;
            #pragma unroll
            for (int i = 0; i < 16; i++) {
                float4 k4 = Ksh[kk][i];
                s += q4[i].x * k4.x + q4[i].y * k4.y + q4[i].z * k4.z + q4[i].w * k4.w;
            }
            s *= 0.125f;
            if (s > m) {
                float corr = __expf(m - s);
                m = s;
                l *= corr;
                #pragma unroll
                for (int i = 0; i < 16; i++) {
                    o4[i].x *= corr; o4[i].y *= corr; o4[i].z *= corr; o4[i].w *= corr;
                }
            }
            float p = __expf(s - m);
            l += p;
            #pragma unroll
            for (int i = 0; i < 16; i++) {
                float4 v4 = Vsh[kk][i];
                o4[i].x += p * v4.x; o4[i].y += p * v4.y;
                o4[i].z += p * v4.z; o4[i].w += p * v4.w;
            }
        }
        __syncthreads();
    }

    float inv = 1.f / l;
    float4* dst = (float4*)(g_ctx + ((size_t)(b * TT + qi)) * DD + h * DHD);
    #pragma unroll
    for (int i = 0; i < 16; i++) {
        float4 o = o4[i];
        dst[i] = make_float4(o.x * inv, o.y * inv, o.z * inv, o.w * inv);
    }
}

// ---------------------------------------------------------------------------
// Launch
// ---------------------------------------------------------------------------
extern "C" void kernel_launch(void* const* d_in, const int* in_sizes, int n_in,
                              void* d_out, int out_size) {
    const float* x     = (const float*)d_in[0];
    const float* gamma = (const float*)d_in[1];
    const float* beta  = (const float*)d_in[2];
    const float* w_qkv = (const float*)d_in[3];   // [3072, 1024]
    const float* w_o   = (const float*)d_in[4];   // [1024, 1024]
    float* out = (float*)d_out;                   // [8192, 1024]

    float* qkv; cudaGetSymbolAddress((void**)&qkv, g_qkv);
    float* ctx; cudaGetSymbolAddress((void**)&ctx, g_ctx);
    __nv_bfloat16 *xnh, *xnl, *wqh, *wql, *woh, *wol, *cxh, *cxl;
    cudaGetSymbolAddress((void**)&xnh, g_xnh);
    cudaGetSymbolAddress((void**)&xnl, g_xnl);
    cudaGetSymbolAddress((void**)&wqh, g_wqh);
    cudaGetSymbolAddress((void**)&wql, g_wql);
    cudaGetSymbolAddress((void**)&woh, g_woh);
    cudaGetSymbolAddress((void**)&wol, g_wol);
    cudaGetSymbolAddress((void**)&cxh, g_cxh);
    cudaGetSymbolAddress((void**)&cxl, g_cxl);

    // 1. LayerNorm (fused bf16 hi/lo split output)
    ln_kernel<<<BT, 256>>>(x, gamma, beta);

    // 2. Weight splits
    cvt_kernel<<<(D3 * DD / 4 + 255) / 256, 256>>>(w_qkv, wqh, wql, D3 * DD / 4);
    cvt_kernel<<<(DD * DD / 4 + 255) / 256, 256>>>(w_o, woh, wol, DD * DD / 4);

    // 3. QKV projection via HMMA bf16x3
    {
        dim3 grid(D3 / 128, BT / 128);
        gemm3<<<grid, 256>>>(xnh, xnl, wqh, wql, qkv, D3);
    }

    // 4. Causal attention
    {
        dim3 grid(TT / 128, NB * HH);
        attn_kernel<<<grid, 128>>>();
    }

    // 5. ctx split + output projection
    cvt_kernel<<<(BT * DD / 4 + 255) / 256, 256>>>(ctx, cxh, cxl, BT * DD / 4);
    {
        dim3 grid(DD / 128, BT / 128);
        gemm3<<<grid, 256>>>(cxh, cxl, woh, wol, out, DD);
    }
}

// round 4
// speedup vs baseline: 2.2547x; 1.7245x over previous
#include <cuda_runtime.h>
#include <cuda_bf16.h>
#include <math.h>
#include <stdint.h>

// Problem constants
#define NB   4
#define TT   2048
#define DD   1024
#define HH   16
#define DHD  64
#define BT   (NB * TT)          // 8192 rows
#define D3   (3 * DD)           // 3072

// ---------------------------------------------------------------------------
// Scratch (no cudaMalloc allowed — device globals)
// ---------------------------------------------------------------------------
__device__ float g_qkv[BT * D3];                           // fused QKV (fp32)
__device__ __nv_bfloat16 g_xnh[BT * DD], g_xnl[BT * DD];   // LN output hi/lo
__device__ __nv_bfloat16 g_wqh[D3 * DD], g_wql[D3 * DD];   // W_qkv hi/lo
__device__ __nv_bfloat16 g_woh[DD * DD], g_wol[DD * DD];   // W_o hi/lo
__device__ __nv_bfloat16 g_cxh[BT * DD], g_cxl[BT * DD];   // ctx hi/lo (attn out)

// ---------------------------------------------------------------------------
// HMMA m16n8k16 bf16 (row.col)
// ---------------------------------------------------------------------------
#define MMA16816(Cacc, Afrag, Bfrag) \
    asm volatile( \
        "mma.sync.aligned.m16n8k16.row.col.f32.bf16.bf16.f32 " \
        "{%0,%1,%2,%3}, {%4,%5,%6,%7}, {%8,%9}, {%0,%1,%2,%3};" \
        : "+f"((Cacc)[0]), "+f"((Cacc)[1]), "+f"((Cacc)[2]), "+f"((Cacc)[3]) \
        : "r"((Afrag)[0]), "r"((Afrag)[1]), "r"((Afrag)[2]), "r"((Afrag)[3]), \
          "r"((Bfrag)[0]), "r"((Bfrag)[1]))

__device__ __forceinline__ void split2(float a, float b, uint32_t& hi, uint32_t& lo) {
    __nv_bfloat16 ha = __float2bfloat16(a), hb = __float2bfloat16(b);
    __nv_bfloat16 la = __float2bfloat16(a - __bfloat162float(ha));
    __nv_bfloat16 lb = __float2bfloat16(b - __bfloat162float(hb));
    __nv_bfloat162 th = __halves2bfloat162(ha, hb);
    __nv_bfloat162 tl = __halves2bfloat162(la, lb);
    hi = *reinterpret_cast<uint32_t*>(&th);
    lo = *reinterpret_cast<uint32_t*>(&tl);
}

// ---------------------------------------------------------------------------
// LayerNorm: one block (256 threads) per row; writes bf16 hi/lo split
// ---------------------------------------------------------------------------
__global__ void __launch_bounds__(256) ln_kernel(const float* __restrict__ x,
                                                 const float* __restrict__ gamma,
                                                 const float* __restrict__ beta) {
    int row = blockIdx.x;
    int tid = threadIdx.x;
    __shared__ float red[2][8];

    const float4* xr = (const float4*)(x + (size_t)row * DD);
    float4 xv = xr[tid];
    float s  = xv.x + xv.y + xv.z + xv.w;
    float s2 = xv.x * xv.x + xv.y * xv.y + xv.z * xv.z + xv.w * xv.w;

    #pragma unroll
    for (int o = 16; o > 0; o >>= 1) {
        s  += __shfl_xor_sync(0xffffffffu, s, o);
        s2 += __shfl_xor_sync(0xffffffffu, s2, o);
    }
    if ((tid & 31) == 0) { red[0][tid >> 5] = s; red[1][tid >> 5] = s2; }
    __syncthreads();
    if (tid < 32) {
        float a = (tid < 8) ? red[0][tid] : 0.f;
        float b = (tid < 8) ? red[1][tid] : 0.f;
        #pragma unroll
        for (int o = 4; o > 0; o >>= 1) {
            a += __shfl_xor_sync(0xffffffffu, a, o);
            b += __shfl_xor_sync(0xffffffffu, b, o);
        }
        if (tid == 0) { red[0][0] = a * (1.f / DD); red[1][0] = b * (1.f / DD); }
    }
    __syncthreads();

    float mu   = red[0][0];
    float var  = red[1][0] - mu * mu;
    float rstd = rsqrtf(var + 1e-5f);

    float4 g  = ((const float4*)gamma)[tid];
    float4 bb = ((const float4*)beta)[tid];
    float y[4];
    y[0] = (xv.x - mu) * rstd * g.x + bb.x;
    y[1] = (xv.y - mu) * rstd * g.y + bb.y;
    y[2] = (xv.z - mu) * rstd * g.z + bb.z;
    y[3] = (xv.w - mu) * rstd * g.w + bb.w;

    size_t base = (size_t)row * DD + tid * 4;
    uint32_t h01, l01, h23, l23;
    split2(y[0], y[1], h01, l01);
    split2(y[2], y[3], h23, l23);
    ((uint32_t*)(g_xnh + base))[0] = h01;
    ((uint32_t*)(g_xnh + base))[1] = h23;
    ((uint32_t*)(g_xnl + base))[0] = l01;
    ((uint32_t*)(g_xnl + base))[1] = l23;
}

// ---------------------------------------------------------------------------
// fp32 -> bf16 hi/lo split convert (weights)
// ---------------------------------------------------------------------------
__global__ void __launch_bounds__(256) cvt_kernel(const float* __restrict__ src,
                                                  __nv_bfloat16* __restrict__ oh,
                                                  __nv_bfloat16* __restrict__ ol,
                                                  int n4) {
    int i = blockIdx.x * blockDim.x + threadIdx.x;
    if (i >= n4) return;
    float4 v = ((const float4*)src)[i];
    size_t base = (size_t)i * 4;
    uint32_t h01, l01, h23, l23;
    split2(v.x, v.y, h01, l01);
    split2(v.z, v.w, h23, l23);
    ((uint32_t*)(oh + base))[0] = h01;
    ((uint32_t*)(oh + base))[1] = h23;
    ((uint32_t*)(ol + base))[0] = l01;
    ((uint32_t*)(ol + base))[1] = l23;
}

// ---------------------------------------------------------------------------
// HMMA bf16x3 GEMM (unchanged from R3): C = (Ah+Al) @ (Bh+Bl)^T
// ---------------------------------------------------------------------------
#define SPAD 40

__global__ void __launch_bounds__(256, 1) gemm3(const __nv_bfloat16* __restrict__ Ah,
                                                const __nv_bfloat16* __restrict__ Al,
                                                const __nv_bfloat16* __restrict__ Bh,
                                                const __nv_bfloat16* __restrict__ Bl,
                                                float* __restrict__ C, int Ntot) {
    __shared__ __align__(16) uint16_t sAh[128][SPAD], sAl[128][SPAD];
    __shared__ __align__(16) uint16_t sBh[128][SPAD], sBl[128][SPAD];

    int tid = threadIdx.x;
    int wid = tid >> 5, lid = tid & 31;
    int wm = wid >> 2, wn = wid & 3;
    int g = lid >> 2, t = lid & 3;
    int bm = blockIdx.y * 128;
    int bn = blockIdx.x * 128;

    float acc[4][4][4];
    #pragma unroll
    for (int i = 0; i < 4; i++)
        #pragma unroll
        for (int j = 0; j < 4; j++)
            #pragma unroll
            for (int r = 0; r < 4; r++) acc[i][j][r] = 0.f;

    for (int kc = 0; kc < DD; kc += 32) {
        #pragma unroll
        for (int c = 0; c < 2; c++) {
            int idx = tid + c * 256;
            int row = idx >> 2, c8 = idx & 3;
            size_t ga = (size_t)(bm + row) * DD + kc + c8 * 8;
            size_t gb = (size_t)(bn + row) * DD + kc + c8 * 8;
            *(uint4*)&sAh[row][c8 * 8] = *(const uint4*)(Ah + ga);
            *(uint4*)&sAl[row][c8 * 8] = *(const uint4*)(Al + ga);
            *(uint4*)&sBh[row][c8 * 8] = *(const uint4*)(Bh + gb);
            *(uint4*)&sBl[row][c8 * 8] = *(const uint4*)(Bl + gb);
        }
        __syncthreads();

        #pragma unroll
        for (int ks = 0; ks < 2; ks++) {
            int kb = ks * 16;
            uint32_t ah[4][4], al[4][4], bh[4][2], bl[4][2];
            #pragma unroll
            for (int i = 0; i < 4; i++) {
                int m0 = wm * 64 + i * 16;
                ah[i][0] = *(const uint32_t*)&sAh[m0 + g][kb + 2 * t];
                ah[i][1] = *(const uint32_t*)&sAh[m0 + 8 + g][kb + 2 * t];
                ah[i][2] = *(const uint32_t*)&sAh[m0 + g][kb + 8 + 2 * t];
                ah[i][3] = *(const uint32_t*)&sAh[m0 + 8 + g][kb + 8 + 2 * t];
                al[i][0] = *(const uint32_t*)&sAl[m0 + g][kb + 2 * t];
                al[i][1] = *(const uint32_t*)&sAl[m0 + 8 + g][kb + 2 * t];
                al[i][2] = *(const uint32_t*)&sAl[m0 + g][kb + 8 + 2 * t];
                al[i][3] = *(const uint32_t*)&sAl[m0 + 8 + g][kb + 8 + 2 * t];
            }
            #pragma unroll
            for (int j = 0; j < 4; j++) {
                int n0 = wn * 32 + j * 8;
                bh[j][0] = *(const uint32_t*)&sBh[n0 + g][kb + 2 * t];
                bh[j][1] = *(const uint32_t*)&sBh[n0 + g][kb + 8 + 2 * t];
                bl[j][0] = *(const uint32_t*)&sBl[n0 + g][kb + 2 * t];
                bl[j][1] = *(const uint32_t*)&sBl[n0 + g][kb + 8 + 2 * t];
            }
            #pragma unroll
            for (int i = 0; i < 4; i++)
                #pragma unroll
                for (int j = 0; j < 4; j++) {
                    MMA16816(acc[i][j], ah[i], bh[j]);
                    MMA16816(acc[i][j], ah[i], bl[j]);
                    MMA16816(acc[i][j], al[i], bh[j]);
                }
        }
        __syncthreads();
    }

    #pragma unroll
    for (int i = 0; i < 4; i++) {
        int r0 = bm + wm * 64 + i * 16 + g;
        #pragma unroll
        for (int j = 0; j < 4; j++) {
            int c0 = bn + wn * 32 + j * 8 + 2 * t;
            *(float2*)&C[(size_t)r0 * Ntot + c0]       = make_float2(acc[i][j][0], acc[i][j][1]);
            *(float2*)&C[(size_t)(r0 + 8) * Ntot + c0] = make_float2(acc[i][j][2], acc[i][j][3]);
        }
    }
}

// ---------------------------------------------------------------------------
// HMMA flash attention (causal), bf16x3 splits for S=QK^T and P·V.
// grid=(T/128, B*H), block=256 (8 warps, warp w owns query rows w*16..w*16+15).
// Writes ctx directly as bf16 hi/lo into g_cxh/g_cxl.
// ---------------------------------------------------------------------------
#define APAD 72
struct AttnSmem {
    uint16_t Qh[128][APAD];
    uint16_t Ql[128][APAD];
    uint16_t Kh[64][APAD];
    uint16_t Kl[64][APAD];
    uint16_t Vth[64][APAD];   // V transposed: [d][key]
    uint16_t Vtl[64][APAD];
};

__global__ void __launch_bounds__(256, 1) attn_hmma() {
    int qt  = gridDim.x - 1 - blockIdx.x;   // heavy tiles first
    int bh  = blockIdx.y;
    int b   = bh >> 4;
    int h   = bh & 15;
    int tid = threadIdx.x;
    int w   = tid >> 5, lid = tid & 31;
    int g   = lid >> 2, t = lid & 3;

    extern __shared__ char smem_raw[];
    AttnSmem& S = *reinterpret_cast<AttnSmem*>(smem_raw);

    // ---- stage Q (scaled by 1/8), hi/lo split
    {
        int row = tid >> 1, half = tid & 1;
        const float* qsrc = g_qkv + (size_t)(b * TT + qt * 128 + row) * D3 + h * 192 + half * 32;
        #pragma unroll
        for (int i = 0; i < 8; i++) {
            float4 v = ((const float4*)qsrc)[i];
            int c = half * 32 + i * 4;
            uint32_t h01, l01, h23, l23;
            split2(v.x * 0.125f, v.y * 0.125f, h01, l01);
            split2(v.z * 0.125f, v.w * 0.125f, h23, l23);
            *(uint32_t*)&S.Qh[row][c]     = h01;
            *(uint32_t*)&S.Qh[row][c + 2] = h23;
            *(uint32_t*)&S.Ql[row][c]     = l01;
            *(uint32_t*)&S.Ql[row][c + 2] = l23;
        }
    }

    float oacc[8][4];
    #pragma unroll
    for (int c = 0; c < 8; c++)
        #pragma unroll
        for (int r = 0; r < 4; r++) oacc[c][r] = 0.f;
    float m0 = -1e30f, m1 = -1e30f, l0 = 0.f, l1 = 0.f;

    int ntiles = 2 * qt + 2;
    for (int kt = 0; kt < ntiles; kt++) {
        __syncthreads();   // protect K/V smem from previous iteration's readers
        // ---- stage K tile [64 keys][64 d] and V^T tile [64 d][64 keys]
        {
            int r = tid >> 2, q4 = tid & 3;
            const float* base = g_qkv + (size_t)(b * TT + kt * 64 + r) * D3 + h * 192;
            const float* ksrc = base + 64 + q4 * 16;
            const float* vsrc = base + 128 + q4 * 16;
            #pragma unroll
            for (int j = 0; j < 4; j++) {
                float4 kv = ((const float4*)ksrc)[j];
                int c = q4 * 16 + j * 4;
                uint32_t h01, l01, h23, l23;
                split2(kv.x, kv.y, h01, l01);
                split2(kv.z, kv.w, h23, l23);
                *(uint32_t*)&S.Kh[r][c]     = h01;
                *(uint32_t*)&S.Kh[r][c + 2] = h23;
                *(uint32_t*)&S.Kl[r][c]     = l01;
                *(uint32_t*)&S.Kl[r][c + 2] = l23;

                float4 vv = ((const float4*)vsrc)[j];
                float ve[4] = {vv.x, vv.y, vv.z, vv.w};
                #pragma unroll
                for (int e = 0; e < 4; e++) {
                    int d = c + e;
                    __nv_bfloat16 hi = __float2bfloat16(ve[e]);
                    __nv_bfloat16 lo = __float2bfloat16(ve[e] - __bfloat162float(hi));
                    S.Vth[d][r] = *reinterpret_cast<uint16_t*>(&hi);
                    S.Vtl[d][r] = *reinterpret_cast<uint16_t*>(&lo);
                }
            }
        }
        __syncthreads();

        // ---- S = Q K^T (3-term), fragment accumulators
        float sf[8][4];
        #pragma unroll
        for (int c = 0; c < 8; c++)
            #pragma unroll
            for (int r = 0; r < 4; r++) sf[c][r] = 0.f;

        #pragma unroll
        for (int ks = 0; ks < 4; ks++) {
            int kb = ks * 16;
            int mq = w * 16;
            uint32_t ah[4], al[4];
            ah[0] = *(const uint32_t*)&S.Qh[mq + g][kb + 2 * t];
            ah[1] = *(const uint32_t*)&S.Qh[mq + 8 + g][kb + 2 * t];
            ah[2] = *(const uint32_t*)&S.Qh[mq + g][kb + 8 + 2 * t];
            ah[3] = *(const uint32_t*)&S.Qh[mq + 8 + g][kb + 8 + 2 * t];
            al[0] = *(const uint32_t*)&S.Ql[mq + g][kb + 2 * t];
            al[1] = *(const uint32_t*)&S.Ql[mq + 8 + g][kb + 2 * t];
            al[2] = *(const uint32_t*)&S.Ql[mq + g][kb + 8 + 2 * t];
            al[3] = *(const uint32_t*)&S.Ql[mq + 8 + g][kb + 8 + 2 * t];
            #pragma unroll
            for (int c = 0; c < 8; c++) {
                uint32_t bh[2], bl[2];
                bh[0] = *(const uint32_t*)&S.Kh[c * 8 + g][kb + 2 * t];
                bh[1] = *(const uint32_t*)&S.Kh[c * 8 + g][kb + 8 + 2 * t];
                bl[0] = *(const uint32_t*)&S.Kl[c * 8 + g][kb + 2 * t];
                bl[1] = *(const uint32_t*)&S.Kl[c * 8 + g][kb + 8 + 2 * t];
                MMA16816(sf[c], ah, bh);
                MMA16816(sf[c], ah, bl);
                MMA16816(sf[c], al, bh);
            }
        }

        // ---- causal mask (only the two diagonal tiles need it)
        if (kt >= 2 * qt) {
            int colb = kt * 64 + 2 * t;
            int row0 = qt * 128 + w * 16 + g;
            #pragma unroll
            for (int c = 0; c < 8; c++) {
                int col = colb + c * 8;
                if (col     > row0)     sf[c][0] = -1e30f;
                if (col + 1 > row0)     sf[c][1] = -1e30f;
                if (col     > row0 + 8) sf[c][2] = -1e30f;
                if (col + 1 > row0 + 8) sf[c][3] = -1e30f;
            }
        }

        // ---- online softmax on fragments
        float rm0 = -1e30f, rm1 = -1e30f;
        #pragma unroll
        for (int c = 0; c < 8; c++) {
            rm0 = fmaxf(rm0, fmaxf(sf[c][0], sf[c][1]));
            rm1 = fmaxf(rm1, fmaxf(sf[c][2], sf[c][3]));
        }
        rm0 = fmaxf(rm0, __shfl_xor_sync(0xffffffffu, rm0, 1));
        rm0 = fmaxf(rm0, __shfl_xor_sync(0xffffffffu, rm0, 2));
        rm1 = fmaxf(rm1, __shfl_xor_sync(0xffffffffu, rm1, 1));
        rm1 = fmaxf(rm1, __shfl_xor_sync(0xffffffffu, rm1, 2));

        float mn0 = fmaxf(m0, rm0), mn1 = fmaxf(m1, rm1);
        float corr0 = __expf(m0 - mn0), corr1 = __expf(m1 - mn1);
        l0 *= corr0; l1 *= corr1;
        #pragma unroll
        for (int c = 0; c < 8; c++) {
            oacc[c][0] *= corr0; oacc[c][1] *= corr0;
            oacc[c][2] *= corr1; oacc[c][3] *= corr1;
        }

        uint32_t phA[8], phB[8], plA[8], plB[8];
        float rs0 = 0.f, rs1 = 0.f;
        #pragma unroll
        for (int c = 0; c < 8; c++) {
            float p0 = __expf(sf[c][0] - mn0);
            float p1 = __expf(sf[c][1] - mn0);
            float p2 = __expf(sf[c][2] - mn1);
            float p3 = __expf(sf[c][3] - mn1);
            rs0 += p0 + p1; rs1 += p2 + p3;
            split2(p0, p1, phA[c], plA[c]);
            split2(p2, p3, phB[c], plB[c]);
        }
        rs0 += __shfl_xor_sync(0xffffffffu, rs0, 1);
        rs0 += __shfl_xor_sync(0xffffffffu, rs0, 2);
        rs1 += __shfl_xor_sync(0xffffffffu, rs1, 1);
        rs1 += __shfl_xor_sync(0xffffffffu, rs1, 2);
        l0 += rs0; l1 += rs1;
        m0 = mn0; m1 = mn1;

        // ---- P · V (3-term): A = P fragments, B = V^T
        #pragma unroll
        for (int j = 0; j < 4; j++) {
            uint32_t a_h[4] = {phA[2 * j], phB[2 * j], phA[2 * j + 1], phB[2 * j + 1]};
            uint32_t a_l[4] = {plA[2 * j], plB[2 * j], plA[2 * j + 1], plB[2 * j + 1]};
            int kb = j * 16;
            #pragma unroll
            for (int c = 0; c < 8; c++) {
                uint32_t vh[2], vl[2];
                vh[0] = *(const uint32_t*)&S.Vth[c * 8 + g][kb + 2 * t];
                vh[1] = *(const uint32_t*)&S.Vth[c * 8 + g][kb + 8 + 2 * t];
                vl[0] = *(const uint32_t*)&S.Vtl[c * 8 + g][kb + 2 * t];
                vl[1] = *(const uint32_t*)&S.Vtl[c * 8 + g][kb + 8 + 2 * t];
                MMA16816(oacc[c], a_h, vh);
                MMA16816(oacc[c], a_h, vl);
                MMA16816(oacc[c], a_l, vh);
            }
        }
    }

    // ---- epilogue: divide by l, hi/lo split, write to g_cxh/g_cxl
    float il0 = 1.f / l0, il1 = 1.f / l1;
    int row0 = b * TT + qt * 128 + w * 16 + g;
    #pragma unroll
    for (int c = 0; c < 8; c++) {
        int col = h * DHD + c * 8 + 2 * t;
        uint32_t hA, lA, hB, lB;
        split2(oacc[c][0] * il0, oacc[c][1] * il0, hA, lA);
        split2(oacc[c][2] * il1, oacc[c][3] * il1, hB, lB);
        *(uint32_t*)&g_cxh[(size_t)row0 * DD + col]       = hA;
        *(uint32_t*)&g_cxl[(size_t)row0 * DD + col]       = lA;
        *(uint32_t*)&g_cxh[(size_t)(row0 + 8) * DD + col] = hB;
        *(uint32_t*)&g_cxl[(size_t)(row0 + 8) * DD + col] = lB;
    }
}

// ---------------------------------------------------------------------------
// Launch
// ---------------------------------------------------------------------------
extern "C" void kernel_launch(void* const* d_in, const int* in_sizes, int n_in,
                              void* d_out, int out_size) {
    const float* x     = (const float*)d_in[0];
    const float* gamma = (const float*)d_in[1];
    const float* beta  = (const float*)d_in[2];
    const float* w_qkv = (const float*)d_in[3];   // [3072, 1024]
    const float* w_o   = (const float*)d_in[4];   // [1024, 1024]
    float* out = (float*)d_out;                   // [8192, 1024]

    float* qkv; cudaGetSymbolAddress((void**)&qkv, g_qkv);
    __nv_bfloat16 *xnh, *xnl, *wqh, *wql, *woh, *wol, *cxh, *cxl;
    cudaGetSymbolAddress((void**)&xnh, g_xnh);
    cudaGetSymbolAddress((void**)&xnl, g_xnl);
    cudaGetSymbolAddress((void**)&wqh, g_wqh);
    cudaGetSymbolAddress((void**)&wql, g_wql);
    cudaGetSymbolAddress((void**)&woh, g_woh);
    cudaGetSymbolAddress((void**)&wol, g_wol);
    cudaGetSymbolAddress((void**)&cxh, g_cxh);
    cudaGetSymbolAddress((void**)&cxl, g_cxl);

    static int attn_smem_set = 0;
    if (!attn_smem_set) {
        cudaFuncSetAttribute(attn_hmma, cudaFuncAttributeMaxDynamicSharedMemorySize,
                             (int)sizeof(AttnSmem));
        attn_smem_set = 1;
    }

    // 1. LayerNorm (fused bf16 hi/lo split output)
    ln_kernel<<<BT, 256>>>(x, gamma, beta);

    // 2. Weight splits
    cvt_kernel<<<(D3 * DD / 4 + 255) / 256, 256>>>(w_qkv, wqh, wql, D3 * DD / 4);
    cvt_kernel<<<(DD * DD / 4 + 255) / 256, 256>>>(w_o, woh, wol, DD * DD / 4);

    // 3. QKV projection via HMMA bf16x3
    {
        dim3 grid(D3 / 128, BT / 128);
        gemm3<<<grid, 256>>>(xnh, xnl, wqh, wql, qkv, D3);
    }

    // 4. Causal attention (HMMA flash) — writes cxh/cxl directly
    {
        dim3 grid(TT / 128, NB * HH);
        attn_hmma<<<grid, 256, sizeof(AttnSmem)>>>();
    }

    // 5. Output projection
    {
        dim3 grid(DD / 128, BT / 128);
        gemm3<<<grid, 256>>>(cxh, cxl, woh, wol, out, DD);
    }
}

// round 7
// speedup vs baseline: 2.2609x; 1.0028x over previous
#include <cuda_runtime.h>
#include <cuda_bf16.h>
#include <math.h>
#include <stdint.h>

// Problem constants
#define NB   4
#define TT   2048
#define DD   1024
#define HH   16
#define DHD  64
#define BT   (NB * TT)          // 8192 rows
#define D3   (3 * DD)           // 3072

// ---------------------------------------------------------------------------
// Scratch (no cudaMalloc allowed — device globals)
// ---------------------------------------------------------------------------
__device__ float g_qkv[BT * D3];                           // fused QKV (fp32)
__device__ __nv_bfloat16 g_xnh[BT * DD], g_xnl[BT * DD];   // LN output hi/lo
__device__ __nv_bfloat16 g_wqh[D3 * DD], g_wql[D3 * DD];   // W_qkv hi/lo
__device__ __nv_bfloat16 g_woh[DD * DD], g_wol[DD * DD];   // W_o hi/lo
__device__ __nv_bfloat16 g_cxh[BT * DD], g_cxl[BT * DD];   // ctx hi/lo (attn out)

// ---------------------------------------------------------------------------
// HMMA m16n8k16 bf16 (row.col)
// ---------------------------------------------------------------------------
#define MMA16816(Cacc, Afrag, Bfrag) \
    asm volatile( \
        "mma.sync.aligned.m16n8k16.row.col.f32.bf16.bf16.f32 " \
        "{%0,%1,%2,%3}, {%4,%5,%6,%7}, {%8,%9}, {%0,%1,%2,%3};" \
        : "+f"((Cacc)[0]), "+f"((Cacc)[1]), "+f"((Cacc)[2]), "+f"((Cacc)[3]) \
        : "r"((Afrag)[0]), "r"((Afrag)[1]), "r"((Afrag)[2]), "r"((Afrag)[3]), \
          "r"((Bfrag)[0]), "r"((Bfrag)[1]))

__device__ __forceinline__ void split2(float a, float b, uint32_t& hi, uint32_t& lo) {
    __nv_bfloat16 ha = __float2bfloat16(a), hb = __float2bfloat16(b);
    __nv_bfloat16 la = __float2bfloat16(a - __bfloat162float(ha));
    __nv_bfloat16 lb = __float2bfloat16(b - __bfloat162float(hb));
    __nv_bfloat162 th = __halves2bfloat162(ha, hb);
    __nv_bfloat162 tl = __halves2bfloat162(la, lb);
    hi = *reinterpret_cast<uint32_t*>(&th);
    lo = *reinterpret_cast<uint32_t*>(&tl);
}

// ---------------------------------------------------------------------------
// LayerNorm: one block (256 threads) per row; writes bf16 hi/lo split
// ---------------------------------------------------------------------------
__global__ void __launch_bounds__(256) ln_kernel(const float* __restrict__ x,
                                                 const float* __restrict__ gamma,
                                                 const float* __restrict__ beta) {
    int row = blockIdx.x;
    int tid = threadIdx.x;
    __shared__ float red[2][8];

    const float4* xr = (const float4*)(x + (size_t)row * DD);
    float4 xv = xr[tid];
    float s  = xv.x + xv.y + xv.z + xv.w;
    float s2 = xv.x * xv.x + xv.y * xv.y + xv.z * xv.z + xv.w * xv.w;

    #pragma unroll
    for (int o = 16; o > 0; o >>= 1) {
        s  += __shfl_xor_sync(0xffffffffu, s, o);
        s2 += __shfl_xor_sync(0xffffffffu, s2, o);
    }
    if ((tid & 31) == 0) { red[0][tid >> 5] = s; red[1][tid >> 5] = s2; }
    __syncthreads();
    if (tid < 32) {
        float a = (tid < 8) ? red[0][tid] : 0.f;
        float b = (tid < 8) ? red[1][tid] : 0.f;
        #pragma unroll
        for (int o = 4; o > 0; o >>= 1) {
            a += __shfl_xor_sync(0xffffffffu, a, o);
            b += __shfl_xor_sync(0xffffffffu, b, o);
        }
        if (tid == 0) { red[0][0] = a * (1.f / DD); red[1][0] = b * (1.f / DD); }
    }
    __syncthreads();

    float mu   = red[0][0];
    float var  = red[1][0] - mu * mu;
    float rstd = rsqrtf(var + 1e-5f);

    float4 g  = ((const float4*)gamma)[tid];
    float4 bb = ((const float4*)beta)[tid];
    float y[4];
    y[0] = (xv.x - mu) * rstd * g.x + bb.x;
    y[1] = (xv.y - mu) * rstd * g.y + bb.y;
    y[2] = (xv.z - mu) * rstd * g.z + bb.z;
    y[3] = (xv.w - mu) * rstd * g.w + bb.w;

    size_t base = (size_t)row * DD + tid * 4;
    uint32_t h01, l01, h23, l23;
    split2(y[0], y[1], h01, l01);
    split2(y[2], y[3], h23, l23);
    ((uint32_t*)(g_xnh + base))[0] = h01;
    ((uint32_t*)(g_xnh + base))[1] = h23;
    ((uint32_t*)(g_xnl + base))[0] = l01;
    ((uint32_t*)(g_xnl + base))[1] = l23;
}

// ---------------------------------------------------------------------------
// fp32 -> bf16 hi/lo split convert (weights)
// ---------------------------------------------------------------------------
__global__ void __launch_bounds__(256) cvt_kernel(const float* __restrict__ src,
                                                  __nv_bfloat16* __restrict__ oh,
                                                  __nv_bfloat16* __restrict__ ol,
                                                  int n4) {
    int i = blockIdx.x * blockDim.x + threadIdx.x;
    if (i >= n4) return;
    float4 v = ((const float4*)src)[i];
    size_t base = (size_t)i * 4;
    uint32_t h01, l01, h23, l23;
    split2(v.x, v.y, h01, l01);
    split2(v.z, v.w, h23, l23);
    ((uint32_t*)(oh + base))[0] = h01;
    ((uint32_t*)(oh + base))[1] = h23;
    ((uint32_t*)(ol + base))[0] = l01;
    ((uint32_t*)(ol + base))[1] = l23;
}

// ---------------------------------------------------------------------------
// HMMA bf16x3 GEMM (VERBATIM from R4, the 1417us passing run):
// C[M,Ntot] = (Ah+Al)[M,K] @ (Bh+Bl)[Ntot,K]^T
// CTA tile 128x128, 256 threads (8 warps, 2Mx4N), warp tile 64x32.
// BK=32 staged in smem, padded rows (stride 40) for conflict-light LDS.
// ---------------------------------------------------------------------------
#define SPAD 40

__global__ void __launch_bounds__(256, 1) gemm3(const __nv_bfloat16* __restrict__ Ah,
                                                const __nv_bfloat16* __restrict__ Al,
                                                const __nv_bfloat16* __restrict__ Bh,
                                                const __nv_bfloat16* __restrict__ Bl,
                                                float* __restrict__ C, int Ntot) {
    __shared__ __align__(16) uint16_t sAh[128][SPAD], sAl[128][SPAD];
    __shared__ __align__(16) uint16_t sBh[128][SPAD], sBl[128][SPAD];

    int tid = threadIdx.x;
    int wid = tid >> 5, lid = tid & 31;
    int wm = wid >> 2, wn = wid & 3;         // 2 x 4 warp grid
    int g = lid >> 2, t = lid & 3;
    int bm = blockIdx.y * 128;
    int bn = blockIdx.x * 128;

    float acc[4][4][4];
    #pragma unroll
    for (int i = 0; i < 4; i++)
        #pragma unroll
        for (int j = 0; j < 4; j++)
            #pragma unroll
            for (int r = 0; r < 4; r++) acc[i][j][r] = 0.f;

    for (int kc = 0; kc < DD; kc += 32) {
        // ---- stage tiles: each array 128 rows x 32 bf16 = 512 8-elem chunks
        #pragma unroll
        for (int c = 0; c < 2; c++) {
            int idx = tid + c * 256;
            int row = idx >> 2, c8 = idx & 3;
            size_t ga = (size_t)(bm + row) * DD + kc + c8 * 8;
            size_t gb = (size_t)(bn + row) * DD + kc + c8 * 8;
            *(uint4*)&sAh[row][c8 * 8] = *(const uint4*)(Ah + ga);
            *(uint4*)&sAl[row][c8 * 8] = *(const uint4*)(Al + ga);
            *(uint4*)&sBh[row][c8 * 8] = *(const uint4*)(Bh + gb);
            *(uint4*)&sBl[row][c8 * 8] = *(const uint4*)(Bl + gb);
        }
        __syncthreads();

        #pragma unroll
        for (int ks = 0; ks < 2; ks++) {
            int kb = ks * 16;
            uint32_t ah[4][4], al[4][4], bh[4][2], bl[4][2];
            #pragma unroll
            for (int i = 0; i < 4; i++) {
                int m0 = wm * 64 + i * 16;
                ah[i][0] = *(const uint32_t*)&sAh[m0 + g][kb + 2 * t];
                ah[i][1] = *(const uint32_t*)&sAh[m0 + 8 + g][kb + 2 * t];
                ah[i][2] = *(const uint32_t*)&sAh[m0 + g][kb + 8 + 2 * t];
                ah[i][3] = *(const uint32_t*)&sAh[m0 + 8 + g][kb + 8 + 2 * t];
                al[i][0] = *(const uint32_t*)&sAl[m0 + g][kb + 2 * t];
                al[i][1] = *(const uint32_t*)&sAl[m0 + 8 + g][kb + 2 * t];
                al[i][2] = *(const uint32_t*)&sAl[m0 + g][kb + 8 + 2 * t];
                al[i][3] = *(const uint32_t*)&sAl[m0 + 8 + g][kb + 8 + 2 * t];
            }
            #pragma unroll
            for (int j = 0; j < 4; j++) {
                int n0 = wn * 32 + j * 8;
                bh[j][0] = *(const uint32_t*)&sBh[n0 + g][kb + 2 * t];
                bh[j][1] = *(const uint32_t*)&sBh[n0 + g][kb + 8 + 2 * t];
                bl[j][0] = *(const uint32_t*)&sBl[n0 + g][kb + 2 * t];
                bl[j][1] = *(const uint32_t*)&sBl[n0 + g][kb + 8 + 2 * t];
            }
            #pragma unroll
            for (int i = 0; i < 4; i++)
                #pragma unroll
                for (int j = 0; j < 4; j++) {
                    MMA16816(acc[i][j], ah[i], bh[j]);
                    MMA16816(acc[i][j], ah[i], bl[j]);
                    MMA16816(acc[i][j], al[i], bh[j]);
                }
        }
        __syncthreads();
    }

    #pragma unroll
    for (int i = 0; i < 4; i++) {
        int r0 = bm + wm * 64 + i * 16 + g;
        #pragma unroll
        for (int j = 0; j < 4; j++) {
            int c0 = bn + wn * 32 + j * 8 + 2 * t;
            *(float2*)&C[(size_t)r0 * Ntot + c0]       = make_float2(acc[i][j][0], acc[i][j][1]);
            *(float2*)&C[(size_t)(r0 + 8) * Ntot + c0] = make_float2(acc[i][j][2], acc[i][j][3]);
        }
    }
}

// ---------------------------------------------------------------------------
// HMMA flash attention (causal), bf16x3 splits.
// R4 body with ONE change: Q fragments hoisted into registers (loaded once,
// reused across all key tiles) instead of re-read from smem every tile.
// ---------------------------------------------------------------------------
#define APAD 72
struct AttnSmem {
    uint16_t Qh[128][APAD];
    uint16_t Ql[128][APAD];
    uint16_t Kh[64][APAD];
    uint16_t Kl[64][APAD];
    uint16_t Vth[64][APAD];   // V transposed: [d][key]
    uint16_t Vtl[64][APAD];
};

__global__ void __launch_bounds__(256, 1) attn_hmma() {
    int qt  = gridDim.x - 1 - blockIdx.x;   // heavy tiles first
    int bh  = blockIdx.y;
    int b   = bh >> 4;
    int h   = bh & 15;
    int tid = threadIdx.x;
    int w   = tid >> 5, lid = tid & 31;
    int g   = lid >> 2, t = lid & 3;

    extern __shared__ char smem_raw[];
    AttnSmem& S = *reinterpret_cast<AttnSmem*>(smem_raw);

    // ---- stage Q (scaled by 1/8), hi/lo split
    {
        int row = tid >> 1, half = tid & 1;
        const float* qsrc = g_qkv + (size_t)(b * TT + qt * 128 + row) * D3 + h * 192 + half * 32;
        #pragma unroll
        for (int i = 0; i < 8; i++) {
            float4 v = ((const float4*)qsrc)[i];
            int c = half * 32 + i * 4;
            uint32_t h01, l01, h23, l23;
            split2(v.x * 0.125f, v.y * 0.125f, h01, l01);
            split2(v.z * 0.125f, v.w * 0.125f, h23, l23);
            *(uint32_t*)&S.Qh[row][c]     = h01;
            *(uint32_t*)&S.Qh[row][c + 2] = h23;
            *(uint32_t*)&S.Ql[row][c]     = l01;
            *(uint32_t*)&S.Ql[row][c + 2] = l23;
        }
    }
    __syncthreads();   // Q staging visible to all warps

    // ---- hoist Q fragments to registers (invariant across key tiles)
    uint32_t qh[4][4], ql[4][4];
    {
        int mq = w * 16;
        #pragma unroll
        for (int ks = 0; ks < 4; ks++) {
            int kb = ks * 16;
            qh[ks][0] = *(const uint32_t*)&S.Qh[mq + g][kb + 2 * t];
            qh[ks][1] = *(const uint32_t*)&S.Qh[mq + 8 + g][kb + 2 * t];
            qh[ks][2] = *(const uint32_t*)&S.Qh[mq + g][kb + 8 + 2 * t];
            qh[ks][3] = *(const uint32_t*)&S.Qh[mq + 8 + g][kb + 8 + 2 * t];
            ql[ks][0] = *(const uint32_t*)&S.Ql[mq + g][kb + 2 * t];
            ql[ks][1] = *(const uint32_t*)&S.Ql[mq + 8 + g][kb + 2 * t];
            ql[ks][2] = *(const uint32_t*)&S.Ql[mq + g][kb + 8 + 2 * t];
            ql[ks][3] = *(const uint32_t*)&S.Ql[mq + 8 + g][kb + 8 + 2 * t];
        }
    }

    float oacc[8][4];
    #pragma unroll
    for (int c = 0; c < 8; c++)
        #pragma unroll
        for (int r = 0; r < 4; r++) oacc[c][r] = 0.f;
    float m0 = -1e30f, m1 = -1e30f, l0 = 0.f, l1 = 0.f;

    int ntiles = 2 * qt + 2;
    for (int kt = 0; kt < ntiles; kt++) {
        __syncthreads();   // protect K/V smem from previous iteration's readers
        // ---- stage K tile [64 keys][64 d] and V^T tile [64 d][64 keys]
        {
            int r = tid >> 2, q4 = tid & 3;
            const float* base = g_qkv + (size_t)(b * TT + kt * 64 + r) * D3 + h * 192;
            const float* ksrc = base + 64 + q4 * 16;
            const float* vsrc = base + 128 + q4 * 16;
            #pragma unroll
            for (int j = 0; j < 4; j++) {
                float4 kv = ((const float4*)ksrc)[j];
                int c = q4 * 16 + j * 4;
                uint32_t h01, l01, h23, l23;
                split2(kv.x, kv.y, h01, l01);
                split2(kv.z, kv.w, h23, l23);
                *(uint32_t*)&S.Kh[r][c]     = h01;
                *(uint32_t*)&S.Kh[r][c + 2] = h23;
                *(uint32_t*)&S.Kl[r][c]     = l01;
                *(uint32_t*)&S.Kl[r][c + 2] = l23;

                float4 vv = ((const float4*)vsrc)[j];
                float ve[4] = {vv.x, vv.y, vv.z, vv.w};
                #pragma unroll
                for (int e = 0; e < 4; e++) {
                    int d = c + e;
                    __nv_bfloat16 hi = __float2bfloat16(ve[e]);
                    __nv_bfloat16 lo = __float2bfloat16(ve[e] - __bfloat162float(hi));
                    S.Vth[d][r] = *reinterpret_cast<uint16_t*>(&hi);
                    S.Vtl[d][r] = *reinterpret_cast<uint16_t*>(&lo);
                }
            }
        }
        __syncthreads();

        // ---- S = Q K^T (3-term), fragment accumulators
        float sf[8][4];
        #pragma unroll
        for (int c = 0; c < 8; c++)
            #pragma unroll
            for (int r = 0; r < 4; r++) sf[c][r] = 0.f;

        #pragma unroll
        for (int ks = 0; ks < 4; ks++) {
            int kb = ks * 16;
            #pragma unroll
            for (int c = 0; c < 8; c++) {
                uint32_t bhf[2], blf[2];
                bhf[0] = *(const uint32_t*)&S.Kh[c * 8 + g][kb + 2 * t];
                bhf[1] = *(const uint32_t*)&S.Kh[c * 8 + g][kb + 8 + 2 * t];
                blf[0] = *(const uint32_t*)&S.Kl[c * 8 + g][kb + 2 * t];
                blf[1] = *(const uint32_t*)&S.Kl[c * 8 + g][kb + 8 + 2 * t];
                MMA16816(sf[c], qh[ks], bhf);
                MMA16816(sf[c], qh[ks], blf);
                MMA16816(sf[c], ql[ks], bhf);
            }
        }

        // ---- causal mask (only the two diagonal tiles need it)
        if (kt >= 2 * qt) {
            int colb = kt * 64 + 2 * t;
            int row0 = qt * 128 + w * 16 + g;
            #pragma unroll
            for (int c = 0; c < 8; c++) {
                int col = colb + c * 8;
                if (col     > row0)     sf[c][0] = -1e30f;
                if (col + 1 > row0)     sf[c][1] = -1e30f;
                if (col     > row0 + 8) sf[c][2] = -1e30f;
                if (col + 1 > row0 + 8) sf[c][3] = -1e30f;
            }
        }

        // ---- online softmax on fragments
        float rm0 = -1e30f, rm1 = -1e30f;
        #pragma unroll
        for (int c = 0; c < 8; c++) {
            rm0 = fmaxf(rm0, fmaxf(sf[c][0], sf[c][1]));
            rm1 = fmaxf(rm1, fmaxf(sf[c][2], sf[c][3]));
        }
        rm0 = fmaxf(rm0, __shfl_xor_sync(0xffffffffu, rm0, 1));
        rm0 = fmaxf(rm0, __shfl_xor_sync(0xffffffffu, rm0, 2));
        rm1 = fmaxf(rm1, __shfl_xor_sync(0xffffffffu, rm1, 1));
        rm1 = fmaxf(rm1, __shfl_xor_sync(0xffffffffu, rm1, 2));

        float mn0 = fmaxf(m0, rm0), mn1 = fmaxf(m1, rm1);
        float corr0 = __expf(m0 - mn0), corr1 = __expf(m1 - mn1);
        l0 *= corr0; l1 *= corr1;
        #pragma unroll
        for (int c = 0; c < 8; c++) {
            oacc[c][0] *= corr0; oacc[c][1] *= corr0;
            oacc[c][2] *= corr1; oacc[c][3] *= corr1;
        }

        uint32_t phA[8], phB[8], plA[8], plB[8];
        float rs0 = 0.f, rs1 = 0.f;
        #pragma unroll
        for (int c = 0; c < 8; c++) {
            float p0 = __expf(sf[c][0] - mn0);
            float p1 = __expf(sf[c][1] - mn0);
            float p2 = __expf(sf[c][2] - mn1);
            float p3 = __expf(sf[c][3] - mn1);
            rs0 += p0 + p1; rs1 += p2 + p3;
            split2(p0, p1, phA[c], plA[c]);
            split2(p2, p3, phB[c], plB[c]);
        }
        rs0 += __shfl_xor_sync(0xffffffffu, rs0, 1);
        rs0 += __shfl_xor_sync(0xffffffffu, rs0, 2);
        rs1 += __shfl_xor_sync(0xffffffffu, rs1, 1);
        rs1 += __shfl_xor_sync(0xffffffffu, rs1, 2);
        l0 += rs0; l1 += rs1;
        m0 = mn0; m1 = mn1;

        // ---- P · V (3-term): A = P fragments, B = V^T
        #pragma unroll
        for (int j = 0; j < 4; j++) {
            uint32_t a_h[4] = {phA[2 * j], phB[2 * j], phA[2 * j + 1], phB[2 * j + 1]};
            uint32_t a_l[4] = {plA[2 * j], plB[2 * j], plA[2 * j + 1], plB[2 * j + 1]};
            int kb = j * 16;
            #pragma unroll
            for (int c = 0; c < 8; c++) {
                uint32_t vh[2], vl[2];
                vh[0] = *(const uint32_t*)&S.Vth[c * 8 + g][kb + 2 * t];
                vh[1] = *(const uint32_t*)&S.Vth[c * 8 + g][kb + 8 + 2 * t];
                vl[0] = *(const uint32_t*)&S.Vtl[c * 8 + g][kb + 2 * t];
                vl[1] = *(const uint32_t*)&S.Vtl[c * 8 + g][kb + 8 + 2 * t];
                MMA16816(oacc[c], a_h, vh);
                MMA16816(oacc[c], a_h, vl);
                MMA16816(oacc[c], a_l, vh);
            }
        }
    }

    // ---- epilogue: divide by l, hi/lo split, write to g_cxh/g_cxl
    float il0 = 1.f / l0, il1 = 1.f / l1;
    int row0 = b * TT + qt * 128 + w * 16 + g;
    #pragma unroll
    for (int c = 0; c < 8; c++) {
        int col = h * DHD + c * 8 + 2 * t;
        uint32_t hA, lA, hB, lB;
        split2(oacc[c][0] * il0, oacc[c][1] * il0, hA, lA);
        split2(oacc[c][2] * il1, oacc[c][3] * il1, hB, lB);
        *(uint32_t*)&g_cxh[(size_t)row0 * DD + col]       = hA;
        *(uint32_t*)&g_cxl[(size_t)row0 * DD + col]       = lA;
        *(uint32_t*)&g_cxh[(size_t)(row0 + 8) * DD + col] = hB;
        *(uint32_t*)&g_cxl[(size_t)(row0 + 8) * DD + col] = lB;
    }
}

// ---------------------------------------------------------------------------
// Launch
// ---------------------------------------------------------------------------
extern "C" void kernel_launch(void* const* d_in, const int* in_sizes, int n_in,
                              void* d_out, int out_size) {
    const float* x     = (const float*)d_in[0];
    const float* gamma = (const float*)d_in[1];
    const float* beta  = (const float*)d_in[2];
    const float* w_qkv = (const float*)d_in[3];   // [3072, 1024]
    const float* w_o   = (const float*)d_in[4];   // [1024, 1024]
    float* out = (float*)d_out;                   // [8192, 1024]

    float* qkv; cudaGetSymbolAddress((void**)&qkv, g_qkv);
    __nv_bfloat16 *xnh, *xnl, *wqh, *wql, *woh, *wol, *cxh, *cxl;
    cudaGetSymbolAddress((void**)&xnh, g_xnh);
    cudaGetSymbolAddress((void**)&xnl, g_xnl);
    cudaGetSymbolAddress((void**)&wqh, g_wqh);
    cudaGetSymbolAddress((void**)&wql, g_wql);
    cudaGetSymbolAddress((void**)&woh, g_woh);
    cudaGetSymbolAddress((void**)&wol, g_wol);
    cudaGetSymbolAddress((void**)&cxh, g_cxh);
    cudaGetSymbolAddress((void**)&cxl, g_cxl);

    static int attn_smem_set = 0;
    if (!attn_smem_set) {
        cudaFuncSetAttribute(attn_hmma, cudaFuncAttributeMaxDynamicSharedMemorySize,
                             (int)sizeof(AttnSmem));
        attn_smem_set = 1;
    }

    // 1. LayerNorm (fused bf16 hi/lo split output)
    ln_kernel<<<BT, 256>>>(x, gamma, beta);

    // 2. Weight splits
    cvt_kernel<<<(D3 * DD / 4 + 255) / 256, 256>>>(w_qkv, wqh, wql, D3 * DD / 4);
    cvt_kernel<<<(DD * DD / 4 + 255) / 256, 256>>>(w_o, woh, wol, DD * DD / 4);

    // 3. QKV projection via HMMA bf16x3
    {
        dim3 grid(D3 / 128, BT / 128);
        gemm3<<<grid, 256>>>(xnh, xnl, wqh, wql, qkv, D3);
    }

    // 4. Causal attention (HMMA flash) — writes cxh/cxl directly
    {
        dim3 grid(TT / 128, NB * HH);
        attn_hmma<<<grid, 256, sizeof(AttnSmem)>>>();
    }

    // 5. Output projection
    {
        dim3 grid(DD / 128, BT / 128);
        gemm3<<<grid, 256>>>(cxh, cxl, woh, wol, out, DD);
    }
}

// round 8
// speedup vs baseline: 2.4420x; 1.0801x over previous
#include <cuda_runtime.h>
#include <cuda_bf16.h>
#include <math.h>
#include <stdint.h>

// Problem constants
#define NB   4
#define TT   2048
#define DD   1024
#define HH   16
#define DHD  64
#define BT   (NB * TT)          // 8192 rows
#define D3   (3 * DD)           // 3072

// ---------------------------------------------------------------------------
// Scratch (no cudaMalloc allowed — device globals)
// ---------------------------------------------------------------------------
__device__ float g_qkv[BT * D3];                           // fused QKV (fp32)
__device__ __nv_bfloat16 g_xnh[BT * DD], g_xnl[BT * DD];   // LN output hi/lo
__device__ __nv_bfloat16 g_wqh[D3 * DD], g_wql[D3 * DD];   // W_qkv hi/lo
__device__ __nv_bfloat16 g_woh[DD * DD], g_wol[DD * DD];   // W_o hi/lo
__device__ __nv_bfloat16 g_cxh[BT * DD], g_cxl[BT * DD];   // ctx hi/lo (attn out)

// ---------------------------------------------------------------------------
// HMMA m16n8k16 bf16 (row.col)
// ---------------------------------------------------------------------------
#define MMA16816(Cacc, Afrag, Bfrag) \
    asm volatile( \
        "mma.sync.aligned.m16n8k16.row.col.f32.bf16.bf16.f32 " \
        "{%0,%1,%2,%3}, {%4,%5,%6,%7}, {%8,%9}, {%0,%1,%2,%3};" \
        : "+f"((Cacc)[0]), "+f"((Cacc)[1]), "+f"((Cacc)[2]), "+f"((Cacc)[3]) \
        : "r"((Afrag)[0]), "r"((Afrag)[1]), "r"((Afrag)[2]), "r"((Afrag)[3]), \
          "r"((Bfrag)[0]), "r"((Bfrag)[1]))

__device__ __forceinline__ void split2(float a, float b, uint32_t& hi, uint32_t& lo) {
    __nv_bfloat16 ha = __float2bfloat16(a), hb = __float2bfloat16(b);
    __nv_bfloat16 la = __float2bfloat16(a - __bfloat162float(ha));
    __nv_bfloat16 lb = __float2bfloat16(b - __bfloat162float(hb));
    __nv_bfloat162 th = __halves2bfloat162(ha, hb);
    __nv_bfloat162 tl = __halves2bfloat162(la, lb);
    hi = *reinterpret_cast<uint32_t*>(&th);
    lo = *reinterpret_cast<uint32_t*>(&tl);
}

// ---------------------------------------------------------------------------
// LayerNorm: one block (256 threads) per row; writes bf16 hi/lo split
// ---------------------------------------------------------------------------
__global__ void __launch_bounds__(256) ln_kernel(const float* __restrict__ x,
                                                 const float* __restrict__ gamma,
                                                 const float* __restrict__ beta) {
    int row = blockIdx.x;
    int tid = threadIdx.x;
    __shared__ float red[2][8];

    const float4* xr = (const float4*)(x + (size_t)row * DD);
    float4 xv = xr[tid];
    float s  = xv.x + xv.y + xv.z + xv.w;
    float s2 = xv.x * xv.x + xv.y * xv.y + xv.z * xv.z + xv.w * xv.w;

    #pragma unroll
    for (int o = 16; o > 0; o >>= 1) {
        s  += __shfl_xor_sync(0xffffffffu, s, o);
        s2 += __shfl_xor_sync(0xffffffffu, s2, o);
    }
    if ((tid & 31) == 0) { red[0][tid >> 5] = s; red[1][tid >> 5] = s2; }
    __syncthreads();
    if (tid < 32) {
        float a = (tid < 8) ? red[0][tid] : 0.f;
        float b = (tid < 8) ? red[1][tid] : 0.f;
        #pragma unroll
        for (int o = 4; o > 0; o >>= 1) {
            a += __shfl_xor_sync(0xffffffffu, a, o);
            b += __shfl_xor_sync(0xffffffffu, b, o);
        }
        if (tid == 0) { red[0][0] = a * (1.f / DD); red[1][0] = b * (1.f / DD); }
    }
    __syncthreads();

    float mu   = red[0][0];
    float var  = red[1][0] - mu * mu;
    float rstd = rsqrtf(var + 1e-5f);

    float4 g  = ((const float4*)gamma)[tid];
    float4 bb = ((const float4*)beta)[tid];
    float y[4];
    y[0] = (xv.x - mu) * rstd * g.x + bb.x;
    y[1] = (xv.y - mu) * rstd * g.y + bb.y;
    y[2] = (xv.z - mu) * rstd * g.z + bb.z;
    y[3] = (xv.w - mu) * rstd * g.w + bb.w;

    size_t base = (size_t)row * DD + tid * 4;
    uint32_t h01, l01, h23, l23;
    split2(y[0], y[1], h01, l01);
    split2(y[2], y[3], h23, l23);
    ((uint32_t*)(g_xnh + base))[0] = h01;
    ((uint32_t*)(g_xnh + base))[1] = h23;
    ((uint32_t*)(g_xnl + base))[0] = l01;
    ((uint32_t*)(g_xnl + base))[1] = l23;
}

// ---------------------------------------------------------------------------
// fp32 -> bf16 hi/lo split convert (weights)
// ---------------------------------------------------------------------------
__global__ void __launch_bounds__(256) cvt_kernel(const float* __restrict__ src,
                                                  __nv_bfloat16* __restrict__ oh,
                                                  __nv_bfloat16* __restrict__ ol,
                                                  int n4) {
    int i = blockIdx.x * blockDim.x + threadIdx.x;
    if (i >= n4) return;
    float4 v = ((const float4*)src)[i];
    size_t base = (size_t)i * 4;
    uint32_t h01, l01, h23, l23;
    split2(v.x, v.y, h01, l01);
    split2(v.z, v.w, h23, l23);
    ((uint32_t*)(oh + base))[0] = h01;
    ((uint32_t*)(oh + base))[1] = h23;
    ((uint32_t*)(ol + base))[0] = l01;
    ((uint32_t*)(ol + base))[1] = l23;
}

// ---------------------------------------------------------------------------
// HMMA bf16x3 GEMM: C[M,Ntot] = (Ah+Al)[M,K] @ (Bh+Bl)[Ntot,K]^T
// R4-proven warp body; reshaped CTA: 128 threads (4 warps, 2Mx2N),
// CTA tile 128x64, 3 CTAs/SM for staging/compute overlap across CTAs.
// ---------------------------------------------------------------------------
#define SPAD 40

__global__ void __launch_bounds__(128, 3) gemm3(const __nv_bfloat16* __restrict__ Ah,
                                                const __nv_bfloat16* __restrict__ Al,
                                                const __nv_bfloat16* __restrict__ Bh,
                                                const __nv_bfloat16* __restrict__ Bl,
                                                float* __restrict__ C, int Ntot) {
    __shared__ __align__(16) uint16_t sAh[128][SPAD], sAl[128][SPAD];
    __shared__ __align__(16) uint16_t sBh[64][SPAD],  sBl[64][SPAD];

    int tid = threadIdx.x;
    int wid = tid >> 5, lid = tid & 31;
    int wm = wid >> 1, wn = wid & 1;         // 2 x 2 warp grid
    int g = lid >> 2, t = lid & 3;
    int bm = blockIdx.y * 128;
    int bn = blockIdx.x * 64;

    float acc[4][4][4];
    #pragma unroll
    for (int i = 0; i < 4; i++)
        #pragma unroll
        for (int j = 0; j < 4; j++)
            #pragma unroll
            for (int r = 0; r < 4; r++) acc[i][j][r] = 0.f;

    for (int kc = 0; kc < DD; kc += 32) {
        // ---- stage A tile (128 rows x 32 bf16): 512 chunks / 128 thr = 4 each
        #pragma unroll
        for (int c = 0; c < 4; c++) {
            int idx = tid + c * 128;
            int row = idx >> 2, c8 = idx & 3;
            size_t ga = (size_t)(bm + row) * DD + kc + c8 * 8;
            *(uint4*)&sAh[row][c8 * 8] = *(const uint4*)(Ah + ga);
            *(uint4*)&sAl[row][c8 * 8] = *(const uint4*)(Al + ga);
        }
        // ---- stage B tile (64 rows x 32 bf16): 256 chunks / 128 thr = 2 each
        #pragma unroll
        for (int c = 0; c < 2; c++) {
            int idx = tid + c * 128;
            int row = idx >> 2, c8 = idx & 3;
            size_t gb = (size_t)(bn + row) * DD + kc + c8 * 8;
            *(uint4*)&sBh[row][c8 * 8] = *(const uint4*)(Bh + gb);
            *(uint4*)&sBl[row][c8 * 8] = *(const uint4*)(Bl + gb);
        }
        __syncthreads();

        // ---- compute (warp body verbatim from R4)
        #pragma unroll
        for (int ks = 0; ks < 2; ks++) {
            int kb = ks * 16;
            uint32_t ah[4][4], al[4][4], bh[4][2], bl[4][2];
            #pragma unroll
            for (int i = 0; i < 4; i++) {
                int m0 = wm * 64 + i * 16;
                ah[i][0] = *(const uint32_t*)&sAh[m0 + g][kb + 2 * t];
                ah[i][1] = *(const uint32_t*)&sAh[m0 + 8 + g][kb + 2 * t];
                ah[i][2] = *(const uint32_t*)&sAh[m0 + g][kb + 8 + 2 * t];
                ah[i][3] = *(const uint32_t*)&sAh[m0 + 8 + g][kb + 8 + 2 * t];
                al[i][0] = *(const uint32_t*)&sAl[m0 + g][kb + 2 * t];
                al[i][1] = *(const uint32_t*)&sAl[m0 + 8 + g][kb + 2 * t];
                al[i][2] = *(const uint32_t*)&sAl[m0 + g][kb + 8 + 2 * t];
                al[i][3] = *(const uint32_t*)&sAl[m0 + 8 + g][kb + 8 + 2 * t];
            }
            #pragma unroll
            for (int j = 0; j < 4; j++) {
                int n0 = wn * 32 + j * 8;
                bh[j][0] = *(const uint32_t*)&sBh[n0 + g][kb + 2 * t];
                bh[j][1] = *(const uint32_t*)&sBh[n0 + g][kb + 8 + 2 * t];
                bl[j][0] = *(const uint32_t*)&sBl[n0 + g][kb + 2 * t];
                bl[j][1] = *(const uint32_t*)&sBl[n0 + g][kb + 8 + 2 * t];
            }
            #pragma unroll
            for (int i = 0; i < 4; i++)
                #pragma unroll
                for (int j = 0; j < 4; j++) {
                    MMA16816(acc[i][j], ah[i], bh[j]);
                    MMA16816(acc[i][j], ah[i], bl[j]);
                    MMA16816(acc[i][j], al[i], bh[j]);
                }
        }
        __syncthreads();
    }

    // ---- epilogue (same mapping; N-warp range is 0..1)
    #pragma unroll
    for (int i = 0; i < 4; i++) {
        int r0 = bm + wm * 64 + i * 16 + g;
        #pragma unroll
        for (int j = 0; j < 4; j++) {
            int c0 = bn + wn * 32 + j * 8 + 2 * t;
            *(float2*)&C[(size_t)r0 * Ntot + c0]       = make_float2(acc[i][j][0], acc[i][j][1]);
            *(float2*)&C[(size_t)(r0 + 8) * Ntot + c0] = make_float2(acc[i][j][2], acc[i][j][3]);
        }
    }
}

// ---------------------------------------------------------------------------
// HMMA flash attention (causal), bf16x3 splits (unchanged from R7 pass).
// ---------------------------------------------------------------------------
#define APAD 72
struct AttnSmem {
    uint16_t Qh[128][APAD];
    uint16_t Ql[128][APAD];
    uint16_t Kh[64][APAD];
    uint16_t Kl[64][APAD];
    uint16_t Vth[64][APAD];   // V transposed: [d][key]
    uint16_t Vtl[64][APAD];
};

__global__ void __launch_bounds__(256, 1) attn_hmma() {
    int qt  = gridDim.x - 1 - blockIdx.x;   // heavy tiles first
    int bh  = blockIdx.y;
    int b   = bh >> 4;
    int h   = bh & 15;
    int tid = threadIdx.x;
    int w   = tid >> 5, lid = tid & 31;
    int g   = lid >> 2, t = lid & 3;

    extern __shared__ char smem_raw[];
    AttnSmem& S = *reinterpret_cast<AttnSmem*>(smem_raw);

    // ---- stage Q (scaled by 1/8), hi/lo split
    {
        int row = tid >> 1, half = tid & 1;
        const float* qsrc = g_qkv + (size_t)(b * TT + qt * 128 + row) * D3 + h * 192 + half * 32;
        #pragma unroll
        for (int i = 0; i < 8; i++) {
            float4 v = ((const float4*)qsrc)[i];
            int c = half * 32 + i * 4;
            uint32_t h01, l01, h23, l23;
            split2(v.x * 0.125f, v.y * 0.125f, h01, l01);
            split2(v.z * 0.125f, v.w * 0.125f, h23, l23);
            *(uint32_t*)&S.Qh[row][c]     = h01;
            *(uint32_t*)&S.Qh[row][c + 2] = h23;
            *(uint32_t*)&S.Ql[row][c]     = l01;
            *(uint32_t*)&S.Ql[row][c + 2] = l23;
        }
    }
    __syncthreads();   // Q staging visible to all warps

    // ---- hoist Q fragments to registers (invariant across key tiles)
    uint32_t qh[4][4], ql[4][4];
    {
        int mq = w * 16;
        #pragma unroll
        for (int ks = 0; ks < 4; ks++) {
            int kb = ks * 16;
            qh[ks][0] = *(const uint32_t*)&S.Qh[mq + g][kb + 2 * t];
            qh[ks][1] = *(const uint32_t*)&S.Qh[mq + 8 + g][kb + 2 * t];
            qh[ks][2] = *(const uint32_t*)&S.Qh[mq + g][kb + 8 + 2 * t];
            qh[ks][3] = *(const uint32_t*)&S.Qh[mq + 8 + g][kb + 8 + 2 * t];
            ql[ks][0] = *(const uint32_t*)&S.Ql[mq + g][kb + 2 * t];
            ql[ks][1] = *(const uint32_t*)&S.Ql[mq + 8 + g][kb + 2 * t];
            ql[ks][2] = *(const uint32_t*)&S.Ql[mq + g][kb + 8 + 2 * t];
            ql[ks][3] = *(const uint32_t*)&S.Ql[mq + 8 + g][kb + 8 + 2 * t];
        }
    }

    float oacc[8][4];
    #pragma unroll
    for (int c = 0; c < 8; c++)
        #pragma unroll
        for (int r = 0; r < 4; r++) oacc[c][r] = 0.f;
    float m0 = -1e30f, m1 = -1e30f, l0 = 0.f, l1 = 0.f;

    int ntiles = 2 * qt + 2;
    for (int kt = 0; kt < ntiles; kt++) {
        __syncthreads();   // protect K/V smem from previous iteration's readers
        // ---- stage K tile [64 keys][64 d] and V^T tile [64 d][64 keys]
        {
            int r = tid >> 2, q4 = tid & 3;
            const float* base = g_qkv + (size_t)(b * TT + kt * 64 + r) * D3 + h * 192;
            const float* ksrc = base + 64 + q4 * 16;
            const float* vsrc = base + 128 + q4 * 16;
            #pragma unroll
            for (int j = 0; j < 4; j++) {
                float4 kv = ((const float4*)ksrc)[j];
                int c = q4 * 16 + j * 4;
                uint32_t h01, l01, h23, l23;
                split2(kv.x, kv.y, h01, l01);
                split2(kv.z, kv.w, h23, l23);
                *(uint32_t*)&S.Kh[r][c]     = h01;
                *(uint32_t*)&S.Kh[r][c + 2] = h23;
                *(uint32_t*)&S.Kl[r][c]     = l01;
                *(uint32_t*)&S.Kl[r][c + 2] = l23;

                float4 vv = ((const float4*)vsrc)[j];
                float ve[4] = {vv.x, vv.y, vv.z, vv.w};
                #pragma unroll
                for (int e = 0; e < 4; e++) {
                    int d = c + e;
                    __nv_bfloat16 hi = __float2bfloat16(ve[e]);
                    __nv_bfloat16 lo = __float2bfloat16(ve[e] - __bfloat162float(hi));
                    S.Vth[d][r] = *reinterpret_cast<uint16_t*>(&hi);
                    S.Vtl[d][r] = *reinterpret_cast<uint16_t*>(&lo);
                }
            }
        }
        __syncthreads();

        // ---- S = Q K^T (3-term), fragment accumulators
        float sf[8][4];
        #pragma unroll
        for (int c = 0; c < 8; c++)
            #pragma unroll
            for (int r = 0; r < 4; r++) sf[c][r] = 0.f;

        #pragma unroll
        for (int ks = 0; ks < 4; ks++) {
            int kb = ks * 16;
            #pragma unroll
            for (int c = 0; c < 8; c++) {
                uint32_t bhf[2], blf[2];
                bhf[0] = *(const uint32_t*)&S.Kh[c * 8 + g][kb + 2 * t];
                bhf[1] = *(const uint32_t*)&S.Kh[c * 8 + g][kb + 8 + 2 * t];
                blf[0] = *(const uint32_t*)&S.Kl[c * 8 + g][kb + 2 * t];
                blf[1] = *(const uint32_t*)&S.Kl[c * 8 + g][kb + 8 + 2 * t];
                MMA16816(sf[c], qh[ks], bhf);
                MMA16816(sf[c], qh[ks], blf);
                MMA16816(sf[c], ql[ks], bhf);
            }
        }

        // ---- causal mask (only the two diagonal tiles need it)
        if (kt >= 2 * qt) {
            int colb = kt * 64 + 2 * t;
            int row0 = qt * 128 + w * 16 + g;
            #pragma unroll
            for (int c = 0; c < 8; c++) {
                int col = colb + c * 8;
                if (col     > row0)     sf[c][0] = -1e30f;
                if (col + 1 > row0)     sf[c][1] = -1e30f;
                if (col     > row0 + 8) sf[c][2] = -1e30f;
                if (col + 1 > row0 + 8) sf[c][3] = -1e30f;
            }
        }

        // ---- online softmax on fragments
        float rm0 = -1e30f, rm1 = -1e30f;
        #pragma unroll
        for (int c = 0; c < 8; c++) {
            rm0 = fmaxf(rm0, fmaxf(sf[c][0], sf[c][1]));
            rm1 = fmaxf(rm1, fmaxf(sf[c][2], sf[c][3]));
        }
        rm0 = fmaxf(rm0, __shfl_xor_sync(0xffffffffu, rm0, 1));
        rm0 = fmaxf(rm0, __shfl_xor_sync(0xffffffffu, rm0, 2));
        rm1 = fmaxf(rm1, __shfl_xor_sync(0xffffffffu, rm1, 1));
        rm1 = fmaxf(rm1, __shfl_xor_sync(0xffffffffu, rm1, 2));

        float mn0 = fmaxf(m0, rm0), mn1 = fmaxf(m1, rm1);
        float corr0 = __expf(m0 - mn0), corr1 = __expf(m1 - mn1);
        l0 *= corr0; l1 *= corr1;
        #pragma unroll
        for (int c = 0; c < 8; c++) {
            oacc[c][0] *= corr0; oacc[c][1] *= corr0;
            oacc[c][2] *= corr1; oacc[c][3] *= corr1;
        }

        uint32_t phA[8], phB[8], plA[8], plB[8];
        float rs0 = 0.f, rs1 = 0.f;
        #pragma unroll
        for (int c = 0; c < 8; c++) {
            float p0 = __expf(sf[c][0] - mn0);
            float p1 = __expf(sf[c][1] - mn0);
            float p2 = __expf(sf[c][2] - mn1);
            float p3 = __expf(sf[c][3] - mn1);
            rs0 += p0 + p1; rs1 += p2 + p3;
            split2(p0, p1, phA[c], plA[c]);
            split2(p2, p3, phB[c], plB[c]);
        }
        rs0 += __shfl_xor_sync(0xffffffffu, rs0, 1);
        rs0 += __shfl_xor_sync(0xffffffffu, rs0, 2);
        rs1 += __shfl_xor_sync(0xffffffffu, rs1, 1);
        rs1 += __shfl_xor_sync(0xffffffffu, rs1, 2);
        l0 += rs0; l1 += rs1;
        m0 = mn0; m1 = mn1;

        // ---- P · V (3-term): A = P fragments, B = V^T
        #pragma unroll
        for (int j = 0; j < 4; j++) {
            uint32_t a_h[4] = {phA[2 * j], phB[2 * j], phA[2 * j + 1], phB[2 * j + 1]};
            uint32_t a_l[4] = {plA[2 * j], plB[2 * j], plA[2 * j + 1], plB[2 * j + 1]};
            int kb = j * 16;
            #pragma unroll
            for (int c = 0; c < 8; c++) {
                uint32_t vh[2], vl[2];
                vh[0] = *(const uint32_t*)&S.Vth[c * 8 + g][kb + 2 * t];
                vh[1] = *(const uint32_t*)&S.Vth[c * 8 + g][kb + 8 + 2 * t];
                vl[0] = *(const uint32_t*)&S.Vtl[c * 8 + g][kb + 2 * t];
                vl[1] = *(const uint32_t*)&S.Vtl[c * 8 + g][kb + 8 + 2 * t];
                MMA16816(oacc[c], a_h, vh);
                MMA16816(oacc[c], a_h, vl);
                MMA16816(oacc[c], a_l, vh);
            }
        }
    }

    // ---- epilogue: divide by l, hi/lo split, write to g_cxh/g_cxl
    float il0 = 1.f / l0, il1 = 1.f / l1;
    int row0 = b * TT + qt * 128 + w * 16 + g;
    #pragma unroll
    for (int c = 0; c < 8; c++) {
        int col = h * DHD + c * 8 + 2 * t;
        uint32_t hA, lA, hB, lB;
        split2(oacc[c][0] * il0, oacc[c][1] * il0, hA, lA);
        split2(oacc[c][2] * il1, oacc[c][3] * il1, hB, lB);
        *(uint32_t*)&g_cxh[(size_t)row0 * DD + col]       = hA;
        *(uint32_t*)&g_cxl[(size_t)row0 * DD + col]       = lA;
        *(uint32_t*)&g_cxh[(size_t)(row0 + 8) * DD + col] = hB;
        *(uint32_t*)&g_cxl[(size_t)(row0 + 8) * DD + col] = lB;
    }
}

// ---------------------------------------------------------------------------
// Launch
// ---------------------------------------------------------------------------
extern "C" void kernel_launch(void* const* d_in, const int* in_sizes, int n_in,
                              void* d_out, int out_size) {
    const float* x     = (const float*)d_in[0];
    const float* gamma = (const float*)d_in[1];
    const float* beta  = (const float*)d_in[2];
    const float* w_qkv = (const float*)d_in[3];   // [3072, 1024]
    const float* w_o   = (const float*)d_in[4];   // [1024, 1024]
    float* out = (float*)d_out;                   // [8192, 1024]

    float* qkv; cudaGetSymbolAddress((void**)&qkv, g_qkv);
    __nv_bfloat16 *xnh, *xnl, *wqh, *wql, *woh, *wol, *cxh, *cxl;
    cudaGetSymbolAddress((void**)&xnh, g_xnh);
    cudaGetSymbolAddress((void**)&xnl, g_xnl);
    cudaGetSymbolAddress((void**)&wqh, g_wqh);
    cudaGetSymbolAddress((void**)&wql, g_wql);
    cudaGetSymbolAddress((void**)&woh, g_woh);
    cudaGetSymbolAddress((void**)&wol, g_wol);
    cudaGetSymbolAddress((void**)&cxh, g_cxh);
    cudaGetSymbolAddress((void**)&cxl, g_cxl);

    static int attn_smem_set = 0;
    if (!attn_smem_set) {
        cudaFuncSetAttribute(attn_hmma, cudaFuncAttributeMaxDynamicSharedMemorySize,
                             (int)sizeof(AttnSmem));
        attn_smem_set = 1;
    }

    // 1. LayerNorm (fused bf16 hi/lo split output)
    ln_kernel<<<BT, 256>>>(x, gamma, beta);

    // 2. Weight splits
    cvt_kernel<<<(D3 * DD / 4 + 255) / 256, 256>>>(w_qkv, wqh, wql, D3 * DD / 4);
    cvt_kernel<<<(DD * DD / 4 + 255) / 256, 256>>>(w_o, woh, wol, DD * DD / 4);

    // 3. QKV projection via HMMA bf16x3 (128x64 CTAs, 3/SM)
    {
        dim3 grid(D3 / 64, BT / 128);
        gemm3<<<grid, 128>>>(xnh, xnl, wqh, wql, qkv, D3);
    }

    // 4. Causal attention (HMMA flash) — writes cxh/cxl directly
    {
        dim3 grid(TT / 128, NB * HH);
        attn_hmma<<<grid, 256, sizeof(AttnSmem)>>>();
    }

    // 5. Output projection
    {
        dim3 grid(DD / 64, BT / 128);
        gemm3<<<grid, 128>>>(cxh, cxl, woh, wol, out, DD);
    }
}

// round 9
// speedup vs baseline: 2.4684x; 1.0108x over previous
#include <cuda_runtime.h>
#include <cuda_bf16.h>
#include <math.h>
#include <stdint.h>

// Problem constants
#define NB   4
#define TT   2048
#define DD   1024
#define HH   16
#define DHD  64
#define BT   (NB * TT)          // 8192 rows
#define D3   (3 * DD)           // 3072

// ---------------------------------------------------------------------------
// Scratch (no cudaMalloc allowed — device globals)
// ---------------------------------------------------------------------------
__device__ __nv_bfloat16 g_qh[BT * D3], g_ql[BT * D3];     // QKV bf16 hi/lo
__device__ __nv_bfloat16 g_xnh[BT * DD], g_xnl[BT * DD];   // LN output hi/lo
__device__ __nv_bfloat16 g_wqh[D3 * DD], g_wql[D3 * DD];   // W_qkv hi/lo
__device__ __nv_bfloat16 g_woh[DD * DD], g_wol[DD * DD];   // W_o hi/lo
__device__ __nv_bfloat16 g_cxh[BT * DD], g_cxl[BT * DD];   // ctx hi/lo (attn out)

// ---------------------------------------------------------------------------
// HMMA m16n8k16 bf16 (row.col)
// ---------------------------------------------------------------------------
#define MMA16816(Cacc, Afrag, Bfrag) \
    asm volatile( \
        "mma.sync.aligned.m16n8k16.row.col.f32.bf16.bf16.f32 " \
        "{%0,%1,%2,%3}, {%4,%5,%6,%7}, {%8,%9}, {%0,%1,%2,%3};" \
        : "+f"((Cacc)[0]), "+f"((Cacc)[1]), "+f"((Cacc)[2]), "+f"((Cacc)[3]) \
        : "r"((Afrag)[0]), "r"((Afrag)[1]), "r"((Afrag)[2]), "r"((Afrag)[3]), \
          "r"((Bfrag)[0]), "r"((Bfrag)[1]))

__device__ __forceinline__ void split2(float a, float b, uint32_t& hi, uint32_t& lo) {
    __nv_bfloat16 ha = __float2bfloat16(a), hb = __float2bfloat16(b);
    __nv_bfloat16 la = __float2bfloat16(a - __bfloat162float(ha));
    __nv_bfloat16 lb = __float2bfloat16(b - __bfloat162float(hb));
    __nv_bfloat162 th = __halves2bfloat162(ha, hb);
    __nv_bfloat162 tl = __halves2bfloat162(la, lb);
    hi = *reinterpret_cast<uint32_t*>(&th);
    lo = *reinterpret_cast<uint32_t*>(&tl);
}

// ---------------------------------------------------------------------------
// LayerNorm: one block (256 threads) per row; writes bf16 hi/lo split
// ---------------------------------------------------------------------------
__global__ void __launch_bounds__(256) ln_kernel(const float* __restrict__ x,
                                                 const float* __restrict__ gamma,
                                                 const float* __restrict__ beta) {
    int row = blockIdx.x;
    int tid = threadIdx.x;
    __shared__ float red[2][8];

    const float4* xr = (const float4*)(x + (size_t)row * DD);
    float4 xv = xr[tid];
    float s  = xv.x + xv.y + xv.z + xv.w;
    float s2 = xv.x * xv.x + xv.y * xv.y + xv.z * xv.z + xv.w * xv.w;

    #pragma unroll
    for (int o = 16; o > 0; o >>= 1) {
        s  += __shfl_xor_sync(0xffffffffu, s, o);
        s2 += __shfl_xor_sync(0xffffffffu, s2, o);
    }
    if ((tid & 31) == 0) { red[0][tid >> 5] = s; red[1][tid >> 5] = s2; }
    __syncthreads();
    if (tid < 32) {
        float a = (tid < 8) ? red[0][tid] : 0.f;
        float b = (tid < 8) ? red[1][tid] : 0.f;
        #pragma unroll
        for (int o = 4; o > 0; o >>= 1) {
            a += __shfl_xor_sync(0xffffffffu, a, o);
            b += __shfl_xor_sync(0xffffffffu, b, o);
        }
        if (tid == 0) { red[0][0] = a * (1.f / DD); red[1][0] = b * (1.f / DD); }
    }
    __syncthreads();

    float mu   = red[0][0];
    float var  = red[1][0] - mu * mu;
    float rstd = rsqrtf(var + 1e-5f);

    float4 g  = ((const float4*)gamma)[tid];
    float4 bb = ((const float4*)beta)[tid];
    float y[4];
    y[0] = (xv.x - mu) * rstd * g.x + bb.x;
    y[1] = (xv.y - mu) * rstd * g.y + bb.y;
    y[2] = (xv.z - mu) * rstd * g.z + bb.z;
    y[3] = (xv.w - mu) * rstd * g.w + bb.w;

    size_t base = (size_t)row * DD + tid * 4;
    uint32_t h01, l01, h23, l23;
    split2(y[0], y[1], h01, l01);
    split2(y[2], y[3], h23, l23);
    ((uint32_t*)(g_xnh + base))[0] = h01;
    ((uint32_t*)(g_xnh + base))[1] = h23;
    ((uint32_t*)(g_xnl + base))[0] = l01;
    ((uint32_t*)(g_xnl + base))[1] = l23;
}

// ---------------------------------------------------------------------------
// fp32 -> bf16 hi/lo split convert (weights)
// ---------------------------------------------------------------------------
__global__ void __launch_bounds__(256) cvt_kernel(const float* __restrict__ src,
                                                  __nv_bfloat16* __restrict__ oh,
                                                  __nv_bfloat16* __restrict__ ol,
                                                  int n4) {
    int i = blockIdx.x * blockDim.x + threadIdx.x;
    if (i >= n4) return;
    float4 v = ((const float4*)src)[i];
    size_t base = (size_t)i * 4;
    uint32_t h01, l01, h23, l23;
    split2(v.x, v.y, h01, l01);
    split2(v.z, v.w, h23, l23);
    ((uint32_t*)(oh + base))[0] = h01;
    ((uint32_t*)(oh + base))[1] = h23;
    ((uint32_t*)(ol + base))[0] = l01;
    ((uint32_t*)(ol + base))[1] = l23;
}

// ---------------------------------------------------------------------------
// HMMA bf16x3 GEMM (R8-proven body): C = (Ah+Al) @ (Bh+Bl)^T
// 128 threads (4 warps, 2Mx2N), CTA tile 128x64, 3 CTAs/SM.
// Epilogue: fp32 to Cf if non-null, else bf16 hi/lo split to Chi/Clo.
// ---------------------------------------------------------------------------
#define SPAD 40

__global__ void __launch_bounds__(128, 3) gemm3(const __nv_bfloat16* __restrict__ Ah,
                                                const __nv_bfloat16* __restrict__ Al,
                                                const __nv_bfloat16* __restrict__ Bh,
                                                const __nv_bfloat16* __restrict__ Bl,
                                                float* __restrict__ Cf,
                                                __nv_bfloat16* __restrict__ Chi,
                                                __nv_bfloat16* __restrict__ Clo,
                                                int Ntot) {
    __shared__ __align__(16) uint16_t sAh[128][SPAD], sAl[128][SPAD];
    __shared__ __align__(16) uint16_t sBh[64][SPAD],  sBl[64][SPAD];

    int tid = threadIdx.x;
    int wid = tid >> 5, lid = tid & 31;
    int wm = wid >> 1, wn = wid & 1;         // 2 x 2 warp grid
    int g = lid >> 2, t = lid & 3;
    int bm = blockIdx.y * 128;
    int bn = blockIdx.x * 64;

    float acc[4][4][4];
    #pragma unroll
    for (int i = 0; i < 4; i++)
        #pragma unroll
        for (int j = 0; j < 4; j++)
            #pragma unroll
            for (int r = 0; r < 4; r++) acc[i][j][r] = 0.f;

    for (int kc = 0; kc < DD; kc += 32) {
        #pragma unroll
        for (int c = 0; c < 4; c++) {
            int idx = tid + c * 128;
            int row = idx >> 2, c8 = idx & 3;
            size_t ga = (size_t)(bm + row) * DD + kc + c8 * 8;
            *(uint4*)&sAh[row][c8 * 8] = *(const uint4*)(Ah + ga);
            *(uint4*)&sAl[row][c8 * 8] = *(const uint4*)(Al + ga);
        }
        #pragma unroll
        for (int c = 0; c < 2; c++) {
            int idx = tid + c * 128;
            int row = idx >> 2, c8 = idx & 3;
            size_t gb = (size_t)(bn + row) * DD + kc + c8 * 8;
            *(uint4*)&sBh[row][c8 * 8] = *(const uint4*)(Bh + gb);
            *(uint4*)&sBl[row][c8 * 8] = *(const uint4*)(Bl + gb);
        }
        __syncthreads();

        #pragma unroll
        for (int ks = 0; ks < 2; ks++) {
            int kb = ks * 16;
            uint32_t ah[4][4], al[4][4], bh[4][2], bl[4][2];
            #pragma unroll
            for (int i = 0; i < 4; i++) {
                int m0 = wm * 64 + i * 16;
                ah[i][0] = *(const uint32_t*)&sAh[m0 + g][kb + 2 * t];
                ah[i][1] = *(const uint32_t*)&sAh[m0 + 8 + g][kb + 2 * t];
                ah[i][2] = *(const uint32_t*)&sAh[m0 + g][kb + 8 + 2 * t];
                ah[i][3] = *(const uint32_t*)&sAh[m0 + 8 + g][kb + 8 + 2 * t];
                al[i][0] = *(const uint32_t*)&sAl[m0 + g][kb + 2 * t];
                al[i][1] = *(const uint32_t*)&sAl[m0 + 8 + g][kb + 2 * t];
                al[i][2] = *(const uint32_t*)&sAl[m0 + g][kb + 8 + 2 * t];
                al[i][3] = *(const uint32_t*)&sAl[m0 + 8 + g][kb + 8 + 2 * t];
            }
            #pragma unroll
            for (int j = 0; j < 4; j++) {
                int n0 = wn * 32 + j * 8;
                bh[j][0] = *(const uint32_t*)&sBh[n0 + g][kb + 2 * t];
                bh[j][1] = *(const uint32_t*)&sBh[n0 + g][kb + 8 + 2 * t];
                bl[j][0] = *(const uint32_t*)&sBl[n0 + g][kb + 2 * t];
                bl[j][1] = *(const uint32_t*)&sBl[n0 + g][kb + 8 + 2 * t];
            }
            #pragma unroll
            for (int i = 0; i < 4; i++)
                #pragma unroll
                for (int j = 0; j < 4; j++) {
                    MMA16816(acc[i][j], ah[i], bh[j]);
                    MMA16816(acc[i][j], ah[i], bl[j]);
                    MMA16816(acc[i][j], al[i], bh[j]);
                }
        }
        __syncthreads();
    }

    if (Cf) {
        #pragma unroll
        for (int i = 0; i < 4; i++) {
            int r0 = bm + wm * 64 + i * 16 + g;
            #pragma unroll
            for (int j = 0; j < 4; j++) {
                int c0 = bn + wn * 32 + j * 8 + 2 * t;
                *(float2*)&Cf[(size_t)r0 * Ntot + c0]       = make_float2(acc[i][j][0], acc[i][j][1]);
                *(float2*)&Cf[(size_t)(r0 + 8) * Ntot + c0] = make_float2(acc[i][j][2], acc[i][j][3]);
            }
        }
    } else {
        #pragma unroll
        for (int i = 0; i < 4; i++) {
            int r0 = bm + wm * 64 + i * 16 + g;
            #pragma unroll
            for (int j = 0; j < 4; j++) {
                int c0 = bn + wn * 32 + j * 8 + 2 * t;
                uint32_t hA, lA, hB, lB;
                split2(acc[i][j][0], acc[i][j][1], hA, lA);
                split2(acc[i][j][2], acc[i][j][3], hB, lB);
                *(uint32_t*)&Chi[(size_t)r0 * Ntot + c0]       = hA;
                *(uint32_t*)&Clo[(size_t)r0 * Ntot + c0]       = lA;
                *(uint32_t*)&Chi[(size_t)(r0 + 8) * Ntot + c0] = hB;
                *(uint32_t*)&Clo[(size_t)(r0 + 8) * Ntot + c0] = lB;
            }
        }
    }
}

// ---------------------------------------------------------------------------
// HMMA flash attention v2 (causal), bf16x3 splits.
// 128 threads (4 warps x 16 q-rows = 64-row q-tile), key tiles of 64.
// Reads bf16 hi/lo QKV directly (no conversion math in staging); Q fragments
// loaded straight from gmem. 2 CTAs/SM for stage/compute overlap.
// ---------------------------------------------------------------------------
#define APAD 72

__global__ void __launch_bounds__(128, 2) attn_hmma() {
    int qt  = gridDim.x - 1 - blockIdx.x;   // heavy tiles first
    int bh  = blockIdx.y;
    int b   = bh >> 4;
    int h   = bh & 15;
    int tid = threadIdx.x;
    int w   = tid >> 5, lid = tid & 31;
    int g   = lid >> 2, t = lid & 3;

    __shared__ __align__(16) uint16_t Kh[64][APAD], Kl[64][APAD];
    __shared__ __align__(16) uint16_t Vth[64][APAD], Vtl[64][APAD];  // V^T: [d][key]

    // ---- Q fragments straight from gmem (invariant across key tiles)
    uint32_t qh[4][4], ql[4][4];
    {
        const __nv_bfloat16* qbh = g_qh + (size_t)(b * TT + qt * 64 + w * 16) * D3 + h * 192;
        const __nv_bfloat16* qbl = g_ql + (size_t)(b * TT + qt * 64 + w * 16) * D3 + h * 192;
        #pragma unroll
        for (int ks = 0; ks < 4; ks++) {
            int kb = ks * 16;
            qh[ks][0] = *(const uint32_t*)(qbh + (size_t)g * D3 + kb + 2 * t);
            qh[ks][1] = *(const uint32_t*)(qbh + (size_t)(8 + g) * D3 + kb + 2 * t);
            qh[ks][2] = *(const uint32_t*)(qbh + (size_t)g * D3 + kb + 8 + 2 * t);
            qh[ks][3] = *(const uint32_t*)(qbh + (size_t)(8 + g) * D3 + kb + 8 + 2 * t);
            ql[ks][0] = *(const uint32_t*)(qbl + (size_t)g * D3 + kb + 2 * t);
            ql[ks][1] = *(const uint32_t*)(qbl + (size_t)(8 + g) * D3 + kb + 2 * t);
            ql[ks][2] = *(const uint32_t*)(qbl + (size_t)g * D3 + kb + 8 + 2 * t);
            ql[ks][3] = *(const uint32_t*)(qbl + (size_t)(8 + g) * D3 + kb + 8 + 2 * t);
        }
    }

    float oacc[8][4];
    #pragma unroll
    for (int c = 0; c < 8; c++)
        #pragma unroll
        for (int r = 0; r < 4; r++) oacc[c][r] = 0.f;
    float m0 = -1e30f, m1 = -1e30f, l0 = 0.f, l1 = 0.f;

    int ntiles = qt + 1;
    for (int kt = 0; kt < ntiles; kt++) {
        __syncthreads();   // protect K/V smem from previous iteration's readers
        // ---- stage K tile and V^T tile from bf16 hi/lo (pure copies)
        {
            int r = tid >> 1, half = tid & 1;                 // row 0..63, col half
            size_t base = (size_t)(b * TT + kt * 64 + r) * D3 + h * 192;
            const uint4* kh4 = (const uint4*)(g_qh + base + 64 + half * 32);
            const uint4* kl4 = (const uint4*)(g_ql + base + 64 + half * 32);
            const uint4* vh4 = (const uint4*)(g_qh + base + 128 + half * 32);
            const uint4* vl4 = (const uint4*)(g_ql + base + 128 + half * 32);
            #pragma unroll
            for (int j = 0; j < 4; j++) {
                *(uint4*)&Kh[r][half * 32 + j * 8] = kh4[j];
                *(uint4*)&Kl[r][half * 32 + j * 8] = kl4[j];
                uint4 vh = vh4[j];
                uint4 vl = vl4[j];
                const uint16_t* ph = (const uint16_t*)&vh;
                const uint16_t* pl = (const uint16_t*)&vl;
                #pragma unroll
                for (int e = 0; e < 8; e++) {
                    int d = half * 32 + j * 8 + e;
                    Vth[d][r] = ph[e];
                    Vtl[d][r] = pl[e];
                }
            }
        }
        __syncthreads();

        // ---- S = Q K^T (3-term), fragment accumulators
        float sf[8][4];
        #pragma unroll
        for (int c = 0; c < 8; c++)
            #pragma unroll
            for (int r = 0; r < 4; r++) sf[c][r] = 0.f;

        #pragma unroll
        for (int ks = 0; ks < 4; ks++) {
            int kb = ks * 16;
            #pragma unroll
            for (int c = 0; c < 8; c++) {
                uint32_t bhf[2], blf[2];
                bhf[0] = *(const uint32_t*)&Kh[c * 8 + g][kb + 2 * t];
                bhf[1] = *(const uint32_t*)&Kh[c * 8 + g][kb + 8 + 2 * t];
                blf[0] = *(const uint32_t*)&Kl[c * 8 + g][kb + 2 * t];
                blf[1] = *(const uint32_t*)&Kl[c * 8 + g][kb + 8 + 2 * t];
                MMA16816(sf[c], qh[ks], bhf);
                MMA16816(sf[c], qh[ks], blf);
                MMA16816(sf[c], ql[ks], bhf);
            }
        }

        // ---- scale (1/sqrt(64)) before mask/softmax
        #pragma unroll
        for (int c = 0; c < 8; c++) {
            sf[c][0] *= 0.125f; sf[c][1] *= 0.125f;
            sf[c][2] *= 0.125f; sf[c][3] *= 0.125f;
        }

        // ---- causal mask (only the diagonal tile)
        if (kt == qt) {
            int colb = kt * 64 + 2 * t;
            int row0 = qt * 64 + w * 16 + g;
            #pragma unroll
            for (int c = 0; c < 8; c++) {
                int col = colb + c * 8;
                if (col     > row0)     sf[c][0] = -1e30f;
                if (col + 1 > row0)     sf[c][1] = -1e30f;
                if (col     > row0 + 8) sf[c][2] = -1e30f;
                if (col + 1 > row0 + 8) sf[c][3] = -1e30f;
            }
        }

        // ---- online softmax on fragments
        float rm0 = -1e30f, rm1 = -1e30f;
        #pragma unroll
        for (int c = 0; c < 8; c++) {
            rm0 = fmaxf(rm0, fmaxf(sf[c][0], sf[c][1]));
            rm1 = fmaxf(rm1, fmaxf(sf[c][2], sf[c][3]));
        }
        rm0 = fmaxf(rm0, __shfl_xor_sync(0xffffffffu, rm0, 1));
        rm0 = fmaxf(rm0, __shfl_xor_sync(0xffffffffu, rm0, 2));
        rm1 = fmaxf(rm1, __shfl_xor_sync(0xffffffffu, rm1, 1));
        rm1 = fmaxf(rm1, __shfl_xor_sync(0xffffffffu, rm1, 2));

        float mn0 = fmaxf(m0, rm0), mn1 = fmaxf(m1, rm1);
        float corr0 = __expf(m0 - mn0), corr1 = __expf(m1 - mn1);
        l0 *= corr0; l1 *= corr1;
        #pragma unroll
        for (int c = 0; c < 8; c++) {
            oacc[c][0] *= corr0; oacc[c][1] *= corr0;
            oacc[c][2] *= corr1; oacc[c][3] *= corr1;
        }

        uint32_t phA[8], phB[8], plA[8], plB[8];
        float rs0 = 0.f, rs1 = 0.f;
        #pragma unroll
        for (int c = 0; c < 8; c++) {
            float p0 = __expf(sf[c][0] - mn0);
            float p1 = __expf(sf[c][1] - mn0);
            float p2 = __expf(sf[c][2] - mn1);
            float p3 = __expf(sf[c][3] - mn1);
            rs0 += p0 + p1; rs1 += p2 + p3;
            split2(p0, p1, phA[c], plA[c]);
            split2(p2, p3, phB[c], plB[c]);
        }
        rs0 += __shfl_xor_sync(0xffffffffu, rs0, 1);
        rs0 += __shfl_xor_sync(0xffffffffu, rs0, 2);
        rs1 += __shfl_xor_sync(0xffffffffu, rs1, 1);
        rs1 += __shfl_xor_sync(0xffffffffu, rs1, 2);
        l0 += rs0; l1 += rs1;
        m0 = mn0; m1 = mn1;

        // ---- P · V (3-term): A = P fragments, B = V^T
        #pragma unroll
        for (int j = 0; j < 4; j++) {
            uint32_t a_h[4] = {phA[2 * j], phB[2 * j], phA[2 * j + 1], phB[2 * j + 1]};
            uint32_t a_l[4] = {plA[2 * j], plB[2 * j], plA[2 * j + 1], plB[2 * j + 1]};
            int kb = j * 16;
            #pragma unroll
            for (int c = 0; c < 8; c++) {
                uint32_t vh[2], vl[2];
                vh[0] = *(const uint32_t*)&Vth[c * 8 + g][kb + 2 * t];
                vh[1] = *(const uint32_t*)&Vth[c * 8 + g][kb + 8 + 2 * t];
                vl[0] = *(const uint32_t*)&Vtl[c * 8 + g][kb + 2 * t];
                vl[1] = *(const uint32_t*)&Vtl[c * 8 + g][kb + 8 + 2 * t];
                MMA16816(oacc[c], a_h, vh);
                MMA16816(oacc[c], a_h, vl);
                MMA16816(oacc[c], a_l, vh);
            }
        }
    }

    // ---- epilogue: divide by l, hi/lo split, write to g_cxh/g_cxl
    float il0 = 1.f / l0, il1 = 1.f / l1;
    int row0 = b * TT + qt * 64 + w * 16 + g;
    #pragma unroll
    for (int c = 0; c < 8; c++) {
        int col = h * DHD + c * 8 + 2 * t;
        uint32_t hA, lA, hB, lB;
        split2(oacc[c][0] * il0, oacc[c][1] * il0, hA, lA);
        split2(oacc[c][2] * il1, oacc[c][3] * il1, hB, lB);
        *(uint32_t*)&g_cxh[(size_t)row0 * DD + col]       = hA;
        *(uint32_t*)&g_cxl[(size_t)row0 * DD + col]       = lA;
        *(uint32_t*)&g_cxh[(size_t)(row0 + 8) * DD + col] = hB;
        *(uint32_t*)&g_cxl[(size_t)(row0 + 8) * DD + col] = lB;
    }
}

// ---------------------------------------------------------------------------
// Launch
// ---------------------------------------------------------------------------
extern "C" void kernel_launch(void* const* d_in, const int* in_sizes, int n_in,
                              void* d_out, int out_size) {
    const float* x     = (const float*)d_in[0];
    const float* gamma = (const float*)d_in[1];
    const float* beta  = (const float*)d_in[2];
    const float* w_qkv = (const float*)d_in[3];   // [3072, 1024]
    const float* w_o   = (const float*)d_in[4];   // [1024, 1024]
    float* out = (float*)d_out;                   // [8192, 1024]

    __nv_bfloat16 *qh, *ql, *xnh, *xnl, *wqh, *wql, *woh, *wol, *cxh, *cxl;
    cudaGetSymbolAddress((void**)&qh,  g_qh);
    cudaGetSymbolAddress((void**)&ql,  g_ql);
    cudaGetSymbolAddress((void**)&xnh, g_xnh);
    cudaGetSymbolAddress((void**)&xnl, g_xnl);
    cudaGetSymbolAddress((void**)&wqh, g_wqh);
    cudaGetSymbolAddress((void**)&wql, g_wql);
    cudaGetSymbolAddress((void**)&woh, g_woh);
    cudaGetSymbolAddress((void**)&wol, g_wol);
    cudaGetSymbolAddress((void**)&cxh, g_cxh);
    cudaGetSymbolAddress((void**)&cxl, g_cxl);

    // 1. LayerNorm (fused bf16 hi/lo split output)
    ln_kernel<<<BT, 256>>>(x, gamma, beta);

    // 2. Weight splits
    cvt_kernel<<<(D3 * DD / 4 + 255) / 256, 256>>>(w_qkv, wqh, wql, D3 * DD / 4);
    cvt_kernel<<<(DD * DD / 4 + 255) / 256, 256>>>(w_o, woh, wol, DD * DD / 4);

    // 3. QKV projection -> bf16 hi/lo output
    {
        dim3 grid(D3 / 64, BT / 128);
        gemm3<<<grid, 128>>>(xnh, xnl, wqh, wql, nullptr, qh, ql, D3);
    }

    // 4. Causal attention (HMMA flash v2, 64-row q-tiles, 2 CTAs/SM)
    {
        dim3 grid(TT / 64, NB * HH);
        attn_hmma<<<grid, 128>>>();
    }

    // 5. Output projection (fp32 out)
    {
        dim3 grid(DD / 64, BT / 128);
        gemm3<<<grid, 128>>>(cxh, cxl, woh, wol, out, nullptr, nullptr, DD);
    }
}

// round 10
// speedup vs baseline: 2.5600x; 1.0371x over previous
#include <cuda_runtime.h>
#include <cuda_bf16.h>
#include <math.h>
#include <stdint.h>

// Problem constants
#define NB   4
#define TT   2048
#define DD   1024
#define HH   16
#define DHD  64
#define BT   (NB * TT)          // 8192 rows
#define D3   (3 * DD)           // 3072

// ---------------------------------------------------------------------------
// Scratch (no cudaMalloc allowed — device globals)
// ---------------------------------------------------------------------------
__device__ __nv_bfloat16 g_qh[BT * D3], g_ql[BT * D3];     // QKV bf16 hi/lo
__device__ __nv_bfloat16 g_xnh[BT * DD], g_xnl[BT * DD];   // LN output hi/lo
__device__ __nv_bfloat16 g_wqh[D3 * DD], g_wql[D3 * DD];   // W_qkv hi/lo
__device__ __nv_bfloat16 g_woh[DD * DD], g_wol[DD * DD];   // W_o hi/lo
__device__ __nv_bfloat16 g_cxh[BT * DD], g_cxl[BT * DD];   // ctx hi/lo (attn out)

// ---------------------------------------------------------------------------
// HMMA m16n8k16 bf16 (row.col)
// ---------------------------------------------------------------------------
#define MMA16816(Cacc, Afrag, Bfrag) \
    asm volatile( \
        "mma.sync.aligned.m16n8k16.row.col.f32.bf16.bf16.f32 " \
        "{%0,%1,%2,%3}, {%4,%5,%6,%7}, {%8,%9}, {%0,%1,%2,%3};" \
        : "+f"((Cacc)[0]), "+f"((Cacc)[1]), "+f"((Cacc)[2]), "+f"((Cacc)[3]) \
        : "r"((Afrag)[0]), "r"((Afrag)[1]), "r"((Afrag)[2]), "r"((Afrag)[3]), \
          "r"((Bfrag)[0]), "r"((Bfrag)[1]))

__device__ __forceinline__ void split2(float a, float b, uint32_t& hi, uint32_t& lo) {
    __nv_bfloat16 ha = __float2bfloat16(a), hb = __float2bfloat16(b);
    __nv_bfloat16 la = __float2bfloat16(a - __bfloat162float(ha));
    __nv_bfloat16 lb = __float2bfloat16(b - __bfloat162float(hb));
    __nv_bfloat162 th = __halves2bfloat162(ha, hb);
    __nv_bfloat162 tl = __halves2bfloat162(la, lb);
    hi = *reinterpret_cast<uint32_t*>(&th);
    lo = *reinterpret_cast<uint32_t*>(&tl);
}

// ---------------------------------------------------------------------------
// LayerNorm: one block (256 threads) per row; writes bf16 hi/lo split
// ---------------------------------------------------------------------------
__global__ void __launch_bounds__(256) ln_kernel(const float* __restrict__ x,
                                                 const float* __restrict__ gamma,
                                                 const float* __restrict__ beta) {
    int row = blockIdx.x;
    int tid = threadIdx.x;
    __shared__ float red[2][8];

    const float4* xr = (const float4*)(x + (size_t)row * DD);
    float4 xv = xr[tid];
    float s  = xv.x + xv.y + xv.z + xv.w;
    float s2 = xv.x * xv.x + xv.y * xv.y + xv.z * xv.z + xv.w * xv.w;

    #pragma unroll
    for (int o = 16; o > 0; o >>= 1) {
        s  += __shfl_xor_sync(0xffffffffu, s, o);
        s2 += __shfl_xor_sync(0xffffffffu, s2, o);
    }
    if ((tid & 31) == 0) { red[0][tid >> 5] = s; red[1][tid >> 5] = s2; }
    __syncthreads();
    if (tid < 32) {
        float a = (tid < 8) ? red[0][tid] : 0.f;
        float b = (tid < 8) ? red[1][tid] : 0.f;
        #pragma unroll
        for (int o = 4; o > 0; o >>= 1) {
            a += __shfl_xor_sync(0xffffffffu, a, o);
            b += __shfl_xor_sync(0xffffffffu, b, o);
        }
        if (tid == 0) { red[0][0] = a * (1.f / DD); red[1][0] = b * (1.f / DD); }
    }
    __syncthreads();

    float mu   = red[0][0];
    float var  = red[1][0] - mu * mu;
    float rstd = rsqrtf(var + 1e-5f);

    float4 g  = ((const float4*)gamma)[tid];
    float4 bb = ((const float4*)beta)[tid];
    float y[4];
    y[0] = (xv.x - mu) * rstd * g.x + bb.x;
    y[1] = (xv.y - mu) * rstd * g.y + bb.y;
    y[2] = (xv.z - mu) * rstd * g.z + bb.z;
    y[3] = (xv.w - mu) * rstd * g.w + bb.w;

    size_t base = (size_t)row * DD + tid * 4;
    uint32_t h01, l01, h23, l23;
    split2(y[0], y[1], h01, l01);
    split2(y[2], y[3], h23, l23);
    ((uint32_t*)(g_xnh + base))[0] = h01;
    ((uint32_t*)(g_xnh + base))[1] = h23;
    ((uint32_t*)(g_xnl + base))[0] = l01;
    ((uint32_t*)(g_xnl + base))[1] = l23;
}

// ---------------------------------------------------------------------------
// fp32 -> bf16 hi/lo split convert (weights)
// ---------------------------------------------------------------------------
__global__ void __launch_bounds__(256) cvt_kernel(const float* __restrict__ src,
                                                  __nv_bfloat16* __restrict__ oh,
                                                  __nv_bfloat16* __restrict__ ol,
                                                  int n4) {
    int i = blockIdx.x * blockDim.x + threadIdx.x;
    if (i >= n4) return;
    float4 v = ((const float4*)src)[i];
    size_t base = (size_t)i * 4;
    uint32_t h01, l01, h23, l23;
    split2(v.x, v.y, h01, l01);
    split2(v.z, v.w, h23, l23);
    ((uint32_t*)(oh + base))[0] = h01;
    ((uint32_t*)(oh + base))[1] = h23;
    ((uint32_t*)(ol + base))[0] = l01;
    ((uint32_t*)(ol + base))[1] = l23;
}

// ---------------------------------------------------------------------------
// HMMA bf16x3 GEMM: C = (Ah+Al) @ (Bh+Bl)^T
// 128 threads (4 warps, 2Mx2N), warp tile 64x64, CTA tile 128x128, 2 CTAs/SM.
// Fewer smem bytes per MMA than 64x32 warp tile (smem-BW bound per R9 ncu).
// Epilogue: fp32 to Cf if non-null, else bf16 hi/lo split to Chi/Clo.
// ---------------------------------------------------------------------------
#define SPAD 40

__global__ void __launch_bounds__(128, 2) gemm3(const __nv_bfloat16* __restrict__ Ah,
                                                const __nv_bfloat16* __restrict__ Al,
                                                const __nv_bfloat16* __restrict__ Bh,
                                                const __nv_bfloat16* __restrict__ Bl,
                                                float* __restrict__ Cf,
                                                __nv_bfloat16* __restrict__ Chi,
                                                __nv_bfloat16* __restrict__ Clo,
                                                int Ntot) {
    __shared__ __align__(16) uint16_t sAh[128][SPAD], sAl[128][SPAD];
    __shared__ __align__(16) uint16_t sBh[128][SPAD], sBl[128][SPAD];

    int tid = threadIdx.x;
    int wid = tid >> 5, lid = tid & 31;
    int wm = wid >> 1, wn = wid & 1;         // 2 x 2 warp grid
    int g = lid >> 2, t = lid & 3;
    int bm = blockIdx.y * 128;
    int bn = blockIdx.x * 128;

    float acc[4][8][4];
    #pragma unroll
    for (int i = 0; i < 4; i++)
        #pragma unroll
        for (int j = 0; j < 8; j++)
            #pragma unroll
            for (int r = 0; r < 4; r++) acc[i][j][r] = 0.f;

    for (int kc = 0; kc < DD; kc += 32) {
        // ---- stage A and B tiles (each 128 rows x 32 bf16; 4 chunks/thread)
        #pragma unroll
        for (int c = 0; c < 4; c++) {
            int idx = tid + c * 128;
            int row = idx >> 2, c8 = idx & 3;
            size_t ga = (size_t)(bm + row) * DD + kc + c8 * 8;
            size_t gb = (size_t)(bn + row) * DD + kc + c8 * 8;
            *(uint4*)&sAh[row][c8 * 8] = *(const uint4*)(Ah + ga);
            *(uint4*)&sAl[row][c8 * 8] = *(const uint4*)(Al + ga);
            *(uint4*)&sBh[row][c8 * 8] = *(const uint4*)(Bh + gb);
            *(uint4*)&sBl[row][c8 * 8] = *(const uint4*)(Bl + gb);
        }
        __syncthreads();

        #pragma unroll
        for (int ks = 0; ks < 2; ks++) {
            int kb = ks * 16;
            uint32_t ah[4][4], al[4][4], bh[8][2], bl[8][2];
            #pragma unroll
            for (int i = 0; i < 4; i++) {
                int m0 = wm * 64 + i * 16;
                ah[i][0] = *(const uint32_t*)&sAh[m0 + g][kb + 2 * t];
                ah[i][1] = *(const uint32_t*)&sAh[m0 + 8 + g][kb + 2 * t];
                ah[i][2] = *(const uint32_t*)&sAh[m0 + g][kb + 8 + 2 * t];
                ah[i][3] = *(const uint32_t*)&sAh[m0 + 8 + g][kb + 8 + 2 * t];
                al[i][0] = *(const uint32_t*)&sAl[m0 + g][kb + 2 * t];
                al[i][1] = *(const uint32_t*)&sAl[m0 + 8 + g][kb + 2 * t];
                al[i][2] = *(const uint32_t*)&sAl[m0 + g][kb + 8 + 2 * t];
                al[i][3] = *(const uint32_t*)&sAl[m0 + 8 + g][kb + 8 + 2 * t];
            }
            #pragma unroll
            for (int j = 0; j < 8; j++) {
                int n0 = wn * 64 + j * 8;
                bh[j][0] = *(const uint32_t*)&sBh[n0 + g][kb + 2 * t];
                bh[j][1] = *(const uint32_t*)&sBh[n0 + g][kb + 8 + 2 * t];
                bl[j][0] = *(const uint32_t*)&sBl[n0 + g][kb + 2 * t];
                bl[j][1] = *(const uint32_t*)&sBl[n0 + g][kb + 8 + 2 * t];
            }
            #pragma unroll
            for (int i = 0; i < 4; i++)
                #pragma unroll
                for (int j = 0; j < 8; j++) {
                    MMA16816(acc[i][j], ah[i], bh[j]);
                    MMA16816(acc[i][j], ah[i], bl[j]);
                    MMA16816(acc[i][j], al[i], bh[j]);
                }
        }
        __syncthreads();
    }

    if (Cf) {
        #pragma unroll
        for (int i = 0; i < 4; i++) {
            int r0 = bm + wm * 64 + i * 16 + g;
            #pragma unroll
            for (int j = 0; j < 8; j++) {
                int c0 = bn + wn * 64 + j * 8 + 2 * t;
                *(float2*)&Cf[(size_t)r0 * Ntot + c0]       = make_float2(acc[i][j][0], acc[i][j][1]);
                *(float2*)&Cf[(size_t)(r0 + 8) * Ntot + c0] = make_float2(acc[i][j][2], acc[i][j][3]);
            }
        }
    } else {
        #pragma unroll
        for (int i = 0; i < 4; i++) {
            int r0 = bm + wm * 64 + i * 16 + g;
            #pragma unroll
            for (int j = 0; j < 8; j++) {
                int c0 = bn + wn * 64 + j * 8 + 2 * t;
                uint32_t hA, lA, hB, lB;
                split2(acc[i][j][0], acc[i][j][1], hA, lA);
                split2(acc[i][j][2], acc[i][j][3], hB, lB);
                *(uint32_t*)&Chi[(size_t)r0 * Ntot + c0]       = hA;
                *(uint32_t*)&Clo[(size_t)r0 * Ntot + c0]       = lA;
                *(uint32_t*)&Chi[(size_t)(r0 + 8) * Ntot + c0] = hB;
                *(uint32_t*)&Clo[(size_t)(r0 + 8) * Ntot + c0] = lB;
            }
        }
    }
}

// ---------------------------------------------------------------------------
// HMMA flash attention v2 (causal), bf16x3 splits (unchanged from R9 pass).
// 128 threads (4 warps x 16 q-rows = 64-row q-tile), key tiles of 64.
// ---------------------------------------------------------------------------
#define APAD 72

__global__ void __launch_bounds__(128, 2) attn_hmma() {
    int qt  = gridDim.x - 1 - blockIdx.x;   // heavy tiles first
    int bh  = blockIdx.y;
    int b   = bh >> 4;
    int h   = bh & 15;
    int tid = threadIdx.x;
    int w   = tid >> 5, lid = tid & 31;
    int g   = lid >> 2, t = lid & 3;

    __shared__ __align__(16) uint16_t Kh[64][APAD], Kl[64][APAD];
    __shared__ __align__(16) uint16_t Vth[64][APAD], Vtl[64][APAD];  // V^T: [d][key]

    // ---- Q fragments straight from gmem (invariant across key tiles)
    uint32_t qh[4][4], ql[4][4];
    {
        const __nv_bfloat16* qbh = g_qh + (size_t)(b * TT + qt * 64 + w * 16) * D3 + h * 192;
        const __nv_bfloat16* qbl = g_ql + (size_t)(b * TT + qt * 64 + w * 16) * D3 + h * 192;
        #pragma unroll
        for (int ks = 0; ks < 4; ks++) {
            int kb = ks * 16;
            qh[ks][0] = *(const uint32_t*)(qbh + (size_t)g * D3 + kb + 2 * t);
            qh[ks][1] = *(const uint32_t*)(qbh + (size_t)(8 + g) * D3 + kb + 2 * t);
            qh[ks][2] = *(const uint32_t*)(qbh + (size_t)g * D3 + kb + 8 + 2 * t);
            qh[ks][3] = *(const uint32_t*)(qbh + (size_t)(8 + g) * D3 + kb + 8 + 2 * t);
            ql[ks][0] = *(const uint32_t*)(qbl + (size_t)g * D3 + kb + 2 * t);
            ql[ks][1] = *(const uint32_t*)(qbl + (size_t)(8 + g) * D3 + kb + 2 * t);
            ql[ks][2] = *(const uint32_t*)(qbl + (size_t)g * D3 + kb + 8 + 2 * t);
            ql[ks][3] = *(const uint32_t*)(qbl + (size_t)(8 + g) * D3 + kb + 8 + 2 * t);
        }
    }

    float oacc[8][4];
    #pragma unroll
    for (int c = 0; c < 8; c++)
        #pragma unroll
        for (int r = 0; r < 4; r++) oacc[c][r] = 0.f;
    float m0 = -1e30f, m1 = -1e30f, l0 = 0.f, l1 = 0.f;

    int ntiles = qt + 1;
    for (int kt = 0; kt < ntiles; kt++) {
        __syncthreads();
        {
            int r = tid >> 1, half = tid & 1;
            size_t base = (size_t)(b * TT + kt * 64 + r) * D3 + h * 192;
            const uint4* kh4 = (const uint4*)(g_qh + base + 64 + half * 32);
            const uint4* kl4 = (const uint4*)(g_ql + base + 64 + half * 32);
            const uint4* vh4 = (const uint4*)(g_qh + base + 128 + half * 32);
            const uint4* vl4 = (const uint4*)(g_ql + base + 128 + half * 32);
            #pragma unroll
            for (int j = 0; j < 4; j++) {
                *(uint4*)&Kh[r][half * 32 + j * 8] = kh4[j];
                *(uint4*)&Kl[r][half * 32 + j * 8] = kl4[j];
                uint4 vh = vh4[j];
                uint4 vl = vl4[j];
                const uint16_t* ph = (const uint16_t*)&vh;
                const uint16_t* pl = (const uint16_t*)&vl;
                #pragma unroll
                for (int e = 0; e < 8; e++) {
                    int d = half * 32 + j * 8 + e;
                    Vth[d][r] = ph[e];
                    Vtl[d][r] = pl[e];
                }
            }
        }
        __syncthreads();

        float sf[8][4];
        #pragma unroll
        for (int c = 0; c < 8; c++)
            #pragma unroll
            for (int r = 0; r < 4; r++) sf[c][r] = 0.f;

        #pragma unroll
        for (int ks = 0; ks < 4; ks++) {
            int kb = ks * 16;
            #pragma unroll
            for (int c = 0; c < 8; c++) {
                uint32_t bhf[2], blf[2];
                bhf[0] = *(const uint32_t*)&Kh[c * 8 + g][kb + 2 * t];
                bhf[1] = *(const uint32_t*)&Kh[c * 8 + g][kb + 8 + 2 * t];
                blf[0] = *(const uint32_t*)&Kl[c * 8 + g][kb + 2 * t];
                blf[1] = *(const uint32_t*)&Kl[c * 8 + g][kb + 8 + 2 * t];
                MMA16816(sf[c], qh[ks], bhf);
                MMA16816(sf[c], qh[ks], blf);
                MMA16816(sf[c], ql[ks], bhf);
            }
        }

        #pragma unroll
        for (int c = 0; c < 8; c++) {
            sf[c][0] *= 0.125f; sf[c][1] *= 0.125f;
            sf[c][2] *= 0.125f; sf[c][3] *= 0.125f;
        }

        if (kt == qt) {
            int colb = kt * 64 + 2 * t;
            int row0 = qt * 64 + w * 16 + g;
            #pragma unroll
            for (int c = 0; c < 8; c++) {
                int col = colb + c * 8;
                if (col     > row0)     sf[c][0] = -1e30f;
                if (col + 1 > row0)     sf[c][1] = -1e30f;
                if (col     > row0 + 8) sf[c][2] = -1e30f;
                if (col + 1 > row0 + 8) sf[c][3] = -1e30f;
            }
        }

        float rm0 = -1e30f, rm1 = -1e30f;
        #pragma unroll
        for (int c = 0; c < 8; c++) {
            rm0 = fmaxf(rm0, fmaxf(sf[c][0], sf[c][1]));
            rm1 = fmaxf(rm1, fmaxf(sf[c][2], sf[c][3]));
        }
        rm0 = fmaxf(rm0, __shfl_xor_sync(0xffffffffu, rm0, 1));
        rm0 = fmaxf(rm0, __shfl_xor_sync(0xffffffffu, rm0, 2));
        rm1 = fmaxf(rm1, __shfl_xor_sync(0xffffffffu, rm1, 1));
        rm1 = fmaxf(rm1, __shfl_xor_sync(0xffffffffu, rm1, 2));

        float mn0 = fmaxf(m0, rm0), mn1 = fmaxf(m1, rm1);
        float corr0 = __expf(m0 - mn0), corr1 = __expf(m1 - mn1);
        l0 *= corr0; l1 *= corr1;
        #pragma unroll
        for (int c = 0; c < 8; c++) {
            oacc[c][0] *= corr0; oacc[c][1] *= corr0;
            oacc[c][2] *= corr1; oacc[c][3] *= corr1;
        }

        uint32_t phA[8], phB[8], plA[8], plB[8];
        float rs0 = 0.f, rs1 = 0.f;
        #pragma unroll
        for (int c = 0; c < 8; c++) {
            float p0 = __expf(sf[c][0] - mn0);
            float p1 = __expf(sf[c][1] - mn0);
            float p2 = __expf(sf[c][2] - mn1);
            float p3 = __expf(sf[c][3] - mn1);
            rs0 += p0 + p1; rs1 += p2 + p3;
            split2(p0, p1, phA[c], plA[c]);
            split2(p2, p3, phB[c], plB[c]);
        }
        rs0 += __shfl_xor_sync(0xffffffffu, rs0, 1);
        rs0 += __shfl_xor_sync(0xffffffffu, rs0, 2);
        rs1 += __shfl_xor_sync(0xffffffffu, rs1, 1);
        rs1 += __shfl_xor_sync(0xffffffffu, rs1, 2);
        l0 += rs0; l1 += rs1;
        m0 = mn0; m1 = mn1;

        #pragma unroll
        for (int j = 0; j < 4; j++) {
            uint32_t a_h[4] = {phA[2 * j], phB[2 * j], phA[2 * j + 1], phB[2 * j + 1]};
            uint32_t a_l[4] = {plA[2 * j], plB[2 * j], plA[2 * j + 1], plB[2 * j + 1]};
            int kb = j * 16;
            #pragma unroll
            for (int c = 0; c < 8; c++) {
                uint32_t vh[2], vl[2];
                vh[0] = *(const uint32_t*)&Vth[c * 8 + g][kb + 2 * t];
                vh[1] = *(const uint32_t*)&Vth[c * 8 + g][kb + 8 + 2 * t];
                vl[0] = *(const uint32_t*)&Vtl[c * 8 + g][kb + 2 * t];
                vl[1] = *(const uint32_t*)&Vtl[c * 8 + g][kb + 8 + 2 * t];
                MMA16816(oacc[c], a_h, vh);
                MMA16816(oacc[c], a_h, vl);
                MMA16816(oacc[c], a_l, vh);
            }
        }
    }

    float il0 = 1.f / l0, il1 = 1.f / l1;
    int row0 = b * TT + qt * 64 + w * 16 + g;
    #pragma unroll
    for (int c = 0; c < 8; c++) {
        int col = h * DHD + c * 8 + 2 * t;
        uint32_t hA, lA, hB, lB;
        split2(oacc[c][0] * il0, oacc[c][1] * il0, hA, lA);
        split2(oacc[c][2] * il1, oacc[c][3] * il1, hB, lB);
        *(uint32_t*)&g_cxh[(size_t)row0 * DD + col]       = hA;
        *(uint32_t*)&g_cxl[(size_t)row0 * DD + col]       = lA;
        *(uint32_t*)&g_cxh[(size_t)(row0 + 8) * DD + col] = hB;
        *(uint32_t*)&g_cxl[(size_t)(row0 + 8) * DD + col] = lB;
    }
}

// ---------------------------------------------------------------------------
// Launch
// ---------------------------------------------------------------------------
extern "C" void kernel_launch(void* const* d_in, const int* in_sizes, int n_in,
                              void* d_out, int out_size) {
    const float* x     = (const float*)d_in[0];
    const float* gamma = (const float*)d_in[1];
    const float* beta  = (const float*)d_in[2];
    const float* w_qkv = (const float*)d_in[3];   // [3072, 1024]
    const float* w_o   = (const float*)d_in[4];   // [1024, 1024]
    float* out = (float*)d_out;                   // [8192, 1024]

    __nv_bfloat16 *qh, *ql, *xnh, *xnl, *wqh, *wql, *woh, *wol, *cxh, *cxl;
    cudaGetSymbolAddress((void**)&qh,  g_qh);
    cudaGetSymbolAddress((void**)&ql,  g_ql);
    cudaGetSymbolAddress((void**)&xnh, g_xnh);
    cudaGetSymbolAddress((void**)&xnl, g_xnl);
    cudaGetSymbolAddress((void**)&wqh, g_wqh);
    cudaGetSymbolAddress((void**)&wql, g_wql);
    cudaGetSymbolAddress((void**)&woh, g_woh);
    cudaGetSymbolAddress((void**)&wol, g_wol);
    cudaGetSymbolAddress((void**)&cxh, g_cxh);
    cudaGetSymbolAddress((void**)&cxl, g_cxl);

    // 1. LayerNorm (fused bf16 hi/lo split output)
    ln_kernel<<<BT, 256>>>(x, gamma, beta);

    // 2. Weight splits
    cvt_kernel<<<(D3 * DD / 4 + 255) / 256, 256>>>(w_qkv, wqh, wql, D3 * DD / 4);
    cvt_kernel<<<(DD * DD / 4 + 255) / 256, 256>>>(w_o, woh, wol, DD * DD / 4);

    // 3. QKV projection -> bf16 hi/lo output (128x128 CTAs, warp 64x64)
    {
        dim3 grid(D3 / 128, BT / 128);
        gemm3<<<grid, 128>>>(xnh, xnl, wqh, wql, nullptr, qh, ql, D3);
    }

    // 4. Causal attention (HMMA flash v2, 64-row q-tiles, 2 CTAs/SM)
    {
        dim3 grid(TT / 64, NB * HH);
        attn_hmma<<<grid, 128>>>();
    }

    // 5. Output projection (fp32 out)
    {
        dim3 grid(DD / 128, BT / 128);
        gemm3<<<grid, 128>>>(cxh, cxl, woh, wol, out, nullptr, nullptr, DD);
    }
}

// round 11
// speedup vs baseline: 2.8158x; 1.0999x over previous
#include <cuda_runtime.h>
#include <cuda_bf16.h>
#include <math.h>
#include <stdint.h>

// Problem constants
#define NB   4
#define TT   2048
#define DD   1024
#define HH   16
#define DHD  64
#define BT   (NB * TT)          // 8192 rows
#define D3   (3 * DD)           // 3072

// ---------------------------------------------------------------------------
// Scratch (no cudaMalloc allowed — device globals)
// ---------------------------------------------------------------------------
__device__ __nv_bfloat16 g_qh[BT * D3], g_ql[BT * D3];     // QKV bf16 hi/lo
__device__ __nv_bfloat16 g_xnh[BT * DD], g_xnl[BT * DD];   // LN output hi/lo
__device__ __nv_bfloat16 g_wqh[D3 * DD], g_wql[D3 * DD];   // W_qkv hi/lo
__device__ __nv_bfloat16 g_woh[DD * DD], g_wol[DD * DD];   // W_o hi/lo
__device__ __nv_bfloat16 g_cxh[BT * DD], g_cxl[BT * DD];   // ctx hi/lo (attn out)

// ---------------------------------------------------------------------------
// PTX helpers
// ---------------------------------------------------------------------------
#define MMA16816(Cacc, Afrag, Bfrag) \
    asm volatile( \
        "mma.sync.aligned.m16n8k16.row.col.f32.bf16.bf16.f32 " \
        "{%0,%1,%2,%3}, {%4,%5,%6,%7}, {%8,%9}, {%0,%1,%2,%3};" \
        : "+f"((Cacc)[0]), "+f"((Cacc)[1]), "+f"((Cacc)[2]), "+f"((Cacc)[3]) \
        : "r"((Afrag)[0]), "r"((Afrag)[1]), "r"((Afrag)[2]), "r"((Afrag)[3]), \
          "r"((Bfrag)[0]), "r"((Bfrag)[1]))

#define CP16(saddr, gptr) \
    asm volatile("cp.async.cg.shared.global [%0], [%1], 16;" :: "r"(saddr), "l"(gptr))
#define CP_COMMIT() asm volatile("cp.async.commit_group;" ::: "memory")

__device__ __forceinline__ uint32_t sptr(const void* p) {
    return (uint32_t)__cvta_generic_to_shared(p);
}

__device__ __forceinline__ void split2(float a, float b, uint32_t& hi, uint32_t& lo) {
    __nv_bfloat16 ha = __float2bfloat16(a), hb = __float2bfloat16(b);
    __nv_bfloat16 la = __float2bfloat16(a - __bfloat162float(ha));
    __nv_bfloat16 lb = __float2bfloat16(b - __bfloat162float(hb));
    __nv_bfloat162 th = __halves2bfloat162(ha, hb);
    __nv_bfloat162 tl = __halves2bfloat162(la, lb);
    hi = *reinterpret_cast<uint32_t*>(&th);
    lo = *reinterpret_cast<uint32_t*>(&tl);
}

// ---------------------------------------------------------------------------
// LayerNorm: one block (256 threads) per row; writes bf16 hi/lo split
// ---------------------------------------------------------------------------
__global__ void __launch_bounds__(256) ln_kernel(const float* __restrict__ x,
                                                 const float* __restrict__ gamma,
                                                 const float* __restrict__ beta) {
    int row = blockIdx.x;
    int tid = threadIdx.x;
    __shared__ float red[2][8];

    const float4* xr = (const float4*)(x + (size_t)row * DD);
    float4 xv = xr[tid];
    float s  = xv.x + xv.y + xv.z + xv.w;
    float s2 = xv.x * xv.x + xv.y * xv.y + xv.z * xv.z + xv.w * xv.w;

    #pragma unroll
    for (int o = 16; o > 0; o >>= 1) {
        s  += __shfl_xor_sync(0xffffffffu, s, o);
        s2 += __shfl_xor_sync(0xffffffffu, s2, o);
    }
    if ((tid & 31) == 0) { red[0][tid >> 5] = s; red[1][tid >> 5] = s2; }
    __syncthreads();
    if (tid < 32) {
        float a = (tid < 8) ? red[0][tid] : 0.f;
        float b = (tid < 8) ? red[1][tid] : 0.f;
        #pragma unroll
        for (int o = 4; o > 0; o >>= 1) {
            a += __shfl_xor_sync(0xffffffffu, a, o);
            b += __shfl_xor_sync(0xffffffffu, b, o);
        }
        if (tid == 0) { red[0][0] = a * (1.f / DD); red[1][0] = b * (1.f / DD); }
    }
    __syncthreads();

    float mu   = red[0][0];
    float var  = red[1][0] - mu * mu;
    float rstd = rsqrtf(var + 1e-5f);

    float4 g  = ((const float4*)gamma)[tid];
    float4 bb = ((const float4*)beta)[tid];
    float y[4];
    y[0] = (xv.x - mu) * rstd * g.x + bb.x;
    y[1] = (xv.y - mu) * rstd * g.y + bb.y;
    y[2] = (xv.z - mu) * rstd * g.z + bb.z;
    y[3] = (xv.w - mu) * rstd * g.w + bb.w;

    size_t base = (size_t)row * DD + tid * 4;
    uint32_t h01, l01, h23, l23;
    split2(y[0], y[1], h01, l01);
    split2(y[2], y[3], h23, l23);
    ((uint32_t*)(g_xnh + base))[0] = h01;
    ((uint32_t*)(g_xnh + base))[1] = h23;
    ((uint32_t*)(g_xnl + base))[0] = l01;
    ((uint32_t*)(g_xnl + base))[1] = l23;
}

// ---------------------------------------------------------------------------
// fp32 -> bf16 hi/lo split convert (weights)
// ---------------------------------------------------------------------------
__global__ void __launch_bounds__(256) cvt_kernel(const float* __restrict__ src,
                                                  __nv_bfloat16* __restrict__ oh,
                                                  __nv_bfloat16* __restrict__ ol,
                                                  int n4) {
    int i = blockIdx.x * blockDim.x + threadIdx.x;
    if (i >= n4) return;
    float4 v = ((const float4*)src)[i];
    size_t base = (size_t)i * 4;
    uint32_t h01, l01, h23, l23;
    split2(v.x, v.y, h01, l01);
    split2(v.z, v.w, h23, l23);
    ((uint32_t*)(oh + base))[0] = h01;
    ((uint32_t*)(oh + base))[1] = h23;
    ((uint32_t*)(ol + base))[0] = l01;
    ((uint32_t*)(ol + base))[1] = l23;
}

// ---------------------------------------------------------------------------
// HMMA bf16x3 GEMM: C = (Ah+Al) @ (Bh+Bl)^T
// R10-proven compute body (warp tile 64x64, CTA 128x128, 128 threads) +
// 2-stage cp.async double-buffered staging. Loop runs over ALL DD/32 chunks.
// Epilogue: fp32 to Cf if non-null, else bf16 hi/lo split to Chi/Clo.
// ---------------------------------------------------------------------------
#define SPAD 40
#define TILE_ELEMS (128 * SPAD)                 // 5120 uint16 per array
#define GEMM_SMEM_BYTES (2 * 4 * TILE_ELEMS * 2)   // 2 stages x 4 arrays = 81920 B
#define NCHUNK (DD / 32)                        // 32

#define TILEP(s, arr) ((uint16_t(*)[SPAD])(dsm + (size_t)((s) * 4 + (arr)) * TILE_ELEMS))

__global__ void __launch_bounds__(128, 2) gemm3(const __nv_bfloat16* __restrict__ Ah,
                                                const __nv_bfloat16* __restrict__ Al,
                                                const __nv_bfloat16* __restrict__ Bh,
                                                const __nv_bfloat16* __restrict__ Bl,
                                                float* __restrict__ Cf,
                                                __nv_bfloat16* __restrict__ Chi,
                                                __nv_bfloat16* __restrict__ Clo,
                                                int Ntot) {
    extern __shared__ __align__(16) uint16_t dsm[];

    int tid = threadIdx.x;
    int wid = tid >> 5, lid = tid & 31;
    int wm = wid >> 1, wn = wid & 1;         // 2 x 2 warp grid
    int g = lid >> 2, t = lid & 3;
    int bm = blockIdx.y * 128;
    int bn = blockIdx.x * 128;

    float acc[4][8][4];
    #pragma unroll
    for (int i = 0; i < 4; i++)
        #pragma unroll
        for (int j = 0; j < 8; j++)
            #pragma unroll
            for (int r = 0; r < 4; r++) acc[i][j][r] = 0.f;

    #define GISSUE(s, kc) do { \
        uint16_t (*tAh)[SPAD] = TILEP(s, 0); \
        uint16_t (*tAl)[SPAD] = TILEP(s, 1); \
        uint16_t (*tBh)[SPAD] = TILEP(s, 2); \
        uint16_t (*tBl)[SPAD] = TILEP(s, 3); \
        _Pragma("unroll") \
        for (int c = 0; c < 4; c++) { \
            int idx = tid + c * 128; \
            int row = idx >> 2, c8 = idx & 3; \
            size_t ga = (size_t)(bm + row) * DD + (kc) + c8 * 8; \
            size_t gb = (size_t)(bn + row) * DD + (kc) + c8 * 8; \
            CP16(sptr(&tAh[row][c8 * 8]), Ah + ga); \
            CP16(sptr(&tAl[row][c8 * 8]), Al + ga); \
            CP16(sptr(&tBh[row][c8 * 8]), Bh + gb); \
            CP16(sptr(&tBl[row][c8 * 8]), Bl + gb); \
        } \
        CP_COMMIT(); \
    } while (0)

    GISSUE(0, 0);

    for (int ch = 0; ch < NCHUNK; ch++) {      // NCHUNK = DD/32: FULL K coverage
        int cur = ch & 1;
        if (ch + 1 < NCHUNK) {
            GISSUE((ch + 1) & 1, (ch + 1) * 32);
            asm volatile("cp.async.wait_group 1;" ::: "memory");
        } else {
            asm volatile("cp.async.wait_group 0;" ::: "memory");
        }
        __syncthreads();

        uint16_t (*sAh)[SPAD] = TILEP(cur, 0);
        uint16_t (*sAl)[SPAD] = TILEP(cur, 1);
        uint16_t (*sBh)[SPAD] = TILEP(cur, 2);
        uint16_t (*sBl)[SPAD] = TILEP(cur, 3);

        #pragma unroll
        for (int ks = 0; ks < 2; ks++) {
            int kb = ks * 16;
            uint32_t ah[4][4], al[4][4], bh[8][2], bl[8][2];
            #pragma unroll
            for (int i = 0; i < 4; i++) {
                int m0 = wm * 64 + i * 16;
                ah[i][0] = *(const uint32_t*)&sAh[m0 + g][kb + 2 * t];
                ah[i][1] = *(const uint32_t*)&sAh[m0 + 8 + g][kb + 2 * t];
                ah[i][2] = *(const uint32_t*)&sAh[m0 + g][kb + 8 + 2 * t];
                ah[i][3] = *(const uint32_t*)&sAh[m0 + 8 + g][kb + 8 + 2 * t];
                al[i][0] = *(const uint32_t*)&sAl[m0 + g][kb + 2 * t];
                al[i][1] = *(const uint32_t*)&sAl[m0 + 8 + g][kb + 2 * t];
                al[i][2] = *(const uint32_t*)&sAl[m0 + g][kb + 8 + 2 * t];
                al[i][3] = *(const uint32_t*)&sAl[m0 + 8 + g][kb + 8 + 2 * t];
            }
            #pragma unroll
            for (int j = 0; j < 8; j++) {
                int n0 = wn * 64 + j * 8;
                bh[j][0] = *(const uint32_t*)&sBh[n0 + g][kb + 2 * t];
                bh[j][1] = *(const uint32_t*)&sBh[n0 + g][kb + 8 + 2 * t];
                bl[j][0] = *(const uint32_t*)&sBl[n0 + g][kb + 2 * t];
                bl[j][1] = *(const uint32_t*)&sBl[n0 + g][kb + 8 + 2 * t];
            }
            #pragma unroll
            for (int i = 0; i < 4; i++)
                #pragma unroll
                for (int j = 0; j < 8; j++) {
                    MMA16816(acc[i][j], ah[i], bh[j]);
                    MMA16816(acc[i][j], ah[i], bl[j]);
                    MMA16816(acc[i][j], al[i], bh[j]);
                }
        }
        __syncthreads();
    }

    if (Cf) {
        #pragma unroll
        for (int i = 0; i < 4; i++) {
            int r0 = bm + wm * 64 + i * 16 + g;
            #pragma unroll
            for (int j = 0; j < 8; j++) {
                int c0 = bn + wn * 64 + j * 8 + 2 * t;
                *(float2*)&Cf[(size_t)r0 * Ntot + c0]       = make_float2(acc[i][j][0], acc[i][j][1]);
                *(float2*)&Cf[(size_t)(r0 + 8) * Ntot + c0] = make_float2(acc[i][j][2], acc[i][j][3]);
            }
        }
    } else {
        #pragma unroll
        for (int i = 0; i < 4; i++) {
            int r0 = bm + wm * 64 + i * 16 + g;
            #pragma unroll
            for (int j = 0; j < 8; j++) {
                int c0 = bn + wn * 64 + j * 8 + 2 * t;
                uint32_t hA, lA, hB, lB;
                split2(acc[i][j][0], acc[i][j][1], hA, lA);
                split2(acc[i][j][2], acc[i][j][3], hB, lB);
                *(uint32_t*)&Chi[(size_t)r0 * Ntot + c0]       = hA;
                *(uint32_t*)&Clo[(size_t)r0 * Ntot + c0]       = lA;
                *(uint32_t*)&Chi[(size_t)(r0 + 8) * Ntot + c0] = hB;
                *(uint32_t*)&Clo[(size_t)(r0 + 8) * Ntot + c0] = lB;
            }
        }
    }
}

// ---------------------------------------------------------------------------
// HMMA flash attention v2 (causal), bf16x3 splits (unchanged from R10 pass).
// 128 threads (4 warps x 16 q-rows = 64-row q-tile), key tiles of 64.
// ---------------------------------------------------------------------------
#define APAD 72

__global__ void __launch_bounds__(128, 2) attn_hmma() {
    int qt  = gridDim.x - 1 - blockIdx.x;   // heavy tiles first
    int bh  = blockIdx.y;
    int b   = bh >> 4;
    int h   = bh & 15;
    int tid = threadIdx.x;
    int w   = tid >> 5, lid = tid & 31;
    int g   = lid >> 2, t = lid & 3;

    __shared__ __align__(16) uint16_t Kh[64][APAD], Kl[64][APAD];
    __shared__ __align__(16) uint16_t Vth[64][APAD], Vtl[64][APAD];  // V^T: [d][key]

    // ---- Q fragments straight from gmem (invariant across key tiles)
    uint32_t qh[4][4], ql[4][4];
    {
        const __nv_bfloat16* qbh = g_qh + (size_t)(b * TT + qt * 64 + w * 16) * D3 + h * 192;
        const __nv_bfloat16* qbl = g_ql + (size_t)(b * TT + qt * 64 + w * 16) * D3 + h * 192;
        #pragma unroll
        for (int ks = 0; ks < 4; ks++) {
            int kb = ks * 16;
            qh[ks][0] = *(const uint32_t*)(qbh + (size_t)g * D3 + kb + 2 * t);
            qh[ks][1] = *(const uint32_t*)(qbh + (size_t)(8 + g) * D3 + kb + 2 * t);
            qh[ks][2] = *(const uint32_t*)(qbh + (size_t)g * D3 + kb + 8 + 2 * t);
            qh[ks][3] = *(const uint32_t*)(qbh + (size_t)(8 + g) * D3 + kb + 8 + 2 * t);
            ql[ks][0] = *(const uint32_t*)(qbl + (size_t)g * D3 + kb + 2 * t);
            ql[ks][1] = *(const uint32_t*)(qbl + (size_t)(8 + g) * D3 + kb + 2 * t);
            ql[ks][2] = *(const uint32_t*)(qbl + (size_t)g * D3 + kb + 8 + 2 * t);
            ql[ks][3] = *(const uint32_t*)(qbl + (size_t)(8 + g) * D3 + kb + 8 + 2 * t);
        }
    }

    float oacc[8][4];
    #pragma unroll
    for (int c = 0; c < 8; c++)
        #pragma unroll
        for (int r = 0; r < 4; r++) oacc[c][r] = 0.f;
    float m0 = -1e30f, m1 = -1e30f, l0 = 0.f, l1 = 0.f;

    int ntiles = qt + 1;
    for (int kt = 0; kt < ntiles; kt++) {
        __syncthreads();
        {
            int r = tid >> 1, half = tid & 1;
            size_t base = (size_t)(b * TT + kt * 64 + r) * D3 + h * 192;
            const uint4* kh4 = (const uint4*)(g_qh + base + 64 + half * 32);
            const uint4* kl4 = (const uint4*)(g_ql + base + 64 + half * 32);
            const uint4* vh4 = (const uint4*)(g_qh + base + 128 + half * 32);
            const uint4* vl4 = (const uint4*)(g_ql + base + 128 + half * 32);
            #pragma unroll
            for (int j = 0; j < 4; j++) {
                *(uint4*)&Kh[r][half * 32 + j * 8] = kh4[j];
                *(uint4*)&Kl[r][half * 32 + j * 8] = kl4[j];
                uint4 vh = vh4[j];
                uint4 vl = vl4[j];
                const uint16_t* ph = (const uint16_t*)&vh;
                const uint16_t* pl = (const uint16_t*)&vl;
                #pragma unroll
                for (int e = 0; e < 8; e++) {
                    int d = half * 32 + j * 8 + e;
                    Vth[d][r] = ph[e];
                    Vtl[d][r] = pl[e];
                }
            }
        }
        __syncthreads();

        float sf[8][4];
        #pragma unroll
        for (int c = 0; c < 8; c++)
            #pragma unroll
            for (int r = 0; r < 4; r++) sf[c][r] = 0.f;

        #pragma unroll
        for (int ks = 0; ks < 4; ks++) {
            int kb = ks * 16;
            #pragma unroll
            for (int c = 0; c < 8; c++) {
                uint32_t bhf[2], blf[2];
                bhf[0] = *(const uint32_t*)&Kh[c * 8 + g][kb + 2 * t];
                bhf[1] = *(const uint32_t*)&Kh[c * 8 + g][kb + 8 + 2 * t];
                blf[0] = *(const uint32_t*)&Kl[c * 8 + g][kb + 2 * t];
                blf[1] = *(const uint32_t*)&Kl[c * 8 + g][kb + 8 + 2 * t];
                MMA16816(sf[c], qh[ks], bhf);
                MMA16816(sf[c], qh[ks], blf);
                MMA16816(sf[c], ql[ks], bhf);
            }
        }

        #pragma unroll
        for (int c = 0; c < 8; c++) {
            sf[c][0] *= 0.125f; sf[c][1] *= 0.125f;
            sf[c][2] *= 0.125f; sf[c][3] *= 0.125f;
        }

        if (kt == qt) {
            int colb = kt * 64 + 2 * t;
            int row0 = qt * 64 + w * 16 + g;
            #pragma unroll
            for (int c = 0; c < 8; c++) {
                int col = colb + c * 8;
                if (col     > row0)     sf[c][0] = -1e30f;
                if (col + 1 > row0)     sf[c][1] = -1e30f;
                if (col     > row0 + 8) sf[c][2] = -1e30f;
                if (col + 1 > row0 + 8) sf[c][3] = -1e30f;
            }
        }

        float rm0 = -1e30f, rm1 = -1e30f;
        #pragma unroll
        for (int c = 0; c < 8; c++) {
            rm0 = fmaxf(rm0, fmaxf(sf[c][0], sf[c][1]));
            rm1 = fmaxf(rm1, fmaxf(sf[c][2], sf[c][3]));
        }
        rm0 = fmaxf(rm0, __shfl_xor_sync(0xffffffffu, rm0, 1));
        rm0 = fmaxf(rm0, __shfl_xor_sync(0xffffffffu, rm0, 2));
        rm1 = fmaxf(rm1, __shfl_xor_sync(0xffffffffu, rm1, 1));
        rm1 = fmaxf(rm1, __shfl_xor_sync(0xffffffffu, rm1, 2));

        float mn0 = fmaxf(m0, rm0), mn1 = fmaxf(m1, rm1);
        float corr0 = __expf(m0 - mn0), corr1 = __expf(m1 - mn1);
        l0 *= corr0; l1 *= corr1;
        #pragma unroll
        for (int c = 0; c < 8; c++) {
            oacc[c][0] *= corr0; oacc[c][1] *= corr0;
            oacc[c][2] *= corr1; oacc[c][3] *= corr1;
        }

        uint32_t phA[8], phB[8], plA[8], plB[8];
        float rs0 = 0.f, rs1 = 0.f;
        #pragma unroll
        for (int c = 0; c < 8; c++) {
            float p0 = __expf(sf[c][0] - mn0);
            float p1 = __expf(sf[c][1] - mn0);
            float p2 = __expf(sf[c][2] - mn1);
            float p3 = __expf(sf[c][3] - mn1);
            rs0 += p0 + p1; rs1 += p2 + p3;
            split2(p0, p1, phA[c], plA[c]);
            split2(p2, p3, phB[c], plB[c]);
        }
        rs0 += __shfl_xor_sync(0xffffffffu, rs0, 1);
        rs0 += __shfl_xor_sync(0xffffffffu, rs0, 2);
        rs1 += __shfl_xor_sync(0xffffffffu, rs1, 1);
        rs1 += __shfl_xor_sync(0xffffffffu, rs1, 2);
        l0 += rs0; l1 += rs1;
        m0 = mn0; m1 = mn1;

        #pragma unroll
        for (int j = 0; j < 4; j++) {
            uint32_t a_h[4] = {phA[2 * j], phB[2 * j], phA[2 * j + 1], phB[2 * j + 1]};
            uint32_t a_l[4] = {plA[2 * j], plB[2 * j], plA[2 * j + 1], plB[2 * j + 1]};
            int kb = j * 16;
            #pragma unroll
            for (int c = 0; c < 8; c++) {
                uint32_t vh[2], vl[2];
                vh[0] = *(const uint32_t*)&Vth[c * 8 + g][kb + 2 * t];
                vh[1] = *(const uint32_t*)&Vth[c * 8 + g][kb + 8 + 2 * t];
                vl[0] = *(const uint32_t*)&Vtl[c * 8 + g][kb + 2 * t];
                vl[1] = *(const uint32_t*)&Vtl[c * 8 + g][kb + 8 + 2 * t];
                MMA16816(oacc[c], a_h, vh);
                MMA16816(oacc[c], a_h, vl);
                MMA16816(oacc[c], a_l, vh);
            }
        }
    }

    float il0 = 1.f / l0, il1 = 1.f / l1;
    int row0 = b * TT + qt * 64 + w * 16 + g;
    #pragma unroll
    for (int c = 0; c < 8; c++) {
        int col = h * DHD + c * 8 + 2 * t;
        uint32_t hA, lA, hB, lB;
        split2(oacc[c][0] * il0, oacc[c][1] * il0, hA, lA);
        split2(oacc[c][2] * il1, oacc[c][3] * il1, hB, lB);
        *(uint32_t*)&g_cxh[(size_t)row0 * DD + col]       = hA;
        *(uint32_t*)&g_cxl[(size_t)row0 * DD + col]       = lA;
        *(uint32_t*)&g_cxh[(size_t)(row0 + 8) * DD + col] = hB;
        *(uint32_t*)&g_cxl[(size_t)(row0 + 8) * DD + col] = lB;
    }
}

// ---------------------------------------------------------------------------
// Launch
// ---------------------------------------------------------------------------
extern "C" void kernel_launch(void* const* d_in, const int* in_sizes, int n_in,
                              void* d_out, int out_size) {
    const float* x     = (const float*)d_in[0];
    const float* gamma = (const float*)d_in[1];
    const float* beta  = (const float*)d_in[2];
    const float* w_qkv = (const float*)d_in[3];   // [3072, 1024]
    const float* w_o   = (const float*)d_in[4];   // [1024, 1024]
    float* out = (float*)d_out;                   // [8192, 1024]

    __nv_bfloat16 *qh, *ql, *xnh, *xnl, *wqh, *wql, *woh, *wol, *cxh, *cxl;
    cudaGetSymbolAddress((void**)&qh,  g_qh);
    cudaGetSymbolAddress((void**)&ql,  g_ql);
    cudaGetSymbolAddress((void**)&xnh, g_xnh);
    cudaGetSymbolAddress((void**)&xnl, g_xnl);
    cudaGetSymbolAddress((void**)&wqh, g_wqh);
    cudaGetSymbolAddress((void**)&wql, g_wql);
    cudaGetSymbolAddress((void**)&woh, g_woh);
    cudaGetSymbolAddress((void**)&wol, g_wol);
    cudaGetSymbolAddress((void**)&cxh, g_cxh);
    cudaGetSymbolAddress((void**)&cxl, g_cxl);

    static int attr_set = 0;
    if (!attr_set) {
        cudaFuncSetAttribute(gemm3, cudaFuncAttributeMaxDynamicSharedMemorySize,
                             GEMM_SMEM_BYTES);
        attr_set = 1;
    }

    // 1. LayerNorm (fused bf16 hi/lo split output)
    ln_kernel<<<BT, 256>>>(x, gamma, beta);

    // 2. Weight splits
    cvt_kernel<<<(D3 * DD / 4 + 255) / 256, 256>>>(w_qkv, wqh, wql, D3 * DD / 4);
    cvt_kernel<<<(DD * DD / 4 + 255) / 256, 256>>>(w_o, woh, wol, DD * DD / 4);

    // 3. QKV projection -> bf16 hi/lo output (cp.async double-buffered)
    {
        dim3 grid(D3 / 128, BT / 128);
        gemm3<<<grid, 128, GEMM_SMEM_BYTES>>>(xnh, xnl, wqh, wql, nullptr, qh, ql, D3);
    }

    // 4. Causal attention (HMMA flash v2, 64-row q-tiles, 2 CTAs/SM)
    {
        dim3 grid(TT / 64, NB * HH);
        attn_hmma<<<grid, 128>>>();
    }

    // 5. Output projection (fp32 out)
    {
        dim3 grid(DD / 128, BT / 128);
        gemm3<<<grid, 128, GEMM_SMEM_BYTES>>>(cxh, cxl, woh, wol, out, nullptr, nullptr, DD);
    }
}

// round 12
// speedup vs baseline: 2.9436x; 1.0454x over previous
#include <cuda_runtime.h>
#include <cuda_bf16.h>
#include <math.h>
#include <stdint.h>

// Problem constants
#define NB   4
#define TT   2048
#define DD   1024
#define HH   16
#define DHD  64
#define BT   (NB * TT)          // 8192 rows
#define D3   (3 * DD)           // 3072

// ---------------------------------------------------------------------------
// Scratch (no cudaMalloc allowed — device globals)
// ---------------------------------------------------------------------------
__device__ __nv_bfloat16 g_qh[BT * D3], g_ql[BT * D3];     // QKV bf16 hi/lo
__device__ __nv_bfloat16 g_xnh[BT * DD], g_xnl[BT * DD];   // LN output hi/lo
__device__ __nv_bfloat16 g_wqh[D3 * DD], g_wql[D3 * DD];   // W_qkv hi/lo
__device__ __nv_bfloat16 g_woh[DD * DD], g_wol[DD * DD];   // W_o hi/lo
__device__ __nv_bfloat16 g_cxh[BT * DD], g_cxl[BT * DD];   // ctx hi/lo (attn out)

// ---------------------------------------------------------------------------
// PTX helpers
// ---------------------------------------------------------------------------
#define MMA16816(Cacc, Afrag, Bfrag) \
    asm volatile( \
        "mma.sync.aligned.m16n8k16.row.col.f32.bf16.bf16.f32 " \
        "{%0,%1,%2,%3}, {%4,%5,%6,%7}, {%8,%9}, {%0,%1,%2,%3};" \
        : "+f"((Cacc)[0]), "+f"((Cacc)[1]), "+f"((Cacc)[2]), "+f"((Cacc)[3]) \
        : "r"((Afrag)[0]), "r"((Afrag)[1]), "r"((Afrag)[2]), "r"((Afrag)[3]), \
          "r"((Bfrag)[0]), "r"((Bfrag)[1]))

#define CP16(saddr, gptr) \
    asm volatile("cp.async.cg.shared.global [%0], [%1], 16;" :: "r"(saddr), "l"(gptr))
#define CP_COMMIT() asm volatile("cp.async.commit_group;" ::: "memory")

// ldmatrix x2 transposed (B-fragment loader for V stored [key][d])
#define LDSMT_X2(r, a) \
    asm volatile("ldmatrix.sync.aligned.m8n8.x2.trans.shared.b16 {%0,%1}, [%2];" \
                 : "=r"((r)[0]), "=r"((r)[1]) : "r"(a))

__device__ __forceinline__ uint32_t sptr(const void* p) {
    return (uint32_t)__cvta_generic_to_shared(p);
}

__device__ __forceinline__ void split2(float a, float b, uint32_t& hi, uint32_t& lo) {
    __nv_bfloat16 ha = __float2bfloat16(a), hb = __float2bfloat16(b);
    __nv_bfloat16 la = __float2bfloat16(a - __bfloat162float(ha));
    __nv_bfloat16 lb = __float2bfloat16(b - __bfloat162float(hb));
    __nv_bfloat162 th = __halves2bfloat162(ha, hb);
    __nv_bfloat162 tl = __halves2bfloat162(la, lb);
    hi = *reinterpret_cast<uint32_t*>(&th);
    lo = *reinterpret_cast<uint32_t*>(&tl);
}

// ---------------------------------------------------------------------------
// LayerNorm: one block (256 threads) per row; writes bf16 hi/lo split
// ---------------------------------------------------------------------------
__global__ void __launch_bounds__(256) ln_kernel(const float* __restrict__ x,
                                                 const float* __restrict__ gamma,
                                                 const float* __restrict__ beta) {
    int row = blockIdx.x;
    int tid = threadIdx.x;
    __shared__ float red[2][8];

    const float4* xr = (const float4*)(x + (size_t)row * DD);
    float4 xv = xr[tid];
    float s  = xv.x + xv.y + xv.z + xv.w;
    float s2 = xv.x * xv.x + xv.y * xv.y + xv.z * xv.z + xv.w * xv.w;

    #pragma unroll
    for (int o = 16; o > 0; o >>= 1) {
        s  += __shfl_xor_sync(0xffffffffu, s, o);
        s2 += __shfl_xor_sync(0xffffffffu, s2, o);
    }
    if ((tid & 31) == 0) { red[0][tid >> 5] = s; red[1][tid >> 5] = s2; }
    __syncthreads();
    if (tid < 32) {
        float a = (tid < 8) ? red[0][tid] : 0.f;
        float b = (tid < 8) ? red[1][tid] : 0.f;
        #pragma unroll
        for (int o = 4; o > 0; o >>= 1) {
            a += __shfl_xor_sync(0xffffffffu, a, o);
            b += __shfl_xor_sync(0xffffffffu, b, o);
        }
        if (tid == 0) { red[0][0] = a * (1.f / DD); red[1][0] = b * (1.f / DD); }
    }
    __syncthreads();

    float mu   = red[0][0];
    float var  = red[1][0] - mu * mu;
    float rstd = rsqrtf(var + 1e-5f);

    float4 g  = ((const float4*)gamma)[tid];
    float4 bb = ((const float4*)beta)[tid];
    float y[4];
    y[0] = (xv.x - mu) * rstd * g.x + bb.x;
    y[1] = (xv.y - mu) * rstd * g.y + bb.y;
    y[2] = (xv.z - mu) * rstd * g.z + bb.z;
    y[3] = (xv.w - mu) * rstd * g.w + bb.w;

    size_t base = (size_t)row * DD + tid * 4;
    uint32_t h01, l01, h23, l23;
    split2(y[0], y[1], h01, l01);
    split2(y[2], y[3], h23, l23);
    ((uint32_t*)(g_xnh + base))[0] = h01;
    ((uint32_t*)(g_xnh + base))[1] = h23;
    ((uint32_t*)(g_xnl + base))[0] = l01;
    ((uint32_t*)(g_xnl + base))[1] = l23;
}

// ---------------------------------------------------------------------------
// fp32 -> bf16 hi/lo split convert (weights)
// ---------------------------------------------------------------------------
__global__ void __launch_bounds__(256) cvt_kernel(const float* __restrict__ src,
                                                  __nv_bfloat16* __restrict__ oh,
                                                  __nv_bfloat16* __restrict__ ol,
                                                  int n4) {
    int i = blockIdx.x * blockDim.x + threadIdx.x;
    if (i >= n4) return;
    float4 v = ((const float4*)src)[i];
    size_t base = (size_t)i * 4;
    uint32_t h01, l01, h23, l23;
    split2(v.x, v.y, h01, l01);
    split2(v.z, v.w, h23, l23);
    ((uint32_t*)(oh + base))[0] = h01;
    ((uint32_t*)(oh + base))[1] = h23;
    ((uint32_t*)(ol + base))[0] = l01;
    ((uint32_t*)(ol + base))[1] = l23;
}

// ---------------------------------------------------------------------------
// HMMA bf16x3 GEMM (VERBATIM from R11 pass): C = (Ah+Al) @ (Bh+Bl)^T
// warp tile 64x64, CTA 128x128, 128 threads, 2-stage cp.async pipeline.
// ---------------------------------------------------------------------------
#define SPAD 40
#define TILE_ELEMS (128 * SPAD)
#define GEMM_SMEM_BYTES (2 * 4 * TILE_ELEMS * 2)
#define NCHUNK (DD / 32)

#define TILEP(s, arr) ((uint16_t(*)[SPAD])(dsm + (size_t)((s) * 4 + (arr)) * TILE_ELEMS))

__global__ void __launch_bounds__(128, 2) gemm3(const __nv_bfloat16* __restrict__ Ah,
                                                const __nv_bfloat16* __restrict__ Al,
                                                const __nv_bfloat16* __restrict__ Bh,
                                                const __nv_bfloat16* __restrict__ Bl,
                                                float* __restrict__ Cf,
                                                __nv_bfloat16* __restrict__ Chi,
                                                __nv_bfloat16* __restrict__ Clo,
                                                int Ntot) {
    extern __shared__ __align__(16) uint16_t dsm[];

    int tid = threadIdx.x;
    int wid = tid >> 5, lid = tid & 31;
    int wm = wid >> 1, wn = wid & 1;
    int g = lid >> 2, t = lid & 3;
    int bm = blockIdx.y * 128;
    int bn = blockIdx.x * 128;

    float acc[4][8][4];
    #pragma unroll
    for (int i = 0; i < 4; i++)
        #pragma unroll
        for (int j = 0; j < 8; j++)
            #pragma unroll
            for (int r = 0; r < 4; r++) acc[i][j][r] = 0.f;

    #define GISSUE(s, kc) do { \
        uint16_t (*tAh)[SPAD] = TILEP(s, 0); \
        uint16_t (*tAl)[SPAD] = TILEP(s, 1); \
        uint16_t (*tBh)[SPAD] = TILEP(s, 2); \
        uint16_t (*tBl)[SPAD] = TILEP(s, 3); \
        _Pragma("unroll") \
        for (int c = 0; c < 4; c++) { \
            int idx = tid + c * 128; \
            int row = idx >> 2, c8 = idx & 3; \
            size_t ga = (size_t)(bm + row) * DD + (kc) + c8 * 8; \
            size_t gb = (size_t)(bn + row) * DD + (kc) + c8 * 8; \
            CP16(sptr(&tAh[row][c8 * 8]), Ah + ga); \
            CP16(sptr(&tAl[row][c8 * 8]), Al + ga); \
            CP16(sptr(&tBh[row][c8 * 8]), Bh + gb); \
            CP16(sptr(&tBl[row][c8 * 8]), Bl + gb); \
        } \
        CP_COMMIT(); \
    } while (0)

    GISSUE(0, 0);

    for (int ch = 0; ch < NCHUNK; ch++) {
        int cur = ch & 1;
        if (ch + 1 < NCHUNK) {
            GISSUE((ch + 1) & 1, (ch + 1) * 32);
            asm volatile("cp.async.wait_group 1;" ::: "memory");
        } else {
            asm volatile("cp.async.wait_group 0;" ::: "memory");
        }
        __syncthreads();

        uint16_t (*sAh)[SPAD] = TILEP(cur, 0);
        uint16_t (*sAl)[SPAD] = TILEP(cur, 1);
        uint16_t (*sBh)[SPAD] = TILEP(cur, 2);
        uint16_t (*sBl)[SPAD] = TILEP(cur, 3);

        #pragma unroll
        for (int ks = 0; ks < 2; ks++) {
            int kb = ks * 16;
            uint32_t ah[4][4], al[4][4], bh[8][2], bl[8][2];
            #pragma unroll
            for (int i = 0; i < 4; i++) {
                int m0 = wm * 64 + i * 16;
                ah[i][0] = *(const uint32_t*)&sAh[m0 + g][kb + 2 * t];
                ah[i][1] = *(const uint32_t*)&sAh[m0 + 8 + g][kb + 2 * t];
                ah[i][2] = *(const uint32_t*)&sAh[m0 + g][kb + 8 + 2 * t];
                ah[i][3] = *(const uint32_t*)&sAh[m0 + 8 + g][kb + 8 + 2 * t];
                al[i][0] = *(const uint32_t*)&sAl[m0 + g][kb + 2 * t];
                al[i][1] = *(const uint32_t*)&sAl[m0 + 8 + g][kb + 2 * t];
                al[i][2] = *(const uint32_t*)&sAl[m0 + g][kb + 8 + 2 * t];
                al[i][3] = *(const uint32_t*)&sAl[m0 + 8 + g][kb + 8 + 2 * t];
            }
            #pragma unroll
            for (int j = 0; j < 8; j++) {
                int n0 = wn * 64 + j * 8;
                bh[j][0] = *(const uint32_t*)&sBh[n0 + g][kb + 2 * t];
                bh[j][1] = *(const uint32_t*)&sBh[n0 + g][kb + 8 + 2 * t];
                bl[j][0] = *(const uint32_t*)&sBl[n0 + g][kb + 2 * t];
                bl[j][1] = *(const uint32_t*)&sBl[n0 + g][kb + 8 + 2 * t];
            }
            #pragma unroll
            for (int i = 0; i < 4; i++)
                #pragma unroll
                for (int j = 0; j < 8; j++) {
                    MMA16816(acc[i][j], ah[i], bh[j]);
                    MMA16816(acc[i][j], ah[i], bl[j]);
                    MMA16816(acc[i][j], al[i], bh[j]);
                }
        }
        __syncthreads();
    }

    if (Cf) {
        #pragma unroll
        for (int i = 0; i < 4; i++) {
            int r0 = bm + wm * 64 + i * 16 + g;
            #pragma unroll
            for (int j = 0; j < 8; j++) {
                int c0 = bn + wn * 64 + j * 8 + 2 * t;
                *(float2*)&Cf[(size_t)r0 * Ntot + c0]       = make_float2(acc[i][j][0], acc[i][j][1]);
                *(float2*)&Cf[(size_t)(r0 + 8) * Ntot + c0] = make_float2(acc[i][j][2], acc[i][j][3]);
            }
        }
    } else {
        #pragma unroll
        for (int i = 0; i < 4; i++) {
            int r0 = bm + wm * 64 + i * 16 + g;
            #pragma unroll
            for (int j = 0; j < 8; j++) {
                int c0 = bn + wn * 64 + j * 8 + 2 * t;
                uint32_t hA, lA, hB, lB;
                split2(acc[i][j][0], acc[i][j][1], hA, lA);
                split2(acc[i][j][2], acc[i][j][3], hB, lB);
                *(uint32_t*)&Chi[(size_t)r0 * Ntot + c0]       = hA;
                *(uint32_t*)&Clo[(size_t)r0 * Ntot + c0]       = lA;
                *(uint32_t*)&Chi[(size_t)(r0 + 8) * Ntot + c0] = hB;
                *(uint32_t*)&Clo[(size_t)(r0 + 8) * Ntot + c0] = lB;
            }
        }
    }
}

// ---------------------------------------------------------------------------
// HMMA flash attention v3 (causal), bf16x3 splits.
// Change vs R11: V staged row-major [key][d] (plain uint4 copies, no
// transpose STS); P·V B-fragments loaded via ldmatrix.x2.trans.
// 128 threads (4 warps x 16 q-rows = 64-row q-tile), key tiles of 64.
// ---------------------------------------------------------------------------
#define APAD 72

__global__ void __launch_bounds__(128, 2) attn_hmma() {
    int qt  = gridDim.x - 1 - blockIdx.x;   // heavy tiles first
    int bh  = blockIdx.y;
    int b   = bh >> 4;
    int h   = bh & 15;
    int tid = threadIdx.x;
    int w   = tid >> 5, lid = tid & 31;
    int g   = lid >> 2, t = lid & 3;

    __shared__ __align__(16) uint16_t Kh[64][APAD], Kl[64][APAD];
    __shared__ __align__(16) uint16_t Vh[64][APAD], Vl[64][APAD];   // V row-major [key][d]

    // ldmatrix.trans row address component: lanes 0-7 -> matrix0 rows (k offset
    // 0..7), lanes 8-15 -> matrix1 rows (k offset 8..15). Lanes 16-31 unused
    // by x2 but given valid addresses.
    int moff = (lid & 7) + ((lid >> 3) & 1) * 8;

    // ---- Q fragments straight from gmem (invariant across key tiles)
    uint32_t qh[4][4], ql[4][4];
    {
        const __nv_bfloat16* qbh = g_qh + (size_t)(b * TT + qt * 64 + w * 16) * D3 + h * 192;
        const __nv_bfloat16* qbl = g_ql + (size_t)(b * TT + qt * 64 + w * 16) * D3 + h * 192;
        #pragma unroll
        for (int ks = 0; ks < 4; ks++) {
            int kb = ks * 16;
            qh[ks][0] = *(const uint32_t*)(qbh + (size_t)g * D3 + kb + 2 * t);
            qh[ks][1] = *(const uint32_t*)(qbh + (size_t)(8 + g) * D3 + kb + 2 * t);
            qh[ks][2] = *(const uint32_t*)(qbh + (size_t)g * D3 + kb + 8 + 2 * t);
            qh[ks][3] = *(const uint32_t*)(qbh + (size_t)(8 + g) * D3 + kb + 8 + 2 * t);
            ql[ks][0] = *(const uint32_t*)(qbl + (size_t)g * D3 + kb + 2 * t);
            ql[ks][1] = *(const uint32_t*)(qbl + (size_t)(8 + g) * D3 + kb + 2 * t);
            ql[ks][2] = *(const uint32_t*)(qbl + (size_t)g * D3 + kb + 8 + 2 * t);
            ql[ks][3] = *(const uint32_t*)(qbl + (size_t)(8 + g) * D3 + kb + 8 + 2 * t);
        }
    }

    float oacc[8][4];
    #pragma unroll
    for (int c = 0; c < 8; c++)
        #pragma unroll
        for (int r = 0; r < 4; r++) oacc[c][r] = 0.f;
    float m0 = -1e30f, m1 = -1e30f, l0 = 0.f, l1 = 0.f;

    int ntiles = qt + 1;
    for (int kt = 0; kt < ntiles; kt++) {
        __syncthreads();
        // ---- stage K and V tiles, both row-major [key][d] (pure 16B copies)
        {
            int r = tid >> 1, half = tid & 1;
            size_t base = (size_t)(b * TT + kt * 64 + r) * D3 + h * 192;
            const uint4* kh4 = (const uint4*)(g_qh + base + 64 + half * 32);
            const uint4* kl4 = (const uint4*)(g_ql + base + 64 + half * 32);
            const uint4* vh4 = (const uint4*)(g_qh + base + 128 + half * 32);
            const uint4* vl4 = (const uint4*)(g_ql + base + 128 + half * 32);
            #pragma unroll
            for (int j = 0; j < 4; j++) {
                *(uint4*)&Kh[r][half * 32 + j * 8] = kh4[j];
                *(uint4*)&Kl[r][half * 32 + j * 8] = kl4[j];
                *(uint4*)&Vh[r][half * 32 + j * 8] = vh4[j];
                *(uint4*)&Vl[r][half * 32 + j * 8] = vl4[j];
            }
        }
        __syncthreads();

        // ---- S = Q K^T (3-term), fragment accumulators
        float sf[8][4];
        #pragma unroll
        for (int c = 0; c < 8; c++)
            #pragma unroll
            for (int r = 0; r < 4; r++) sf[c][r] = 0.f;

        #pragma unroll
        for (int ks = 0; ks < 4; ks++) {
            int kb = ks * 16;
            #pragma unroll
            for (int c = 0; c < 8; c++) {
                uint32_t bhf[2], blf[2];
                bhf[0] = *(const uint32_t*)&Kh[c * 8 + g][kb + 2 * t];
                bhf[1] = *(const uint32_t*)&Kh[c * 8 + g][kb + 8 + 2 * t];
                blf[0] = *(const uint32_t*)&Kl[c * 8 + g][kb + 2 * t];
                blf[1] = *(const uint32_t*)&Kl[c * 8 + g][kb + 8 + 2 * t];
                MMA16816(sf[c], qh[ks], bhf);
                MMA16816(sf[c], qh[ks], blf);
                MMA16816(sf[c], ql[ks], bhf);
            }
        }

        #pragma unroll
        for (int c = 0; c < 8; c++) {
            sf[c][0] *= 0.125f; sf[c][1] *= 0.125f;
            sf[c][2] *= 0.125f; sf[c][3] *= 0.125f;
        }

        // ---- causal mask (only the diagonal tile)
        if (kt == qt) {
            int colb = kt * 64 + 2 * t;
            int row0 = qt * 64 + w * 16 + g;
            #pragma unroll
            for (int c = 0; c < 8; c++) {
                int col = colb + c * 8;
                if (col     > row0)     sf[c][0] = -1e30f;
                if (col + 1 > row0)     sf[c][1] = -1e30f;
                if (col     > row0 + 8) sf[c][2] = -1e30f;
                if (col + 1 > row0 + 8) sf[c][3] = -1e30f;
            }
        }

        // ---- online softmax on fragments
        float rm0 = -1e30f, rm1 = -1e30f;
        #pragma unroll
        for (int c = 0; c < 8; c++) {
            rm0 = fmaxf(rm0, fmaxf(sf[c][0], sf[c][1]));
            rm1 = fmaxf(rm1, fmaxf(sf[c][2], sf[c][3]));
        }
        rm0 = fmaxf(rm0, __shfl_xor_sync(0xffffffffu, rm0, 1));
        rm0 = fmaxf(rm0, __shfl_xor_sync(0xffffffffu, rm0, 2));
        rm1 = fmaxf(rm1, __shfl_xor_sync(0xffffffffu, rm1, 1));
        rm1 = fmaxf(rm1, __shfl_xor_sync(0xffffffffu, rm1, 2));

        float mn0 = fmaxf(m0, rm0), mn1 = fmaxf(m1, rm1);
        float corr0 = __expf(m0 - mn0), corr1 = __expf(m1 - mn1);
        l0 *= corr0; l1 *= corr1;
        #pragma unroll
        for (int c = 0; c < 8; c++) {
            oacc[c][0] *= corr0; oacc[c][1] *= corr0;
            oacc[c][2] *= corr1; oacc[c][3] *= corr1;
        }

        uint32_t phA[8], phB[8], plA[8], plB[8];
        float rs0 = 0.f, rs1 = 0.f;
        #pragma unroll
        for (int c = 0; c < 8; c++) {
            float p0 = __expf(sf[c][0] - mn0);
            float p1 = __expf(sf[c][1] - mn0);
            float p2 = __expf(sf[c][2] - mn1);
            float p3 = __expf(sf[c][3] - mn1);
            rs0 += p0 + p1; rs1 += p2 + p3;
            split2(p0, p1, phA[c], plA[c]);
            split2(p2, p3, phB[c], plB[c]);
        }
        rs0 += __shfl_xor_sync(0xffffffffu, rs0, 1);
        rs0 += __shfl_xor_sync(0xffffffffu, rs0, 2);
        rs1 += __shfl_xor_sync(0xffffffffu, rs1, 1);
        rs1 += __shfl_xor_sync(0xffffffffu, rs1, 2);
        l0 += rs0; l1 += rs1;
        m0 = mn0; m1 = mn1;

        // ---- P · V (3-term): B fragments via ldmatrix.x2.trans on V[key][d]
        #pragma unroll
        for (int j = 0; j < 4; j++) {
            uint32_t a_h[4] = {phA[2 * j], phB[2 * j], phA[2 * j + 1], phB[2 * j + 1]};
            uint32_t a_l[4] = {plA[2 * j], plB[2 * j], plA[2 * j + 1], plB[2 * j + 1]};
            int kb = j * 16;
            #pragma unroll
            for (int c = 0; c < 8; c++) {
                uint32_t vh[2], vl[2];
                LDSMT_X2(vh, sptr(&Vh[kb + moff][c * 8]));
                LDSMT_X2(vl, sptr(&Vl[kb + moff][c * 8]));
                MMA16816(oacc[c], a_h, vh);
                MMA16816(oacc[c], a_h, vl);
                MMA16816(oacc[c], a_l, vh);
            }
        }
    }

    // ---- epilogue: divide by l, hi/lo split, write to g_cxh/g_cxl
    float il0 = 1.f / l0, il1 = 1.f / l1;
    int row0 = b * TT + qt * 64 + w * 16 + g;
    #pragma unroll
    for (int c = 0; c < 8; c++) {
        int col = h * DHD + c * 8 + 2 * t;
        uint32_t hA, lA, hB, lB;
        split2(oacc[c][0] * il0, oacc[c][1] * il0, hA, lA);
        split2(oacc[c][2] * il1, oacc[c][3] * il1, hB, lB);
        *(uint32_t*)&g_cxh[(size_t)row0 * DD + col]       = hA;
        *(uint32_t*)&g_cxl[(size_t)row0 * DD + col]       = lA;
        *(uint32_t*)&g_cxh[(size_t)(row0 + 8) * DD + col] = hB;
        *(uint32_t*)&g_cxl[(size_t)(row0 + 8) * DD + col] = lB;
    }
}

// ---------------------------------------------------------------------------
// Launch
// ---------------------------------------------------------------------------
extern "C" void kernel_launch(void* const* d_in, const int* in_sizes, int n_in,
                              void* d_out, int out_size) {
    const float* x     = (const float*)d_in[0];
    const float* gamma = (const float*)d_in[1];
    const float* beta  = (const float*)d_in[2];
    const float* w_qkv = (const float*)d_in[3];   // [3072, 1024]
    const float* w_o   = (const float*)d_in[4];   // [1024, 1024]
    float* out = (float*)d_out;                   // [8192, 1024]

    __nv_bfloat16 *qh, *ql, *xnh, *xnl, *wqh, *wql, *woh, *wol, *cxh, *cxl;
    cudaGetSymbolAddress((void**)&qh,  g_qh);
    cudaGetSymbolAddress((void**)&ql,  g_ql);
    cudaGetSymbolAddress((void**)&xnh, g_xnh);
    cudaGetSymbolAddress((void**)&xnl, g_xnl);
    cudaGetSymbolAddress((void**)&wqh, g_wqh);
    cudaGetSymbolAddress((void**)&wql, g_wql);
    cudaGetSymbolAddress((void**)&woh, g_woh);
    cudaGetSymbolAddress((void**)&wol, g_wol);
    cudaGetSymbolAddress((void**)&cxh, g_cxh);
    cudaGetSymbolAddress((void**)&cxl, g_cxl);

    static int attr_set = 0;
    if (!attr_set) {
        cudaFuncSetAttribute(gemm3, cudaFuncAttributeMaxDynamicSharedMemorySize,
                             GEMM_SMEM_BYTES);
        attr_set = 1;
    }

    // 1. LayerNorm (fused bf16 hi/lo split output)
    ln_kernel<<<BT, 256>>>(x, gamma, beta);

    // 2. Weight splits
    cvt_kernel<<<(D3 * DD / 4 + 255) / 256, 256>>>(w_qkv, wqh, wql, D3 * DD / 4);
    cvt_kernel<<<(DD * DD / 4 + 255) / 256, 256>>>(w_o, woh, wol, DD * DD / 4);

    // 3. QKV projection -> bf16 hi/lo output (cp.async double-buffered)
    {
        dim3 grid(D3 / 128, BT / 128);
        gemm3<<<grid, 128, GEMM_SMEM_BYTES>>>(xnh, xnl, wqh, wql, nullptr, qh, ql, D3);
    }

    // 4. Causal attention (HMMA flash v3, ldmatrix.trans V)
    {
        dim3 grid(TT / 64, NB * HH);
        attn_hmma<<<grid, 128>>>();
    }

    // 5. Output projection (fp32 out)
    {
        dim3 grid(DD / 128, BT / 128);
        gemm3<<<grid, 128, GEMM_SMEM_BYTES>>>(cxh, cxl, woh, wol, out, nullptr, nullptr, DD);
    }
}